// round 7
// baseline (speedup 1.0000x reference)
#include <cuda_runtime.h>
#include <cuda_bf16.h>
#include <stdint.h>
#include <math.h>

#define B_  4
#define T_  2048
#define E_  1024
#define H_  16
#define HD_ 64
#define M_  (B_*T_)   // 8192

// Scratch (device globals: allocation-free)
__device__ __nv_bfloat16 g_xh[M_*E_], g_xl[M_*E_];
__device__ __nv_bfloat16 g_yh[M_*E_], g_yl[M_*E_];
__device__ __nv_bfloat16 g_qh[M_*E_], g_ql[M_*E_];
__device__ __nv_bfloat16 g_kh[M_*E_], g_kl[M_*E_];
__device__ __nv_bfloat16 g_vh[M_*E_], g_vl[M_*E_];
__device__ __nv_bfloat16 g_wqh[E_*E_], g_wql[E_*E_];
__device__ __nv_bfloat16 g_wkh[E_*E_], g_wkl[E_*E_];
__device__ __nv_bfloat16 g_wvh[E_*E_], g_wvl[E_*E_];
__device__ __nv_bfloat16 g_wph[E_*E_], g_wpl[E_*E_];

// ---------------------------------------------------------------------------
// helpers
// ---------------------------------------------------------------------------
__device__ __forceinline__ uint32_t smem_u32(const void* p) {
    return (uint32_t)__cvta_generic_to_shared(p);
}
__device__ __forceinline__ void cp_async16(uint32_t dst, const void* src) {
    asm volatile("cp.async.cg.shared.global [%0], [%1], 16;\n" :: "r"(dst), "l"(src));
}
__device__ __forceinline__ void cp_commit() { asm volatile("cp.async.commit_group;\n"); }
__device__ __forceinline__ void cp_wait0() { asm volatile("cp.async.wait_group 0;\n"); }
__device__ __forceinline__ void cp_wait1() { asm volatile("cp.async.wait_group 1;\n"); }
__device__ __forceinline__ void cp_wait2() { asm volatile("cp.async.wait_group 2;\n"); }

__device__ __forceinline__ void mma_bf16(float c[4], const uint32_t a[4], uint32_t b0, uint32_t b1) {
    asm volatile(
        "mma.sync.aligned.m16n8k16.row.col.f32.bf16.bf16.f32 "
        "{%0,%1,%2,%3}, {%4,%5,%6,%7}, {%8,%9}, {%0,%1,%2,%3};\n"
        : "+f"(c[0]), "+f"(c[1]), "+f"(c[2]), "+f"(c[3])
        : "r"(a[0]), "r"(a[1]), "r"(a[2]), "r"(a[3]), "r"(b0), "r"(b1));
}
__device__ __forceinline__ void ldsm_x4(uint32_t r[4], uint32_t addr) {
    asm volatile("ldmatrix.sync.aligned.m8n8.x4.shared.b16 {%0,%1,%2,%3}, [%4];"
        : "=r"(r[0]), "=r"(r[1]), "=r"(r[2]), "=r"(r[3]) : "r"(addr));
}
__device__ __forceinline__ void ldsm_x4t(uint32_t r[4], uint32_t addr) {
    asm volatile("ldmatrix.sync.aligned.m8n8.x4.trans.shared.b16 {%0,%1,%2,%3}, [%4];"
        : "=r"(r[0]), "=r"(r[1]), "=r"(r[2]), "=r"(r[3]) : "r"(addr));
}
__device__ __forceinline__ void split_bf16(float v, __nv_bfloat16& h, __nv_bfloat16& l) {
    h = __float2bfloat16(v);
    l = __float2bfloat16(v - __bfloat162float(h));
}
__device__ __forceinline__ uint32_t pack_bf162(__nv_bfloat16 a, __nv_bfloat16 b) {
    __nv_bfloat162 p(a, b);
    return *(uint32_t*)&p;
}

// ---------------------------------------------------------------------------
// Prep: split fp32 -> bf16 hi/lo, same layout.
// ---------------------------------------------------------------------------
__global__ void split_kernel(const float* __restrict__ src,
                             __nv_bfloat16* __restrict__ hi,
                             __nv_bfloat16* __restrict__ lo, int n4)
{
    int i = blockIdx.x * blockDim.x + threadIdx.x;
    if (i >= n4) return;
    float4 v = ((const float4*)src)[i];
    __nv_bfloat16 h0,h1,h2,h3,l0,l1,l2,l3;
    split_bf16(v.x,h0,l0); split_bf16(v.y,h1,l1);
    split_bf16(v.z,h2,l2); split_bf16(v.w,h3,l3);
    ((__nv_bfloat162*)hi)[i*2+0] = __nv_bfloat162(h0,h1);
    ((__nv_bfloat162*)hi)[i*2+1] = __nv_bfloat162(h2,h3);
    ((__nv_bfloat162*)lo)[i*2+0] = __nv_bfloat162(l0,l1);
    ((__nv_bfloat162*)lo)[i*2+1] = __nv_bfloat162(l2,l3);
}

// ---------------------------------------------------------------------------
// Prep: transpose + split all 4 weights (blockIdx.z selects).
// ---------------------------------------------------------------------------
__global__ void tsplit4_kernel(
    const float* __restrict__ W0, const float* __restrict__ W1,
    const float* __restrict__ W2, const float* __restrict__ W3,
    __nv_bfloat16* __restrict__ T0h, __nv_bfloat16* __restrict__ T0l,
    __nv_bfloat16* __restrict__ T1h, __nv_bfloat16* __restrict__ T1l,
    __nv_bfloat16* __restrict__ T2h, __nv_bfloat16* __restrict__ T2l,
    __nv_bfloat16* __restrict__ T3h, __nv_bfloat16* __restrict__ T3l)
{
    const float* W = (blockIdx.z == 0) ? W0 : (blockIdx.z == 1) ? W1 : (blockIdx.z == 2) ? W2 : W3;
    __nv_bfloat16* Th = (blockIdx.z == 0) ? T0h : (blockIdx.z == 1) ? T1h : (blockIdx.z == 2) ? T2h : T3h;
    __nv_bfloat16* Tl = (blockIdx.z == 0) ? T0l : (blockIdx.z == 1) ? T1l : (blockIdx.z == 2) ? T2l : T3l;

    __shared__ float t[32][33];
    const int n0 = blockIdx.x * 32, k0 = blockIdx.y * 32;
    const int tx = threadIdx.x, ty = threadIdx.y;   // (32, 8)
    #pragma unroll
    for (int i = 0; i < 4; i++)
        t[ty + 8*i][tx] = W[(size_t)(k0 + ty + 8*i) * E_ + n0 + tx];
    __syncthreads();
    #pragma unroll
    for (int i = 0; i < 4; i++) {
        const int row = ty + 8*i;
        const float v = t[tx][row];
        __nv_bfloat16 h, l;
        split_bf16(v, h, l);
        Th[(size_t)(n0 + row) * E_ + k0 + tx] = h;
        Tl[(size_t)(n0 + row) * E_ + k0 + tx] = l;
    }
}

// ---------------------------------------------------------------------------
// bf16x3 tensor-core GEMM with ldmatrix + 3-stage cp.async.
// REORDER=true:  write split bf16 hi/lo in [B,H,T,hd] layout (Ch, Cl).
// REORDER=false: write fp32 [M][N] (C).
// ---------------------------------------------------------------------------
#define GS_STRIDE 80
#define GS_TILE   (128*GS_STRIDE)      // 10240 B
#define GS_STAGE  (4*GS_TILE)          // 40960 B
#define GS_SMEM   (3*GS_STAGE)         // 122880 B

template<bool REORDER>
__global__ void __launch_bounds__(256) gemm_bf16x3(
    const __nv_bfloat16* __restrict__ Ah, const __nv_bfloat16* __restrict__ Al,
    const __nv_bfloat16* __restrict__ Th, const __nv_bfloat16* __restrict__ Tl,
    const float* __restrict__ bias, float* __restrict__ C,
    __nv_bfloat16* __restrict__ Ch, __nv_bfloat16* __restrict__ Cl)
{
    extern __shared__ char sm[];
    const uint32_t smb = smem_u32(sm);

    const int tid  = threadIdx.x;
    const int warp = tid >> 5;
    const int lane = tid & 31;
    const int group = lane >> 2;
    const int tidg  = lane & 3;

    const int bn = blockIdx.x, bm = blockIdx.y;
    const int m0 = bm * 128, n0 = bn * 128;
    const int warp_m = warp & 1;
    const int warp_n = warp >> 1;

    const int lrow = (lane & 7) + ((lane >> 3) & 1) * 8;
    const int lkb  = ((lane >> 4) & 1) * 16;

    auto load_stage = [&](int s, int c) {
        const int kb = c * 32;
        const uint32_t st = smb + s * GS_STAGE;
        #pragma unroll
        for (int i = 0; i < 2; i++) {
            const int ch = tid + i * 256;
            const int row = ch >> 2, q = ch & 3;
            const uint32_t d = st + row * GS_STRIDE + q * 16;
            const size_t ga = (size_t)(m0 + row) * E_ + kb + q * 8;
            const size_t gb = (size_t)(n0 + row) * E_ + kb + q * 8;
            cp_async16(d,               Ah + ga);
            cp_async16(d + GS_TILE,     Al + ga);
            cp_async16(d + 2*GS_TILE,   Th + gb);
            cp_async16(d + 3*GS_TILE,   Tl + gb);
        }
        cp_commit();
    };

    float acc[4][4][4];
    #pragma unroll
    for (int i = 0; i < 4; i++)
        #pragma unroll
        for (int j = 0; j < 4; j++)
            #pragma unroll
            for (int r = 0; r < 4; r++) acc[i][j][r] = 0.f;

    const int NC = E_ / 32;
    load_stage(0, 0);
    load_stage(1, 1);
    load_stage(2, 2);

    int s = 0;
    for (int c = 0; c < NC; c++) {
        if (c >= NC - 1)      cp_wait0();
        else if (c >= NC - 2) cp_wait1();
        else                  cp_wait2();
        __syncthreads();

        const uint32_t st = smb + s * GS_STAGE;
        const uint32_t abase = st + (warp_m * 64 + lrow) * GS_STRIDE + lkb;
        const uint32_t bbase = st + 2*GS_TILE + (warp_n * 32 + lrow) * GS_STRIDE + lkb;

        #pragma unroll
        for (int h2 = 0; h2 < 2; h2++) {
            const int ko = h2 * 32;
            uint32_t ah[4][4], al[4][4], bh[2][4], bl[2][4];
            #pragma unroll
            for (int i = 0; i < 4; i++) {
                ldsm_x4(ah[i], abase + i * 16 * GS_STRIDE + ko);
                ldsm_x4(al[i], abase + GS_TILE + i * 16 * GS_STRIDE + ko);
            }
            #pragma unroll
            for (int g = 0; g < 2; g++) {
                ldsm_x4(bh[g], bbase + g * 16 * GS_STRIDE + ko);
                ldsm_x4(bl[g], bbase + GS_TILE + g * 16 * GS_STRIDE + ko);
            }
            #pragma unroll
            for (int i = 0; i < 4; i++)
                #pragma unroll
                for (int j = 0; j < 4; j++)
                    mma_bf16(acc[i][j], ah[i], bh[j>>1][j&1], bh[j>>1][(j&1)+2]);
            #pragma unroll
            for (int i = 0; i < 4; i++)
                #pragma unroll
                for (int j = 0; j < 4; j++)
                    mma_bf16(acc[i][j], ah[i], bl[j>>1][j&1], bl[j>>1][(j&1)+2]);
            #pragma unroll
            for (int i = 0; i < 4; i++)
                #pragma unroll
                for (int j = 0; j < 4; j++)
                    mma_bf16(acc[i][j], al[i], bh[j>>1][j&1], bh[j>>1][(j&1)+2]);
        }
        __syncthreads();
        if (c + 3 < NC) load_stage(s, c + 3);
        s = (s == 2) ? 0 : s + 1;
    }

    #pragma unroll
    for (int i = 0; i < 4; i++) {
        const int rmb = m0 + warp_m * 64 + i * 16 + group;
        #pragma unroll
        for (int j = 0; j < 4; j++) {
            const int cb = n0 + warp_n * 32 + j * 8 + tidg * 2;
            const float bx = bias[cb], by = bias[cb + 1];
            #pragma unroll
            for (int half = 0; half < 2; half++) {
                const int m = rmb + half * 8;
                const float vx = acc[i][j][half * 2 + 0] + bx;
                const float vy = acc[i][j][half * 2 + 1] + by;
                if (REORDER) {
                    const int b = m >> 11;
                    const int t = m & (T_ - 1);
                    const int h = cb >> 6;
                    const int d = cb & (HD_ - 1);
                    const size_t o = (((size_t)(b * H_ + h) * T_) + t) * HD_ + d;
                    __nv_bfloat16 hx, lx, hy, ly;
                    split_bf16(vx, hx, lx);
                    split_bf16(vy, hy, ly);
                    *(uint32_t*)&Ch[o] = pack_bf162(hx, hy);
                    *(uint32_t*)&Cl[o] = pack_bf162(lx, ly);
                } else {
                    float2 v; v.x = vx; v.y = vy;
                    *(float2*)&C[(size_t)m * E_ + cb] = v;
                }
            }
        }
    }
}

// ---------------------------------------------------------------------------
// Tensor-core flash attention (causal), bf16x3, STATIC-SHIFT softmax.
// P = exp(S - 14): no online max, no rescaling; row sum accumulated per
// thread across tiles, reduced once at the end.
// Block = 128 q rows of one (b,h); 8 warps x 16 rows. KV tiles 64, 2 stages.
// ---------------------------------------------------------------------------
#define AT_STRIDE 144
#define AT_TILE   (64*AT_STRIDE)     // 9216
#define AT_STAGE  (4*AT_TILE)        // 36864
#define AT_SMEM   (2*AT_STAGE)       // 73728
#define SM_SHIFT  14.0f

__global__ void __launch_bounds__(256) attn_tc(
    const __nv_bfloat16* __restrict__ Qh, const __nv_bfloat16* __restrict__ Ql,
    const __nv_bfloat16* __restrict__ Kh, const __nv_bfloat16* __restrict__ Kl,
    const __nv_bfloat16* __restrict__ Vh, const __nv_bfloat16* __restrict__ Vl,
    __nv_bfloat16* __restrict__ Yh, __nv_bfloat16* __restrict__ Yl)
{
    extern __shared__ char sm[];
    const uint32_t smb = smem_u32(sm);

    const int tid  = threadIdx.x;
    const int warp = tid >> 5;
    const int lane = tid & 31;
    const int g    = lane >> 2;
    const int t4   = lane & 3;

    const int qb = blockIdx.x;
    const int h  = blockIdx.y;
    const int b  = blockIdx.z;
    const int q0 = qb * 128;

    const size_t base = (size_t)(b * H_ + h) * T_ * HD_;
    const __nv_bfloat16* qh = Qh + base + (size_t)q0 * HD_;
    const __nv_bfloat16* ql = Ql + base + (size_t)q0 * HD_;
    const __nv_bfloat16* kh = Kh + base;
    const __nv_bfloat16* kl = Kl + base;
    const __nv_bfloat16* vh = Vh + base;
    const __nv_bfloat16* vl = Vl + base;

    const int arow = (lane & 7) + ((lane >> 3) & 1) * 8;
    const int achk = (lane >> 4) & 1;
    const int brow = (lane & 7) + ((lane >> 4) & 1) * 8;
    const int bchk = (lane >> 3) & 1;

    // ---- load Q (128x64 hi/lo), pull into fragments ----
    #pragma unroll
    for (int i = 0; i < 4; i++) {
        const int ch = tid + i * 256;
        const int row = ch >> 3, q = ch & 7;
        const uint32_t d = smb + (row >> 6) * AT_TILE + (row & 63) * AT_STRIDE + q * 16;
        cp_async16(d,               qh + (size_t)row * HD_ + q * 8);
        cp_async16(d + 2*AT_TILE,   ql + (size_t)row * HD_ + q * 8);
    }
    cp_commit(); cp_wait0();
    __syncthreads();

    uint32_t qfh[4][4], qfl[4][4];
    {
        const int wr = warp * 16;
        const uint32_t qbse = smb + (wr >> 6) * AT_TILE + (wr & 63) * AT_STRIDE
                            + arow * AT_STRIDE + achk * 16;
        #pragma unroll
        for (int kc = 0; kc < 4; kc++) {
            ldsm_x4(qfh[kc], qbse + kc * 32);
            ldsm_x4(qfl[kc], qbse + 2*AT_TILE + kc * 32);
        }
    }
    __syncthreads();

    auto load_stage = [&](int s, int kt) {
        const int kv0 = kt * 64;
        const uint32_t st = smb + s * AT_STAGE;
        #pragma unroll
        for (int i = 0; i < 2; i++) {
            const int ch = tid + i * 256;
            const int row = ch >> 3, q = ch & 7;
            const uint32_t d = st + row * AT_STRIDE + q * 16;
            const size_t go = (size_t)(kv0 + row) * HD_ + q * 8;
            cp_async16(d,               kh + go);
            cp_async16(d + AT_TILE,     kl + go);
            cp_async16(d + 2*AT_TILE,   vh + go);
            cp_async16(d + 3*AT_TILE,   vl + go);
        }
        cp_commit();
    };

    float O[8][4];
    #pragma unroll
    for (int j = 0; j < 8; j++)
        #pragma unroll
        for (int r = 0; r < 4; r++) O[j][r] = 0.f;
    float ps0 = 0.f, ps1 = 0.f;     // row-sum partials (rows g, g+8)

    const int nt = 2 * (qb + 1);
    const int R  = q0 + warp * 16;

    load_stage(0, 0);
    if (nt > 1) load_stage(1, 1);

    for (int kt = 0; kt < nt; kt++) {
        const int s = kt & 1;
        const int kv0 = kt * 64;
        if (kt + 1 < nt) cp_wait1(); else cp_wait0();
        __syncthreads();

        if (kv0 <= R + 15) {
            const uint32_t st = smb + s * AT_STAGE;

            // ---- S = Q K^T (bf16x3) ----
            float S[8][4];
            #pragma unroll
            for (int j = 0; j < 8; j++)
                #pragma unroll
                for (int r = 0; r < 4; r++) S[j][r] = 0.f;

            #pragma unroll
            for (int kc = 0; kc < 4; kc++) {
                uint32_t kfh[16], kfl[16];
                #pragma unroll
                for (int np = 0; np < 4; np++) {
                    const uint32_t a = st + (np * 16 + brow) * AT_STRIDE + bchk * 16 + kc * 32;
                    ldsm_x4(&kfh[np * 4], a);
                    ldsm_x4(&kfl[np * 4], a + AT_TILE);
                }
                #pragma unroll
                for (int j = 0; j < 8; j++) {
                    const int ix = (j >> 1) * 4 + (j & 1) * 2;
                    mma_bf16(S[j], qfh[kc], kfh[ix], kfh[ix + 1]);
                }
                #pragma unroll
                for (int j = 0; j < 8; j++) {
                    const int ix = (j >> 1) * 4 + (j & 1) * 2;
                    mma_bf16(S[j], qfh[kc], kfl[ix], kfl[ix + 1]);
                }
                #pragma unroll
                for (int j = 0; j < 8; j++) {
                    const int ix = (j >> 1) * 4 + (j & 1) * 2;
                    mma_bf16(S[j], qfl[kc], kfh[ix], kfh[ix + 1]);
                }
            }

            // ---- P = exp(S*0.125 - SHIFT), causal mask -> 0 ----
            const int row0 = R + g, row1 = R + g + 8;
            const bool need_mask = (kv0 + 63 > R);
            #pragma unroll
            for (int j = 0; j < 8; j++) {
                S[j][0] = __expf(fmaf(S[j][0], 0.125f, -SM_SHIFT));
                S[j][1] = __expf(fmaf(S[j][1], 0.125f, -SM_SHIFT));
                S[j][2] = __expf(fmaf(S[j][2], 0.125f, -SM_SHIFT));
                S[j][3] = __expf(fmaf(S[j][3], 0.125f, -SM_SHIFT));
                if (need_mask) {
                    const int c0 = kv0 + 8 * j + 2 * t4;
                    if (c0     > row0) S[j][0] = 0.f;
                    if (c0 + 1 > row0) S[j][1] = 0.f;
                    if (c0     > row1) S[j][2] = 0.f;
                    if (c0 + 1 > row1) S[j][3] = 0.f;
                }
                ps0 += S[j][0] + S[j][1];
                ps1 += S[j][2] + S[j][3];
            }

            // ---- P fragments (hi/lo) ----
            uint32_t ph[4][4], pl[4][4];
            #pragma unroll
            for (int kc = 0; kc < 4; kc++) {
                __nv_bfloat16 ha, la, hb, lb;
                split_bf16(S[2*kc][0], ha, la);  split_bf16(S[2*kc][1], hb, lb);
                ph[kc][0] = pack_bf162(ha, hb);  pl[kc][0] = pack_bf162(la, lb);
                split_bf16(S[2*kc][2], ha, la);  split_bf16(S[2*kc][3], hb, lb);
                ph[kc][1] = pack_bf162(ha, hb);  pl[kc][1] = pack_bf162(la, lb);
                split_bf16(S[2*kc+1][0], ha, la); split_bf16(S[2*kc+1][1], hb, lb);
                ph[kc][2] = pack_bf162(ha, hb);  pl[kc][2] = pack_bf162(la, lb);
                split_bf16(S[2*kc+1][2], ha, la); split_bf16(S[2*kc+1][3], hb, lb);
                ph[kc][3] = pack_bf162(ha, hb);  pl[kc][3] = pack_bf162(la, lb);
            }

            // ---- O += P V (bf16x3) ----
            #pragma unroll
            for (int kc = 0; kc < 4; kc++) {
                uint32_t vfh[16], vfl[16];
                #pragma unroll
                for (int np = 0; np < 4; np++) {
                    const uint32_t a = st + 2*AT_TILE + (kc * 16 + arow) * AT_STRIDE
                                     + np * 32 + achk * 16;
                    ldsm_x4t(&vfh[np * 4], a);
                    ldsm_x4t(&vfl[np * 4], a + AT_TILE);
                }
                #pragma unroll
                for (int j = 0; j < 8; j++) {
                    const int ix = (j >> 1) * 4 + (j & 1) * 2;
                    mma_bf16(O[j], ph[kc], vfh[ix], vfh[ix + 1]);
                }
                #pragma unroll
                for (int j = 0; j < 8; j++) {
                    const int ix = (j >> 1) * 4 + (j & 1) * 2;
                    mma_bf16(O[j], pl[kc], vfh[ix], vfh[ix + 1]);
                }
                #pragma unroll
                for (int j = 0; j < 8; j++) {
                    const int ix = (j >> 1) * 4 + (j & 1) * 2;
                    mma_bf16(O[j], ph[kc], vfl[ix], vfl[ix + 1]);
                }
            }
        }

        __syncthreads();
        if (kt + 2 < nt) load_stage(s, kt + 2);
    }

    // ---- one-time row-sum reduction ----
    ps0 += __shfl_xor_sync(0xffffffffu, ps0, 1);
    ps0 += __shfl_xor_sync(0xffffffffu, ps0, 2);
    ps1 += __shfl_xor_sync(0xffffffffu, ps1, 1);
    ps1 += __shfl_xor_sync(0xffffffffu, ps1, 2);
    const float inv0 = 1.0f / ps0;
    const float inv1 = 1.0f / ps1;

    const int row0 = q0 + warp * 16 + g;
    const int row1 = row0 + 8;
    #pragma unroll
    for (int j = 0; j < 8; j++) {
        const int col = h * HD_ + 8 * j + 2 * t4;
        const size_t o0 = (size_t)(b * T_ + row0) * E_ + col;
        const size_t o1 = (size_t)(b * T_ + row1) * E_ + col;
        __nv_bfloat16 ha, la, hb, lb;
        split_bf16(O[j][0] * inv0, ha, la);
        split_bf16(O[j][1] * inv0, hb, lb);
        *(uint32_t*)&Yh[o0] = pack_bf162(ha, hb);
        *(uint32_t*)&Yl[o0] = pack_bf162(la, lb);
        split_bf16(O[j][2] * inv1, ha, la);
        split_bf16(O[j][3] * inv1, hb, lb);
        *(uint32_t*)&Yh[o1] = pack_bf162(ha, hb);
        *(uint32_t*)&Yl[o1] = pack_bf162(la, lb);
    }
}

// ---------------------------------------------------------------------------
extern "C" void kernel_launch(void* const* d_in, const int* in_sizes, int n_in,
                              void* d_out, int out_size)
{
    const float* x  = (const float*)d_in[0];
    const float* Wq = (const float*)d_in[2];
    const float* bq = (const float*)d_in[3];
    const float* Wk = (const float*)d_in[4];
    const float* bk = (const float*)d_in[5];
    const float* Wv = (const float*)d_in[6];
    const float* bv = (const float*)d_in[7];
    const float* Wp = (const float*)d_in[8];
    const float* bp = (const float*)d_in[9];
    float* out = (float*)d_out;

    __nv_bfloat16 *xh, *xl, *yh, *yl, *qh, *ql, *kh, *kl, *vh, *vl;
    __nv_bfloat16 *wqh, *wql, *wkh, *wkl, *wvh, *wvl, *wph, *wpl;
    cudaGetSymbolAddress((void**)&xh, g_xh);  cudaGetSymbolAddress((void**)&xl, g_xl);
    cudaGetSymbolAddress((void**)&yh, g_yh);  cudaGetSymbolAddress((void**)&yl, g_yl);
    cudaGetSymbolAddress((void**)&qh, g_qh);  cudaGetSymbolAddress((void**)&ql, g_ql);
    cudaGetSymbolAddress((void**)&kh, g_kh);  cudaGetSymbolAddress((void**)&kl, g_kl);
    cudaGetSymbolAddress((void**)&vh, g_vh);  cudaGetSymbolAddress((void**)&vl, g_vl);
    cudaGetSymbolAddress((void**)&wqh, g_wqh);  cudaGetSymbolAddress((void**)&wql, g_wql);
    cudaGetSymbolAddress((void**)&wkh, g_wkh);  cudaGetSymbolAddress((void**)&wkl, g_wkl);
    cudaGetSymbolAddress((void**)&wvh, g_wvh);  cudaGetSymbolAddress((void**)&wvl, g_wvl);
    cudaGetSymbolAddress((void**)&wph, g_wph);  cudaGetSymbolAddress((void**)&wpl, g_wpl);

    cudaFuncSetAttribute(gemm_bf16x3<true>,  cudaFuncAttributeMaxDynamicSharedMemorySize, GS_SMEM);
    cudaFuncSetAttribute(gemm_bf16x3<false>, cudaFuncAttributeMaxDynamicSharedMemorySize, GS_SMEM);
    cudaFuncSetAttribute(attn_tc, cudaFuncAttributeMaxDynamicSharedMemorySize, AT_SMEM);

    // Prep
    split_kernel<<<(M_*E_/4 + 255)/256, 256>>>(x, xh, xl, M_*E_/4);
    dim3 tgrid(E_/32, E_/32, 4), tblk(32, 8);
    tsplit4_kernel<<<tgrid, tblk>>>(Wq, Wk, Wv, Wp,
                                    wqh, wql, wkh, wkl, wvh, wvl, wph, wpl);

    dim3 gemm_grid(E_ / 128, M_ / 128);  // (8, 64)
    gemm_bf16x3<true><<<gemm_grid, 256, GS_SMEM>>>(xh, xl, wqh, wql, bq, nullptr, qh, ql);
    gemm_bf16x3<true><<<gemm_grid, 256, GS_SMEM>>>(xh, xl, wkh, wkl, bk, nullptr, kh, kl);
    gemm_bf16x3<true><<<gemm_grid, 256, GS_SMEM>>>(xh, xl, wvh, wvl, bv, nullptr, vh, vl);

    dim3 attn_grid(T_ / 128, H_, B_);    // (16, 16, 4)
    attn_tc<<<attn_grid, 256, AT_SMEM>>>(qh, ql, kh, kl, vh, vl, yh, yl);

    gemm_bf16x3<false><<<gemm_grid, 256, GS_SMEM>>>(yh, yl, wph, wpl, bp, out, nullptr, nullptr);
}

// round 8
// speedup vs baseline: 1.4422x; 1.4422x over previous
#include <cuda_runtime.h>
#include <cuda_bf16.h>
#include <stdint.h>
#include <math.h>

#define B_  4
#define T_  2048
#define E_  1024
#define H_  16
#define HD_ 64
#define M_  (B_*T_)   // 8192

// Scratch (device globals: allocation-free)
__device__ __nv_bfloat16 g_xh[M_*E_], g_xl[M_*E_];
__device__ __nv_bfloat16 g_yh[M_*E_], g_yl[M_*E_];
__device__ __nv_bfloat16 g_qh[M_*E_], g_ql[M_*E_];
__device__ __nv_bfloat16 g_kh[M_*E_], g_kl[M_*E_];
__device__ __nv_bfloat16 g_vh[M_*E_], g_vl[M_*E_];
__device__ __nv_bfloat16 g_wqh[E_*E_], g_wql[E_*E_];
__device__ __nv_bfloat16 g_wkh[E_*E_], g_wkl[E_*E_];
__device__ __nv_bfloat16 g_wvh[E_*E_], g_wvl[E_*E_];
__device__ __nv_bfloat16 g_wph[E_*E_], g_wpl[E_*E_];

// ---------------------------------------------------------------------------
// helpers
// ---------------------------------------------------------------------------
__device__ __forceinline__ uint32_t smem_u32(const void* p) {
    return (uint32_t)__cvta_generic_to_shared(p);
}
__device__ __forceinline__ void cp_async16(uint32_t dst, const void* src) {
    asm volatile("cp.async.cg.shared.global [%0], [%1], 16;\n" :: "r"(dst), "l"(src));
}
__device__ __forceinline__ void cp_commit() { asm volatile("cp.async.commit_group;\n"); }
__device__ __forceinline__ void cp_wait0() { asm volatile("cp.async.wait_group 0;\n"); }
__device__ __forceinline__ void cp_wait1() { asm volatile("cp.async.wait_group 1;\n"); }

__device__ __forceinline__ void mma_bf16(float c[4], const uint32_t a[4], uint32_t b0, uint32_t b1) {
    asm volatile(
        "mma.sync.aligned.m16n8k16.row.col.f32.bf16.bf16.f32 "
        "{%0,%1,%2,%3}, {%4,%5,%6,%7}, {%8,%9}, {%0,%1,%2,%3};\n"
        : "+f"(c[0]), "+f"(c[1]), "+f"(c[2]), "+f"(c[3])
        : "r"(a[0]), "r"(a[1]), "r"(a[2]), "r"(a[3]), "r"(b0), "r"(b1));
}
__device__ __forceinline__ void ldsm_x4(uint32_t r[4], uint32_t addr) {
    asm volatile("ldmatrix.sync.aligned.m8n8.x4.shared.b16 {%0,%1,%2,%3}, [%4];"
        : "=r"(r[0]), "=r"(r[1]), "=r"(r[2]), "=r"(r[3]) : "r"(addr));
}
__device__ __forceinline__ void ldsm_x4t(uint32_t r[4], uint32_t addr) {
    asm volatile("ldmatrix.sync.aligned.m8n8.x4.trans.shared.b16 {%0,%1,%2,%3}, [%4];"
        : "=r"(r[0]), "=r"(r[1]), "=r"(r[2]), "=r"(r[3]) : "r"(addr));
}
__device__ __forceinline__ void split_bf16(float v, __nv_bfloat16& h, __nv_bfloat16& l) {
    h = __float2bfloat16(v);
    l = __float2bfloat16(v - __bfloat162float(h));
}
__device__ __forceinline__ uint32_t pack_bf162(__nv_bfloat16 a, __nv_bfloat16 b) {
    __nv_bfloat162 p(a, b);
    return *(uint32_t*)&p;
}

// ---------------------------------------------------------------------------
// Prep: split fp32 -> bf16 hi/lo, same layout.
// ---------------------------------------------------------------------------
__global__ void split_kernel(const float* __restrict__ src,
                             __nv_bfloat16* __restrict__ hi,
                             __nv_bfloat16* __restrict__ lo, int n4)
{
    int i = blockIdx.x * blockDim.x + threadIdx.x;
    if (i >= n4) return;
    float4 v = ((const float4*)src)[i];
    __nv_bfloat16 h0,h1,h2,h3,l0,l1,l2,l3;
    split_bf16(v.x,h0,l0); split_bf16(v.y,h1,l1);
    split_bf16(v.z,h2,l2); split_bf16(v.w,h3,l3);
    ((__nv_bfloat162*)hi)[i*2+0] = __nv_bfloat162(h0,h1);
    ((__nv_bfloat162*)hi)[i*2+1] = __nv_bfloat162(h2,h3);
    ((__nv_bfloat162*)lo)[i*2+0] = __nv_bfloat162(l0,l1);
    ((__nv_bfloat162*)lo)[i*2+1] = __nv_bfloat162(l2,l3);
}

// ---------------------------------------------------------------------------
// Prep: transpose + split. W[K][N] fp32 -> Th/Tl[N][K] bf16.
// ---------------------------------------------------------------------------
__global__ void tsplit_kernel(const float* __restrict__ W,
                              __nv_bfloat16* __restrict__ Th,
                              __nv_bfloat16* __restrict__ Tl)
{
    __shared__ float t[32][33];
    const int n0 = blockIdx.x * 32, k0 = blockIdx.y * 32;
    const int tx = threadIdx.x, ty = threadIdx.y;   // (32, 8)
    #pragma unroll
    for (int i = 0; i < 4; i++)
        t[ty + 8*i][tx] = W[(size_t)(k0 + ty + 8*i) * E_ + n0 + tx];
    __syncthreads();
    #pragma unroll
    for (int i = 0; i < 4; i++) {
        const int row = ty + 8*i;
        const float v = t[tx][row];
        __nv_bfloat16 h, l;
        split_bf16(v, h, l);
        Th[(size_t)(n0 + row) * E_ + k0 + tx] = h;
        Tl[(size_t)(n0 + row) * E_ + k0 + tx] = l;
    }
}

// ---------------------------------------------------------------------------
// bf16x3 tensor-core GEMM with ldmatrix + 2-stage cp.async, 2 CTAs/SM.
// REORDER=true:  write split bf16 hi/lo in [B,H,T,hd] layout (Ch, Cl).
// REORDER=false: write fp32 [M][N] (C).
// ---------------------------------------------------------------------------
#define GS_STRIDE 80
#define GS_TILE   (128*GS_STRIDE)      // 10240 B
#define GS_STAGE  (4*GS_TILE)          // 40960 B
#define GS_SMEM   (2*GS_STAGE)         // 81920 B -> 2 CTAs/SM

template<bool REORDER>
__global__ void __launch_bounds__(256, 2) gemm_bf16x3(
    const __nv_bfloat16* __restrict__ Ah, const __nv_bfloat16* __restrict__ Al,
    const __nv_bfloat16* __restrict__ Th, const __nv_bfloat16* __restrict__ Tl,
    const float* __restrict__ bias, float* __restrict__ C,
    __nv_bfloat16* __restrict__ Ch, __nv_bfloat16* __restrict__ Cl)
{
    extern __shared__ char sm[];
    const uint32_t smb = smem_u32(sm);

    const int tid  = threadIdx.x;
    const int warp = tid >> 5;
    const int lane = tid & 31;
    const int group = lane >> 2;
    const int tidg  = lane & 3;

    const int bn = blockIdx.x, bm = blockIdx.y;
    const int m0 = bm * 128, n0 = bn * 128;
    const int warp_m = warp & 1;
    const int warp_n = warp >> 1;

    const int lrow = (lane & 7) + ((lane >> 3) & 1) * 8;
    const int lkb  = ((lane >> 4) & 1) * 16;

    auto load_stage = [&](int s, int c) {
        const int kb = c * 32;
        const uint32_t st = smb + s * GS_STAGE;
        #pragma unroll
        for (int i = 0; i < 2; i++) {
            const int ch = tid + i * 256;
            const int row = ch >> 2, q = ch & 3;
            const uint32_t d = st + row * GS_STRIDE + q * 16;
            const size_t ga = (size_t)(m0 + row) * E_ + kb + q * 8;
            const size_t gb = (size_t)(n0 + row) * E_ + kb + q * 8;
            cp_async16(d,               Ah + ga);
            cp_async16(d + GS_TILE,     Al + ga);
            cp_async16(d + 2*GS_TILE,   Th + gb);
            cp_async16(d + 3*GS_TILE,   Tl + gb);
        }
        cp_commit();
    };

    float acc[4][4][4];
    #pragma unroll
    for (int i = 0; i < 4; i++)
        #pragma unroll
        for (int j = 0; j < 4; j++)
            #pragma unroll
            for (int r = 0; r < 4; r++) acc[i][j][r] = 0.f;

    const int NC = E_ / 32;
    load_stage(0, 0);
    load_stage(1, 1);

    for (int c = 0; c < NC; c++) {
        const int s = c & 1;
        if (c + 1 < NC) cp_wait1(); else cp_wait0();
        __syncthreads();

        const uint32_t st = smb + s * GS_STAGE;
        const uint32_t abase = st + (warp_m * 64 + lrow) * GS_STRIDE + lkb;
        const uint32_t bbase = st + 2*GS_TILE + (warp_n * 32 + lrow) * GS_STRIDE + lkb;

        #pragma unroll
        for (int h2 = 0; h2 < 2; h2++) {
            const int ko = h2 * 32;
            uint32_t ah[4][4], al[4][4], bh[2][4], bl[2][4];
            #pragma unroll
            for (int i = 0; i < 4; i++) {
                ldsm_x4(ah[i], abase + i * 16 * GS_STRIDE + ko);
                ldsm_x4(al[i], abase + GS_TILE + i * 16 * GS_STRIDE + ko);
            }
            #pragma unroll
            for (int g = 0; g < 2; g++) {
                ldsm_x4(bh[g], bbase + g * 16 * GS_STRIDE + ko);
                ldsm_x4(bl[g], bbase + GS_TILE + g * 16 * GS_STRIDE + ko);
            }
            #pragma unroll
            for (int i = 0; i < 4; i++)
                #pragma unroll
                for (int j = 0; j < 4; j++)
                    mma_bf16(acc[i][j], ah[i], bh[j>>1][j&1], bh[j>>1][(j&1)+2]);
            #pragma unroll
            for (int i = 0; i < 4; i++)
                #pragma unroll
                for (int j = 0; j < 4; j++)
                    mma_bf16(acc[i][j], ah[i], bl[j>>1][j&1], bl[j>>1][(j&1)+2]);
            #pragma unroll
            for (int i = 0; i < 4; i++)
                #pragma unroll
                for (int j = 0; j < 4; j++)
                    mma_bf16(acc[i][j], al[i], bh[j>>1][j&1], bh[j>>1][(j&1)+2]);
        }
        __syncthreads();
        if (c + 2 < NC) load_stage(s, c + 2);
    }

    #pragma unroll
    for (int i = 0; i < 4; i++) {
        const int rmb = m0 + warp_m * 64 + i * 16 + group;
        #pragma unroll
        for (int j = 0; j < 4; j++) {
            const int cb = n0 + warp_n * 32 + j * 8 + tidg * 2;
            const float bx = bias[cb], by = bias[cb + 1];
            #pragma unroll
            for (int half = 0; half < 2; half++) {
                const int m = rmb + half * 8;
                const float vx = acc[i][j][half * 2 + 0] + bx;
                const float vy = acc[i][j][half * 2 + 1] + by;
                if (REORDER) {
                    const int b = m >> 11;
                    const int t = m & (T_ - 1);
                    const int h = cb >> 6;
                    const int d = cb & (HD_ - 1);
                    const size_t o = (((size_t)(b * H_ + h) * T_) + t) * HD_ + d;
                    __nv_bfloat16 hx, lx, hy, ly;
                    split_bf16(vx, hx, lx);
                    split_bf16(vy, hy, ly);
                    *(uint32_t*)&Ch[o] = pack_bf162(hx, hy);
                    *(uint32_t*)&Cl[o] = pack_bf162(lx, ly);
                } else {
                    float2 v; v.x = vx; v.y = vy;
                    *(float2*)&C[(size_t)m * E_ + cb] = v;
                }
            }
        }
    }
}

// ---------------------------------------------------------------------------
// Tensor-core flash attention (causal), bf16x3 compensated (R6 version).
// Block = 128 q rows of one (b,h); 8 warps x 16 rows. KV tiles 64, 2 stages.
// ---------------------------------------------------------------------------
#define AT_STRIDE 144
#define AT_TILE   (64*AT_STRIDE)     // 9216
#define AT_STAGE  (4*AT_TILE)        // 36864
#define AT_SMEM   (2*AT_STAGE)       // 73728

__global__ void __launch_bounds__(256) attn_tc(
    const __nv_bfloat16* __restrict__ Qh, const __nv_bfloat16* __restrict__ Ql,
    const __nv_bfloat16* __restrict__ Kh, const __nv_bfloat16* __restrict__ Kl,
    const __nv_bfloat16* __restrict__ Vh, const __nv_bfloat16* __restrict__ Vl,
    __nv_bfloat16* __restrict__ Yh, __nv_bfloat16* __restrict__ Yl)
{
    extern __shared__ char sm[];
    const uint32_t smb = smem_u32(sm);

    const int tid  = threadIdx.x;
    const int warp = tid >> 5;
    const int lane = tid & 31;
    const int g    = lane >> 2;
    const int t4   = lane & 3;

    const int qb = blockIdx.x;
    const int h  = blockIdx.y;
    const int b  = blockIdx.z;
    const int q0 = qb * 128;

    const size_t base = (size_t)(b * H_ + h) * T_ * HD_;
    const __nv_bfloat16* qh = Qh + base + (size_t)q0 * HD_;
    const __nv_bfloat16* ql = Ql + base + (size_t)q0 * HD_;
    const __nv_bfloat16* kh = Kh + base;
    const __nv_bfloat16* kl = Kl + base;
    const __nv_bfloat16* vh = Vh + base;
    const __nv_bfloat16* vl = Vl + base;

    const int arow = (lane & 7) + ((lane >> 3) & 1) * 8;
    const int achk = (lane >> 4) & 1;
    const int brow = (lane & 7) + ((lane >> 4) & 1) * 8;
    const int bchk = (lane >> 3) & 1;

    #pragma unroll
    for (int i = 0; i < 4; i++) {
        const int ch = tid + i * 256;
        const int row = ch >> 3, q = ch & 7;
        const uint32_t d = smb + (row >> 6) * AT_TILE + (row & 63) * AT_STRIDE + q * 16;
        cp_async16(d,               qh + (size_t)row * HD_ + q * 8);
        cp_async16(d + 2*AT_TILE,   ql + (size_t)row * HD_ + q * 8);
    }
    cp_commit(); cp_wait0();
    __syncthreads();

    uint32_t qfh[4][4], qfl[4][4];
    {
        const int wr = warp * 16;
        const uint32_t qbse = smb + (wr >> 6) * AT_TILE + (wr & 63) * AT_STRIDE
                            + arow * AT_STRIDE + achk * 16;
        #pragma unroll
        for (int kc = 0; kc < 4; kc++) {
            ldsm_x4(qfh[kc], qbse + kc * 32);
            ldsm_x4(qfl[kc], qbse + 2*AT_TILE + kc * 32);
        }
    }
    __syncthreads();

    auto load_stage = [&](int s, int kt) {
        const int kv0 = kt * 64;
        const uint32_t st = smb + s * AT_STAGE;
        #pragma unroll
        for (int i = 0; i < 2; i++) {
            const int ch = tid + i * 256;
            const int row = ch >> 3, q = ch & 7;
            const uint32_t d = st + row * AT_STRIDE + q * 16;
            const size_t go = (size_t)(kv0 + row) * HD_ + q * 8;
            cp_async16(d,               kh + go);
            cp_async16(d + AT_TILE,     kl + go);
            cp_async16(d + 2*AT_TILE,   vh + go);
            cp_async16(d + 3*AT_TILE,   vl + go);
        }
        cp_commit();
    };

    float O[8][4];
    #pragma unroll
    for (int j = 0; j < 8; j++)
        #pragma unroll
        for (int r = 0; r < 4; r++) O[j][r] = 0.f;
    float m0 = -1e30f, m1 = -1e30f, l0 = 0.f, l1 = 0.f;

    const int nt = 2 * (qb + 1);
    const int R  = q0 + warp * 16;

    load_stage(0, 0);
    if (nt > 1) load_stage(1, 1);

    for (int kt = 0; kt < nt; kt++) {
        const int s = kt & 1;
        const int kv0 = kt * 64;
        if (kt + 1 < nt) cp_wait1(); else cp_wait0();
        __syncthreads();

        if (kv0 <= R + 15) {
            const uint32_t st = smb + s * AT_STAGE;

            float S[8][4];
            #pragma unroll
            for (int j = 0; j < 8; j++)
                #pragma unroll
                for (int r = 0; r < 4; r++) S[j][r] = 0.f;

            #pragma unroll
            for (int kc = 0; kc < 4; kc++) {
                uint32_t kfh[16], kfl[16];
                #pragma unroll
                for (int np = 0; np < 4; np++) {
                    const uint32_t a = st + (np * 16 + brow) * AT_STRIDE + bchk * 16 + kc * 32;
                    ldsm_x4(&kfh[np * 4], a);
                    ldsm_x4(&kfl[np * 4], a + AT_TILE);
                }
                #pragma unroll
                for (int j = 0; j < 8; j++) {
                    const int ix = (j >> 1) * 4 + (j & 1) * 2;
                    mma_bf16(S[j], qfh[kc], kfh[ix], kfh[ix + 1]);
                }
                #pragma unroll
                for (int j = 0; j < 8; j++) {
                    const int ix = (j >> 1) * 4 + (j & 1) * 2;
                    mma_bf16(S[j], qfh[kc], kfl[ix], kfl[ix + 1]);
                }
                #pragma unroll
                for (int j = 0; j < 8; j++) {
                    const int ix = (j >> 1) * 4 + (j & 1) * 2;
                    mma_bf16(S[j], qfl[kc], kfh[ix], kfh[ix + 1]);
                }
            }

            const int row0 = R + g, row1 = R + g + 8;
            const bool need_mask = (kv0 + 63 > R);
            #pragma unroll
            for (int j = 0; j < 8; j++) {
                #pragma unroll
                for (int r = 0; r < 4; r++) S[j][r] *= 0.125f;
                if (need_mask) {
                    const int c0 = kv0 + 8 * j + 2 * t4;
                    if (c0     > row0) S[j][0] = -1e30f;
                    if (c0 + 1 > row0) S[j][1] = -1e30f;
                    if (c0     > row1) S[j][2] = -1e30f;
                    if (c0 + 1 > row1) S[j][3] = -1e30f;
                }
            }

            float mx0 = -1e30f, mx1 = -1e30f;
            #pragma unroll
            for (int j = 0; j < 8; j++) {
                mx0 = fmaxf(mx0, fmaxf(S[j][0], S[j][1]));
                mx1 = fmaxf(mx1, fmaxf(S[j][2], S[j][3]));
            }
            mx0 = fmaxf(mx0, __shfl_xor_sync(0xffffffffu, mx0, 1));
            mx0 = fmaxf(mx0, __shfl_xor_sync(0xffffffffu, mx0, 2));
            mx1 = fmaxf(mx1, __shfl_xor_sync(0xffffffffu, mx1, 1));
            mx1 = fmaxf(mx1, __shfl_xor_sync(0xffffffffu, mx1, 2));

            const float nm0 = fmaxf(m0, mx0);
            const float nm1 = fmaxf(m1, mx1);
            const float cr0 = __expf(m0 - nm0);
            const float cr1 = __expf(m1 - nm1);

            float s0 = 0.f, s1 = 0.f;
            #pragma unroll
            for (int j = 0; j < 8; j++) {
                S[j][0] = __expf(S[j][0] - nm0);
                S[j][1] = __expf(S[j][1] - nm0);
                S[j][2] = __expf(S[j][2] - nm1);
                S[j][3] = __expf(S[j][3] - nm1);
                s0 += S[j][0] + S[j][1];
                s1 += S[j][2] + S[j][3];
            }
            s0 += __shfl_xor_sync(0xffffffffu, s0, 1);
            s0 += __shfl_xor_sync(0xffffffffu, s0, 2);
            s1 += __shfl_xor_sync(0xffffffffu, s1, 1);
            s1 += __shfl_xor_sync(0xffffffffu, s1, 2);

            l0 = l0 * cr0 + s0;  m0 = nm0;
            l1 = l1 * cr1 + s1;  m1 = nm1;

            #pragma unroll
            for (int j = 0; j < 8; j++) {
                O[j][0] *= cr0;  O[j][1] *= cr0;
                O[j][2] *= cr1;  O[j][3] *= cr1;
            }

            uint32_t ph[4][4], pl[4][4];
            #pragma unroll
            for (int kc = 0; kc < 4; kc++) {
                __nv_bfloat16 ha, la, hb, lb;
                split_bf16(S[2*kc][0], ha, la);  split_bf16(S[2*kc][1], hb, lb);
                ph[kc][0] = pack_bf162(ha, hb);  pl[kc][0] = pack_bf162(la, lb);
                split_bf16(S[2*kc][2], ha, la);  split_bf16(S[2*kc][3], hb, lb);
                ph[kc][1] = pack_bf162(ha, hb);  pl[kc][1] = pack_bf162(la, lb);
                split_bf16(S[2*kc+1][0], ha, la); split_bf16(S[2*kc+1][1], hb, lb);
                ph[kc][2] = pack_bf162(ha, hb);  pl[kc][2] = pack_bf162(la, lb);
                split_bf16(S[2*kc+1][2], ha, la); split_bf16(S[2*kc+1][3], hb, lb);
                ph[kc][3] = pack_bf162(ha, hb);  pl[kc][3] = pack_bf162(la, lb);
            }

            #pragma unroll
            for (int kc = 0; kc < 4; kc++) {
                uint32_t vfh[16], vfl[16];
                #pragma unroll
                for (int np = 0; np < 4; np++) {
                    const uint32_t a = st + 2*AT_TILE + (kc * 16 + arow) * AT_STRIDE
                                     + np * 32 + achk * 16;
                    ldsm_x4t(&vfh[np * 4], a);
                    ldsm_x4t(&vfl[np * 4], a + AT_TILE);
                }
                #pragma unroll
                for (int j = 0; j < 8; j++) {
                    const int ix = (j >> 1) * 4 + (j & 1) * 2;
                    mma_bf16(O[j], ph[kc], vfh[ix], vfh[ix + 1]);
                }
                #pragma unroll
                for (int j = 0; j < 8; j++) {
                    const int ix = (j >> 1) * 4 + (j & 1) * 2;
                    mma_bf16(O[j], pl[kc], vfh[ix], vfh[ix + 1]);
                }
                #pragma unroll
                for (int j = 0; j < 8; j++) {
                    const int ix = (j >> 1) * 4 + (j & 1) * 2;
                    mma_bf16(O[j], ph[kc], vfl[ix], vfl[ix + 1]);
                }
            }
        }

        __syncthreads();
        if (kt + 2 < nt) load_stage(s, kt + 2);
    }

    const float inv0 = 1.0f / l0;
    const float inv1 = 1.0f / l1;
    const int row0 = q0 + warp * 16 + g;
    const int row1 = row0 + 8;
    #pragma unroll
    for (int j = 0; j < 8; j++) {
        const int col = h * HD_ + 8 * j + 2 * t4;
        const size_t o0 = (size_t)(b * T_ + row0) * E_ + col;
        const size_t o1 = (size_t)(b * T_ + row1) * E_ + col;
        __nv_bfloat16 ha, la, hb, lb;
        split_bf16(O[j][0] * inv0, ha, la);
        split_bf16(O[j][1] * inv0, hb, lb);
        *(uint32_t*)&Yh[o0] = pack_bf162(ha, hb);
        *(uint32_t*)&Yl[o0] = pack_bf162(la, lb);
        split_bf16(O[j][2] * inv1, ha, la);
        split_bf16(O[j][3] * inv1, hb, lb);
        *(uint32_t*)&Yh[o1] = pack_bf162(ha, hb);
        *(uint32_t*)&Yl[o1] = pack_bf162(la, lb);
    }
}

// ---------------------------------------------------------------------------
extern "C" void kernel_launch(void* const* d_in, const int* in_sizes, int n_in,
                              void* d_out, int out_size)
{
    const float* x  = (const float*)d_in[0];
    const float* Wq = (const float*)d_in[2];
    const float* bq = (const float*)d_in[3];
    const float* Wk = (const float*)d_in[4];
    const float* bk = (const float*)d_in[5];
    const float* Wv = (const float*)d_in[6];
    const float* bv = (const float*)d_in[7];
    const float* Wp = (const float*)d_in[8];
    const float* bp = (const float*)d_in[9];
    float* out = (float*)d_out;

    __nv_bfloat16 *xh, *xl, *yh, *yl, *qh, *ql, *kh, *kl, *vh, *vl;
    __nv_bfloat16 *wqh, *wql, *wkh, *wkl, *wvh, *wvl, *wph, *wpl;
    cudaGetSymbolAddress((void**)&xh, g_xh);  cudaGetSymbolAddress((void**)&xl, g_xl);
    cudaGetSymbolAddress((void**)&yh, g_yh);  cudaGetSymbolAddress((void**)&yl, g_yl);
    cudaGetSymbolAddress((void**)&qh, g_qh);  cudaGetSymbolAddress((void**)&ql, g_ql);
    cudaGetSymbolAddress((void**)&kh, g_kh);  cudaGetSymbolAddress((void**)&kl, g_kl);
    cudaGetSymbolAddress((void**)&vh, g_vh);  cudaGetSymbolAddress((void**)&vl, g_vl);
    cudaGetSymbolAddress((void**)&wqh, g_wqh);  cudaGetSymbolAddress((void**)&wql, g_wql);
    cudaGetSymbolAddress((void**)&wkh, g_wkh);  cudaGetSymbolAddress((void**)&wkl, g_wkl);
    cudaGetSymbolAddress((void**)&wvh, g_wvh);  cudaGetSymbolAddress((void**)&wvl, g_wvl);
    cudaGetSymbolAddress((void**)&wph, g_wph);  cudaGetSymbolAddress((void**)&wpl, g_wpl);

    cudaFuncSetAttribute(gemm_bf16x3<true>,  cudaFuncAttributeMaxDynamicSharedMemorySize, GS_SMEM);
    cudaFuncSetAttribute(gemm_bf16x3<false>, cudaFuncAttributeMaxDynamicSharedMemorySize, GS_SMEM);
    cudaFuncSetAttribute(attn_tc, cudaFuncAttributeMaxDynamicSharedMemorySize, AT_SMEM);

    // Prep: split x, transpose+split weights
    split_kernel<<<(M_*E_/4 + 255)/256, 256>>>(x, xh, xl, M_*E_/4);
    dim3 tgrid(E_/32, E_/32), tblk(32, 8);
    tsplit_kernel<<<tgrid, tblk>>>(Wq, wqh, wql);
    tsplit_kernel<<<tgrid, tblk>>>(Wk, wkh, wkl);
    tsplit_kernel<<<tgrid, tblk>>>(Wv, wvh, wvl);
    tsplit_kernel<<<tgrid, tblk>>>(Wp, wph, wpl);

    dim3 gemm_grid(E_ / 128, M_ / 128);  // (8, 64)
    gemm_bf16x3<true><<<gemm_grid, 256, GS_SMEM>>>(xh, xl, wqh, wql, bq, nullptr, qh, ql);
    gemm_bf16x3<true><<<gemm_grid, 256, GS_SMEM>>>(xh, xl, wkh, wkl, bk, nullptr, kh, kl);
    gemm_bf16x3<true><<<gemm_grid, 256, GS_SMEM>>>(xh, xl, wvh, wvl, bv, nullptr, vh, vl);

    dim3 attn_grid(T_ / 128, H_, B_);    // (16, 16, 4)
    attn_tc<<<attn_grid, 256, AT_SMEM>>>(qh, ql, kh, kl, vh, vl, yh, yl);

    gemm_bf16x3<false><<<gemm_grid, 256, GS_SMEM>>>(yh, yl, wph, wpl, bp, out, nullptr, nullptr);
}

// round 9
// speedup vs baseline: 1.5260x; 1.0581x over previous
#include <cuda_runtime.h>
#include <cuda_bf16.h>
#include <stdint.h>
#include <math.h>

#define B_  4
#define T_  2048
#define E_  1024
#define H_  16
#define HD_ 64
#define M_  (B_*T_)   // 8192

// Scratch (device globals: allocation-free)
__device__ __nv_bfloat16 g_xh[M_*E_], g_xl[M_*E_];
__device__ __nv_bfloat16 g_yh[M_*E_], g_yl[M_*E_];
__device__ __nv_bfloat16 g_qh[M_*E_], g_ql[M_*E_];
__device__ __nv_bfloat16 g_kh[M_*E_], g_kl[M_*E_];
__device__ __nv_bfloat16 g_vh[M_*E_], g_vl[M_*E_];
__device__ __nv_bfloat16 g_wqh[E_*E_], g_wql[E_*E_];
__device__ __nv_bfloat16 g_wkh[E_*E_], g_wkl[E_*E_];
__device__ __nv_bfloat16 g_wvh[E_*E_], g_wvl[E_*E_];
__device__ __nv_bfloat16 g_wph[E_*E_], g_wpl[E_*E_];

// ---------------------------------------------------------------------------
// helpers
// ---------------------------------------------------------------------------
__device__ __forceinline__ uint32_t smem_u32(const void* p) {
    return (uint32_t)__cvta_generic_to_shared(p);
}
__device__ __forceinline__ void cp_async16(uint32_t dst, const void* src) {
    asm volatile("cp.async.cg.shared.global [%0], [%1], 16;\n" :: "r"(dst), "l"(src));
}
__device__ __forceinline__ void cp_commit() { asm volatile("cp.async.commit_group;\n"); }
__device__ __forceinline__ void cp_wait0() { asm volatile("cp.async.wait_group 0;\n"); }
__device__ __forceinline__ void cp_wait1() { asm volatile("cp.async.wait_group 1;\n"); }

__device__ __forceinline__ void mma_bf16(float c[4], const uint32_t a[4], uint32_t b0, uint32_t b1) {
    asm volatile(
        "mma.sync.aligned.m16n8k16.row.col.f32.bf16.bf16.f32 "
        "{%0,%1,%2,%3}, {%4,%5,%6,%7}, {%8,%9}, {%0,%1,%2,%3};\n"
        : "+f"(c[0]), "+f"(c[1]), "+f"(c[2]), "+f"(c[3])
        : "r"(a[0]), "r"(a[1]), "r"(a[2]), "r"(a[3]), "r"(b0), "r"(b1));
}
__device__ __forceinline__ void ldsm_x4(uint32_t r[4], uint32_t addr) {
    asm volatile("ldmatrix.sync.aligned.m8n8.x4.shared.b16 {%0,%1,%2,%3}, [%4];"
        : "=r"(r[0]), "=r"(r[1]), "=r"(r[2]), "=r"(r[3]) : "r"(addr));
}
__device__ __forceinline__ void ldsm_x4t(uint32_t r[4], uint32_t addr) {
    asm volatile("ldmatrix.sync.aligned.m8n8.x4.trans.shared.b16 {%0,%1,%2,%3}, [%4];"
        : "=r"(r[0]), "=r"(r[1]), "=r"(r[2]), "=r"(r[3]) : "r"(addr));
}
__device__ __forceinline__ void split_bf16(float v, __nv_bfloat16& h, __nv_bfloat16& l) {
    h = __float2bfloat16(v);
    l = __float2bfloat16(v - __bfloat162float(h));
}
__device__ __forceinline__ uint32_t pack_bf162(__nv_bfloat16 a, __nv_bfloat16 b) {
    __nv_bfloat162 p(a, b);
    return *(uint32_t*)&p;
}

// ---------------------------------------------------------------------------
// Prep: split fp32 -> bf16 hi/lo, same layout.
// ---------------------------------------------------------------------------
__global__ void split_kernel(const float* __restrict__ src,
                             __nv_bfloat16* __restrict__ hi,
                             __nv_bfloat16* __restrict__ lo, int n4)
{
    int i = blockIdx.x * blockDim.x + threadIdx.x;
    if (i >= n4) return;
    float4 v = ((const float4*)src)[i];
    __nv_bfloat16 h0,h1,h2,h3,l0,l1,l2,l3;
    split_bf16(v.x,h0,l0); split_bf16(v.y,h1,l1);
    split_bf16(v.z,h2,l2); split_bf16(v.w,h3,l3);
    ((__nv_bfloat162*)hi)[i*2+0] = __nv_bfloat162(h0,h1);
    ((__nv_bfloat162*)hi)[i*2+1] = __nv_bfloat162(h2,h3);
    ((__nv_bfloat162*)lo)[i*2+0] = __nv_bfloat162(l0,l1);
    ((__nv_bfloat162*)lo)[i*2+1] = __nv_bfloat162(l2,l3);
}

// ---------------------------------------------------------------------------
// Prep: transpose + split. W[K][N] fp32 -> Th/Tl[N][K] bf16.
// ---------------------------------------------------------------------------
__global__ void tsplit_kernel(const float* __restrict__ W,
                              __nv_bfloat16* __restrict__ Th,
                              __nv_bfloat16* __restrict__ Tl)
{
    __shared__ float t[32][33];
    const int n0 = blockIdx.x * 32, k0 = blockIdx.y * 32;
    const int tx = threadIdx.x, ty = threadIdx.y;   // (32, 8)
    #pragma unroll
    for (int i = 0; i < 4; i++)
        t[ty + 8*i][tx] = W[(size_t)(k0 + ty + 8*i) * E_ + n0 + tx];
    __syncthreads();
    #pragma unroll
    for (int i = 0; i < 4; i++) {
        const int row = ty + 8*i;
        const float v = t[tx][row];
        __nv_bfloat16 h, l;
        split_bf16(v, h, l);
        Th[(size_t)(n0 + row) * E_ + k0 + tx] = h;
        Tl[(size_t)(n0 + row) * E_ + k0 + tx] = l;
    }
}

// ---------------------------------------------------------------------------
// bf16x3 tensor-core GEMM, 3-stage cp.async, SINGLE barrier per iteration.
// REORDER=true:  write split bf16 hi/lo in [B,H,T,hd] layout (Ch, Cl).
// REORDER=false: write fp32 [M][N] (C).
// ---------------------------------------------------------------------------
#define GS_STRIDE 80
#define GS_TILE   (128*GS_STRIDE)      // 10240 B
#define GS_STAGE  (4*GS_TILE)          // 40960 B
#define GS_SMEM   (3*GS_STAGE)         // 122880 B

template<bool REORDER>
__global__ void __launch_bounds__(256) gemm_bf16x3(
    const __nv_bfloat16* __restrict__ Ah, const __nv_bfloat16* __restrict__ Al,
    const __nv_bfloat16* __restrict__ Th, const __nv_bfloat16* __restrict__ Tl,
    const float* __restrict__ bias, float* __restrict__ C,
    __nv_bfloat16* __restrict__ Ch, __nv_bfloat16* __restrict__ Cl)
{
    extern __shared__ char sm[];
    const uint32_t smb = smem_u32(sm);

    const int tid  = threadIdx.x;
    const int warp = tid >> 5;
    const int lane = tid & 31;
    const int group = lane >> 2;
    const int tidg  = lane & 3;

    const int bn = blockIdx.x, bm = blockIdx.y;
    const int m0 = bm * 128, n0 = bn * 128;
    const int warp_m = warp & 1;
    const int warp_n = warp >> 1;

    const int lrow = (lane & 7) + ((lane >> 3) & 1) * 8;
    const int lkb  = ((lane >> 4) & 1) * 16;

    auto load_stage = [&](int s, int c) {
        const int kb = c * 32;
        const uint32_t st = smb + s * GS_STAGE;
        #pragma unroll
        for (int i = 0; i < 2; i++) {
            const int ch = tid + i * 256;
            const int row = ch >> 2, q = ch & 3;
            const uint32_t d = st + row * GS_STRIDE + q * 16;
            const size_t ga = (size_t)(m0 + row) * E_ + kb + q * 8;
            const size_t gb = (size_t)(n0 + row) * E_ + kb + q * 8;
            cp_async16(d,               Ah + ga);
            cp_async16(d + GS_TILE,     Al + ga);
            cp_async16(d + 2*GS_TILE,   Th + gb);
            cp_async16(d + 3*GS_TILE,   Tl + gb);
        }
        cp_commit();
    };

    float acc[4][4][4];
    #pragma unroll
    for (int i = 0; i < 4; i++)
        #pragma unroll
        for (int j = 0; j < 4; j++)
            #pragma unroll
            for (int r = 0; r < 4; r++) acc[i][j][r] = 0.f;

    const int NC = E_ / 32;
    load_stage(0, 0);
    load_stage(1, 1);

    for (int c = 0; c < NC; c++) {
        const int s = c % 3;
        if (c + 1 < NC) cp_wait1(); else cp_wait0();
        __syncthreads();
        // refill stage consumed at iteration c-1 (barrier above proves done)
        if (c + 2 < NC) load_stage((c + 2) % 3, c + 2);

        const uint32_t st = smb + s * GS_STAGE;
        const uint32_t abase = st + (warp_m * 64 + lrow) * GS_STRIDE + lkb;
        const uint32_t bbase = st + 2*GS_TILE + (warp_n * 32 + lrow) * GS_STRIDE + lkb;

        #pragma unroll
        for (int h2 = 0; h2 < 2; h2++) {
            const int ko = h2 * 32;
            uint32_t ah[4][4], al[4][4], bh[2][4], bl[2][4];
            #pragma unroll
            for (int i = 0; i < 4; i++) {
                ldsm_x4(ah[i], abase + i * 16 * GS_STRIDE + ko);
                ldsm_x4(al[i], abase + GS_TILE + i * 16 * GS_STRIDE + ko);
            }
            #pragma unroll
            for (int g = 0; g < 2; g++) {
                ldsm_x4(bh[g], bbase + g * 16 * GS_STRIDE + ko);
                ldsm_x4(bl[g], bbase + GS_TILE + g * 16 * GS_STRIDE + ko);
            }
            #pragma unroll
            for (int i = 0; i < 4; i++)
                #pragma unroll
                for (int j = 0; j < 4; j++)
                    mma_bf16(acc[i][j], ah[i], bh[j>>1][j&1], bh[j>>1][(j&1)+2]);
            #pragma unroll
            for (int i = 0; i < 4; i++)
                #pragma unroll
                for (int j = 0; j < 4; j++)
                    mma_bf16(acc[i][j], ah[i], bl[j>>1][j&1], bl[j>>1][(j&1)+2]);
            #pragma unroll
            for (int i = 0; i < 4; i++)
                #pragma unroll
                for (int j = 0; j < 4; j++)
                    mma_bf16(acc[i][j], al[i], bh[j>>1][j&1], bh[j>>1][(j&1)+2]);
        }
    }

    #pragma unroll
    for (int i = 0; i < 4; i++) {
        const int rmb = m0 + warp_m * 64 + i * 16 + group;
        #pragma unroll
        for (int j = 0; j < 4; j++) {
            const int cb = n0 + warp_n * 32 + j * 8 + tidg * 2;
            const float bx = bias[cb], by = bias[cb + 1];
            #pragma unroll
            for (int half = 0; half < 2; half++) {
                const int m = rmb + half * 8;
                const float vx = acc[i][j][half * 2 + 0] + bx;
                const float vy = acc[i][j][half * 2 + 1] + by;
                if (REORDER) {
                    const int b = m >> 11;
                    const int t = m & (T_ - 1);
                    const int h = cb >> 6;
                    const int d = cb & (HD_ - 1);
                    const size_t o = (((size_t)(b * H_ + h) * T_) + t) * HD_ + d;
                    __nv_bfloat16 hx, lx, hy, ly;
                    split_bf16(vx, hx, lx);
                    split_bf16(vy, hy, ly);
                    *(uint32_t*)&Ch[o] = pack_bf162(hx, hy);
                    *(uint32_t*)&Cl[o] = pack_bf162(lx, ly);
                } else {
                    float2 v; v.x = vx; v.y = vy;
                    *(float2*)&C[(size_t)m * E_ + cb] = v;
                }
            }
        }
    }
}

// ---------------------------------------------------------------------------
// Tensor-core flash attention (causal), bf16x3, online softmax (R6 math).
// 3-stage cp.async, single barrier per KV tile. Heavy blocks first.
// Block = 128 q rows of one (b,h); 8 warps x 16 rows. KV tiles 64.
// ---------------------------------------------------------------------------
#define AT_STRIDE 144
#define AT_TILE   (64*AT_STRIDE)     // 9216
#define AT_STAGE  (4*AT_TILE)        // 36864
#define AT_SMEM   (3*AT_STAGE)       // 110592 -> 2 CTAs/SM

__global__ void __launch_bounds__(256) attn_tc(
    const __nv_bfloat16* __restrict__ Qh, const __nv_bfloat16* __restrict__ Ql,
    const __nv_bfloat16* __restrict__ Kh, const __nv_bfloat16* __restrict__ Kl,
    const __nv_bfloat16* __restrict__ Vh, const __nv_bfloat16* __restrict__ Vl,
    __nv_bfloat16* __restrict__ Yh, __nv_bfloat16* __restrict__ Yl)
{
    extern __shared__ char sm[];
    const uint32_t smb = smem_u32(sm);

    const int tid  = threadIdx.x;
    const int warp = tid >> 5;
    const int lane = tid & 31;
    const int g    = lane >> 2;
    const int t4   = lane & 3;

    // heavy-first: largest qb scheduled earliest
    const int qb = (int)gridDim.x - 1 - (int)blockIdx.x;
    const int h  = blockIdx.y;
    const int b  = blockIdx.z;
    const int q0 = qb * 128;

    const size_t base = (size_t)(b * H_ + h) * T_ * HD_;
    const __nv_bfloat16* qh = Qh + base + (size_t)q0 * HD_;
    const __nv_bfloat16* ql = Ql + base + (size_t)q0 * HD_;
    const __nv_bfloat16* kh = Kh + base;
    const __nv_bfloat16* kl = Kl + base;
    const __nv_bfloat16* vh = Vh + base;
    const __nv_bfloat16* vl = Vl + base;

    const int arow = (lane & 7) + ((lane >> 3) & 1) * 8;
    const int achk = (lane >> 4) & 1;
    const int brow = (lane & 7) + ((lane >> 4) & 1) * 8;
    const int bchk = (lane >> 3) & 1;

    // ---- load Q (128x64 hi/lo) into stage-0 region, pull into fragments ----
    #pragma unroll
    for (int i = 0; i < 4; i++) {
        const int ch = tid + i * 256;
        const int row = ch >> 3, q = ch & 7;
        const uint32_t d = smb + (row >> 6) * AT_TILE + (row & 63) * AT_STRIDE + q * 16;
        cp_async16(d,               qh + (size_t)row * HD_ + q * 8);
        cp_async16(d + 2*AT_TILE,   ql + (size_t)row * HD_ + q * 8);
    }
    cp_commit(); cp_wait0();
    __syncthreads();

    uint32_t qfh[4][4], qfl[4][4];
    {
        const int wr = warp * 16;
        const uint32_t qbse = smb + (wr >> 6) * AT_TILE + (wr & 63) * AT_STRIDE
                            + arow * AT_STRIDE + achk * 16;
        #pragma unroll
        for (int kc = 0; kc < 4; kc++) {
            ldsm_x4(qfh[kc], qbse + kc * 32);
            ldsm_x4(qfl[kc], qbse + 2*AT_TILE + kc * 32);
        }
    }
    __syncthreads();

    auto load_stage = [&](int s, int kt) {
        const int kv0 = kt * 64;
        const uint32_t st = smb + s * AT_STAGE;
        #pragma unroll
        for (int i = 0; i < 2; i++) {
            const int ch = tid + i * 256;
            const int row = ch >> 3, q = ch & 7;
            const uint32_t d = st + row * AT_STRIDE + q * 16;
            const size_t go = (size_t)(kv0 + row) * HD_ + q * 8;
            cp_async16(d,               kh + go);
            cp_async16(d + AT_TILE,     kl + go);
            cp_async16(d + 2*AT_TILE,   vh + go);
            cp_async16(d + 3*AT_TILE,   vl + go);
        }
        cp_commit();
    };

    float O[8][4];
    #pragma unroll
    for (int j = 0; j < 8; j++)
        #pragma unroll
        for (int r = 0; r < 4; r++) O[j][r] = 0.f;
    float m0 = -1e30f, m1 = -1e30f, l0 = 0.f, l1 = 0.f;

    const int nt = 2 * (qb + 1);
    const int R  = q0 + warp * 16;

    load_stage(0, 0);
    if (nt > 1) load_stage(1, 1);

    for (int kt = 0; kt < nt; kt++) {
        const int s = kt % 3;
        const int kv0 = kt * 64;
        if (kt + 1 < nt) cp_wait1(); else cp_wait0();
        __syncthreads();
        if (kt + 2 < nt) load_stage((kt + 2) % 3, kt + 2);

        if (kv0 <= R + 15) {
            const uint32_t st = smb + s * AT_STAGE;

            float S[8][4];
            #pragma unroll
            for (int j = 0; j < 8; j++)
                #pragma unroll
                for (int r = 0; r < 4; r++) S[j][r] = 0.f;

            #pragma unroll
            for (int kc = 0; kc < 4; kc++) {
                uint32_t kfh[16], kfl[16];
                #pragma unroll
                for (int np = 0; np < 4; np++) {
                    const uint32_t a = st + (np * 16 + brow) * AT_STRIDE + bchk * 16 + kc * 32;
                    ldsm_x4(&kfh[np * 4], a);
                    ldsm_x4(&kfl[np * 4], a + AT_TILE);
                }
                #pragma unroll
                for (int j = 0; j < 8; j++) {
                    const int ix = (j >> 1) * 4 + (j & 1) * 2;
                    mma_bf16(S[j], qfh[kc], kfh[ix], kfh[ix + 1]);
                }
                #pragma unroll
                for (int j = 0; j < 8; j++) {
                    const int ix = (j >> 1) * 4 + (j & 1) * 2;
                    mma_bf16(S[j], qfh[kc], kfl[ix], kfl[ix + 1]);
                }
                #pragma unroll
                for (int j = 0; j < 8; j++) {
                    const int ix = (j >> 1) * 4 + (j & 1) * 2;
                    mma_bf16(S[j], qfl[kc], kfh[ix], kfh[ix + 1]);
                }
            }

            const int row0 = R + g, row1 = R + g + 8;
            const bool need_mask = (kv0 + 63 > R);
            #pragma unroll
            for (int j = 0; j < 8; j++) {
                #pragma unroll
                for (int r = 0; r < 4; r++) S[j][r] *= 0.125f;
                if (need_mask) {
                    const int c0 = kv0 + 8 * j + 2 * t4;
                    if (c0     > row0) S[j][0] = -1e30f;
                    if (c0 + 1 > row0) S[j][1] = -1e30f;
                    if (c0     > row1) S[j][2] = -1e30f;
                    if (c0 + 1 > row1) S[j][3] = -1e30f;
                }
            }

            float mx0 = -1e30f, mx1 = -1e30f;
            #pragma unroll
            for (int j = 0; j < 8; j++) {
                mx0 = fmaxf(mx0, fmaxf(S[j][0], S[j][1]));
                mx1 = fmaxf(mx1, fmaxf(S[j][2], S[j][3]));
            }
            mx0 = fmaxf(mx0, __shfl_xor_sync(0xffffffffu, mx0, 1));
            mx0 = fmaxf(mx0, __shfl_xor_sync(0xffffffffu, mx0, 2));
            mx1 = fmaxf(mx1, __shfl_xor_sync(0xffffffffu, mx1, 1));
            mx1 = fmaxf(mx1, __shfl_xor_sync(0xffffffffu, mx1, 2));

            const float nm0 = fmaxf(m0, mx0);
            const float nm1 = fmaxf(m1, mx1);
            const float cr0 = __expf(m0 - nm0);
            const float cr1 = __expf(m1 - nm1);

            float s0 = 0.f, s1 = 0.f;
            #pragma unroll
            for (int j = 0; j < 8; j++) {
                S[j][0] = __expf(S[j][0] - nm0);
                S[j][1] = __expf(S[j][1] - nm0);
                S[j][2] = __expf(S[j][2] - nm1);
                S[j][3] = __expf(S[j][3] - nm1);
                s0 += S[j][0] + S[j][1];
                s1 += S[j][2] + S[j][3];
            }
            s0 += __shfl_xor_sync(0xffffffffu, s0, 1);
            s0 += __shfl_xor_sync(0xffffffffu, s0, 2);
            s1 += __shfl_xor_sync(0xffffffffu, s1, 1);
            s1 += __shfl_xor_sync(0xffffffffu, s1, 2);

            l0 = l0 * cr0 + s0;  m0 = nm0;
            l1 = l1 * cr1 + s1;  m1 = nm1;

            #pragma unroll
            for (int j = 0; j < 8; j++) {
                O[j][0] *= cr0;  O[j][1] *= cr0;
                O[j][2] *= cr1;  O[j][3] *= cr1;
            }

            uint32_t ph[4][4], pl[4][4];
            #pragma unroll
            for (int kc = 0; kc < 4; kc++) {
                __nv_bfloat16 ha, la, hb, lb;
                split_bf16(S[2*kc][0], ha, la);  split_bf16(S[2*kc][1], hb, lb);
                ph[kc][0] = pack_bf162(ha, hb);  pl[kc][0] = pack_bf162(la, lb);
                split_bf16(S[2*kc][2], ha, la);  split_bf16(S[2*kc][3], hb, lb);
                ph[kc][1] = pack_bf162(ha, hb);  pl[kc][1] = pack_bf162(la, lb);
                split_bf16(S[2*kc+1][0], ha, la); split_bf16(S[2*kc+1][1], hb, lb);
                ph[kc][2] = pack_bf162(ha, hb);  pl[kc][2] = pack_bf162(la, lb);
                split_bf16(S[2*kc+1][2], ha, la); split_bf16(S[2*kc+1][3], hb, lb);
                ph[kc][3] = pack_bf162(ha, hb);  pl[kc][3] = pack_bf162(la, lb);
            }

            #pragma unroll
            for (int kc = 0; kc < 4; kc++) {
                uint32_t vfh[16], vfl[16];
                #pragma unroll
                for (int np = 0; np < 4; np++) {
                    const uint32_t a = st + 2*AT_TILE + (kc * 16 + arow) * AT_STRIDE
                                     + np * 32 + achk * 16;
                    ldsm_x4t(&vfh[np * 4], a);
                    ldsm_x4t(&vfl[np * 4], a + AT_TILE);
                }
                #pragma unroll
                for (int j = 0; j < 8; j++) {
                    const int ix = (j >> 1) * 4 + (j & 1) * 2;
                    mma_bf16(O[j], ph[kc], vfh[ix], vfh[ix + 1]);
                }
                #pragma unroll
                for (int j = 0; j < 8; j++) {
                    const int ix = (j >> 1) * 4 + (j & 1) * 2;
                    mma_bf16(O[j], pl[kc], vfh[ix], vfh[ix + 1]);
                }
                #pragma unroll
                for (int j = 0; j < 8; j++) {
                    const int ix = (j >> 1) * 4 + (j & 1) * 2;
                    mma_bf16(O[j], ph[kc], vfl[ix], vfl[ix + 1]);
                }
            }
        }
    }

    const float inv0 = 1.0f / l0;
    const float inv1 = 1.0f / l1;
    const int row0 = q0 + warp * 16 + g;
    const int row1 = row0 + 8;
    #pragma unroll
    for (int j = 0; j < 8; j++) {
        const int col = h * HD_ + 8 * j + 2 * t4;
        const size_t o0 = (size_t)(b * T_ + row0) * E_ + col;
        const size_t o1 = (size_t)(b * T_ + row1) * E_ + col;
        __nv_bfloat16 ha, la, hb, lb;
        split_bf16(O[j][0] * inv0, ha, la);
        split_bf16(O[j][1] * inv0, hb, lb);
        *(uint32_t*)&Yh[o0] = pack_bf162(ha, hb);
        *(uint32_t*)&Yl[o0] = pack_bf162(la, lb);
        split_bf16(O[j][2] * inv1, ha, la);
        split_bf16(O[j][3] * inv1, hb, lb);
        *(uint32_t*)&Yh[o1] = pack_bf162(ha, hb);
        *(uint32_t*)&Yl[o1] = pack_bf162(la, lb);
    }
}

// ---------------------------------------------------------------------------
extern "C" void kernel_launch(void* const* d_in, const int* in_sizes, int n_in,
                              void* d_out, int out_size)
{
    const float* x  = (const float*)d_in[0];
    const float* Wq = (const float*)d_in[2];
    const float* bq = (const float*)d_in[3];
    const float* Wk = (const float*)d_in[4];
    const float* bk = (const float*)d_in[5];
    const float* Wv = (const float*)d_in[6];
    const float* bv = (const float*)d_in[7];
    const float* Wp = (const float*)d_in[8];
    const float* bp = (const float*)d_in[9];
    float* out = (float*)d_out;

    __nv_bfloat16 *xh, *xl, *yh, *yl, *qh, *ql, *kh, *kl, *vh, *vl;
    __nv_bfloat16 *wqh, *wql, *wkh, *wkl, *wvh, *wvl, *wph, *wpl;
    cudaGetSymbolAddress((void**)&xh, g_xh);  cudaGetSymbolAddress((void**)&xl, g_xl);
    cudaGetSymbolAddress((void**)&yh, g_yh);  cudaGetSymbolAddress((void**)&yl, g_yl);
    cudaGetSymbolAddress((void**)&qh, g_qh);  cudaGetSymbolAddress((void**)&ql, g_ql);
    cudaGetSymbolAddress((void**)&kh, g_kh);  cudaGetSymbolAddress((void**)&kl, g_kl);
    cudaGetSymbolAddress((void**)&vh, g_vh);  cudaGetSymbolAddress((void**)&vl, g_vl);
    cudaGetSymbolAddress((void**)&wqh, g_wqh);  cudaGetSymbolAddress((void**)&wql, g_wql);
    cudaGetSymbolAddress((void**)&wkh, g_wkh);  cudaGetSymbolAddress((void**)&wkl, g_wkl);
    cudaGetSymbolAddress((void**)&wvh, g_wvh);  cudaGetSymbolAddress((void**)&wvl, g_wvl);
    cudaGetSymbolAddress((void**)&wph, g_wph);  cudaGetSymbolAddress((void**)&wpl, g_wpl);

    cudaFuncSetAttribute(gemm_bf16x3<true>,  cudaFuncAttributeMaxDynamicSharedMemorySize, GS_SMEM);
    cudaFuncSetAttribute(gemm_bf16x3<false>, cudaFuncAttributeMaxDynamicSharedMemorySize, GS_SMEM);
    cudaFuncSetAttribute(attn_tc, cudaFuncAttributeMaxDynamicSharedMemorySize, AT_SMEM);

    // Prep: split x, transpose+split weights
    split_kernel<<<(M_*E_/4 + 255)/256, 256>>>(x, xh, xl, M_*E_/4);
    dim3 tgrid(E_/32, E_/32), tblk(32, 8);
    tsplit_kernel<<<tgrid, tblk>>>(Wq, wqh, wql);
    tsplit_kernel<<<tgrid, tblk>>>(Wk, wkh, wkl);
    tsplit_kernel<<<tgrid, tblk>>>(Wv, wvh, wvl);
    tsplit_kernel<<<tgrid, tblk>>>(Wp, wph, wpl);

    dim3 gemm_grid(E_ / 128, M_ / 128);  // (8, 64)
    gemm_bf16x3<true><<<gemm_grid, 256, GS_SMEM>>>(xh, xl, wqh, wql, bq, nullptr, qh, ql);
    gemm_bf16x3<true><<<gemm_grid, 256, GS_SMEM>>>(xh, xl, wkh, wkl, bk, nullptr, kh, kl);
    gemm_bf16x3<true><<<gemm_grid, 256, GS_SMEM>>>(xh, xl, wvh, wvl, bv, nullptr, vh, vl);

    dim3 attn_grid(T_ / 128, H_, B_);    // (16, 16, 4)
    attn_tc<<<attn_grid, 256, AT_SMEM>>>(qh, ql, kh, kl, vh, vl, yh, yl);

    gemm_bf16x3<false><<<gemm_grid, 256, GS_SMEM>>>(yh, yl, wph, wpl, bp, out, nullptr, nullptr);
}

// round 10
// speedup vs baseline: 1.8070x; 1.1841x over previous
#include <cuda_runtime.h>
#include <cuda_bf16.h>
#include <stdint.h>
#include <math.h>

#define B_  4
#define T_  2048
#define E_  1024
#define H_  16
#define HD_ 64
#define M_  (B_*T_)   // 8192

// Scratch (device globals: allocation-free)
__device__ __nv_bfloat16 g_xh[M_*E_], g_xl[M_*E_];
__device__ __nv_bfloat16 g_yh[M_*E_], g_yl[M_*E_];
__device__ __nv_bfloat16 g_qh[M_*E_], g_ql[M_*E_];
__device__ __nv_bfloat16 g_kh[M_*E_], g_kl[M_*E_];
__device__ __nv_bfloat16 g_vh[M_*E_], g_vl[M_*E_];
__device__ __nv_bfloat16 g_wqh[E_*E_], g_wql[E_*E_];
__device__ __nv_bfloat16 g_wkh[E_*E_], g_wkl[E_*E_];
__device__ __nv_bfloat16 g_wvh[E_*E_], g_wvl[E_*E_];
__device__ __nv_bfloat16 g_wph[E_*E_], g_wpl[E_*E_];

// ---------------------------------------------------------------------------
// helpers
// ---------------------------------------------------------------------------
__device__ __forceinline__ uint32_t smem_u32(const void* p) {
    return (uint32_t)__cvta_generic_to_shared(p);
}
__device__ __forceinline__ void cp_async16(uint32_t dst, const void* src) {
    asm volatile("cp.async.cg.shared.global [%0], [%1], 16;\n" :: "r"(dst), "l"(src));
}
__device__ __forceinline__ void cp_commit() { asm volatile("cp.async.commit_group;\n"); }
__device__ __forceinline__ void cp_wait0() { asm volatile("cp.async.wait_group 0;\n"); }
__device__ __forceinline__ void cp_wait1() { asm volatile("cp.async.wait_group 1;\n"); }

__device__ __forceinline__ void mma_bf16(float c[4], const uint32_t a[4], uint32_t b0, uint32_t b1) {
    asm volatile(
        "mma.sync.aligned.m16n8k16.row.col.f32.bf16.bf16.f32 "
        "{%0,%1,%2,%3}, {%4,%5,%6,%7}, {%8,%9}, {%0,%1,%2,%3};\n"
        : "+f"(c[0]), "+f"(c[1]), "+f"(c[2]), "+f"(c[3])
        : "r"(a[0]), "r"(a[1]), "r"(a[2]), "r"(a[3]), "r"(b0), "r"(b1));
}
__device__ __forceinline__ void ldsm_x4(uint32_t r[4], uint32_t addr) {
    asm volatile("ldmatrix.sync.aligned.m8n8.x4.shared.b16 {%0,%1,%2,%3}, [%4];"
        : "=r"(r[0]), "=r"(r[1]), "=r"(r[2]), "=r"(r[3]) : "r"(addr));
}
__device__ __forceinline__ void ldsm_x4t(uint32_t r[4], uint32_t addr) {
    asm volatile("ldmatrix.sync.aligned.m8n8.x4.trans.shared.b16 {%0,%1,%2,%3}, [%4];"
        : "=r"(r[0]), "=r"(r[1]), "=r"(r[2]), "=r"(r[3]) : "r"(addr));
}
__device__ __forceinline__ void split_bf16(float v, __nv_bfloat16& h, __nv_bfloat16& l) {
    h = __float2bfloat16(v);
    l = __float2bfloat16(v - __bfloat162float(h));
}
__device__ __forceinline__ uint32_t pack_bf162(__nv_bfloat16 a, __nv_bfloat16 b) {
    __nv_bfloat162 p(a, b);
    return *(uint32_t*)&p;
}

// ---------------------------------------------------------------------------
// Prep: split fp32 -> bf16 hi/lo, same layout.
// ---------------------------------------------------------------------------
__global__ void split_kernel(const float* __restrict__ src,
                             __nv_bfloat16* __restrict__ hi,
                             __nv_bfloat16* __restrict__ lo, int n4)
{
    int i = blockIdx.x * blockDim.x + threadIdx.x;
    if (i >= n4) return;
    float4 v = ((const float4*)src)[i];
    __nv_bfloat16 h0,h1,h2,h3,l0,l1,l2,l3;
    split_bf16(v.x,h0,l0); split_bf16(v.y,h1,l1);
    split_bf16(v.z,h2,l2); split_bf16(v.w,h3,l3);
    ((__nv_bfloat162*)hi)[i*2+0] = __nv_bfloat162(h0,h1);
    ((__nv_bfloat162*)hi)[i*2+1] = __nv_bfloat162(h2,h3);
    ((__nv_bfloat162*)lo)[i*2+0] = __nv_bfloat162(l0,l1);
    ((__nv_bfloat162*)lo)[i*2+1] = __nv_bfloat162(l2,l3);
}

// ---------------------------------------------------------------------------
// Prep: transpose + split. W[K][N] fp32 -> Th/Tl[N][K] bf16.
// ---------------------------------------------------------------------------
__global__ void tsplit_kernel(const float* __restrict__ W,
                              __nv_bfloat16* __restrict__ Th,
                              __nv_bfloat16* __restrict__ Tl)
{
    __shared__ float t[32][33];
    const int n0 = blockIdx.x * 32, k0 = blockIdx.y * 32;
    const int tx = threadIdx.x, ty = threadIdx.y;   // (32, 8)
    #pragma unroll
    for (int i = 0; i < 4; i++)
        t[ty + 8*i][tx] = W[(size_t)(k0 + ty + 8*i) * E_ + n0 + tx];
    __syncthreads();
    #pragma unroll
    for (int i = 0; i < 4; i++) {
        const int row = ty + 8*i;
        const float v = t[tx][row];
        __nv_bfloat16 h, l;
        split_bf16(v, h, l);
        Th[(size_t)(n0 + row) * E_ + k0 + tx] = h;
        Tl[(size_t)(n0 + row) * E_ + k0 + tx] = l;
    }
}

// ---------------------------------------------------------------------------
// bf16x3 tensor-core GEMM, 3-stage cp.async, single barrier per iteration,
// XOR-swizzled smem (64B rows, no padding) -> 98304 B -> 2 CTAs/SM.
// Swizzle: addr(row, chunk) = row*64 + ((chunk ^ ((row>>1)&3))*16).
// REORDER=true:  write split bf16 hi/lo in [B,H,T,hd] layout (Ch, Cl).
// REORDER=false: write fp32 [M][N] (C).
// ---------------------------------------------------------------------------
#define GS_TILE   8192                 // 128 rows x 64 B
#define GS_STAGE  (4*GS_TILE)          // 32768 B
#define GS_SMEM   (3*GS_STAGE)         // 98304 B

template<bool REORDER>
__global__ void __launch_bounds__(256, 2) gemm_bf16x3(
    const __nv_bfloat16* __restrict__ Ah, const __nv_bfloat16* __restrict__ Al,
    const __nv_bfloat16* __restrict__ Th, const __nv_bfloat16* __restrict__ Tl,
    const float* __restrict__ bias, float* __restrict__ C,
    __nv_bfloat16* __restrict__ Ch, __nv_bfloat16* __restrict__ Cl)
{
    extern __shared__ char sm[];
    const uint32_t smb = smem_u32(sm);

    const int tid  = threadIdx.x;
    const int warp = tid >> 5;
    const int lane = tid & 31;
    const int group = lane >> 2;
    const int tidg  = lane & 3;

    const int bn = blockIdx.x, bm = blockIdx.y;
    const int m0 = bm * 128, n0 = bn * 128;
    const int warp_m = warp & 1;
    const int warp_n = warp >> 1;

    const int lrow = (lane & 7) + ((lane >> 3) & 1) * 8;
    const int lchk = (lane >> 4) & 1;            // base chunk (0/1)
    const int sel  = (lrow >> 1) & 3;            // per-lane swizzle selector

    auto load_stage = [&](int s, int c) {
        const int kb = c * 32;
        const uint32_t st = smb + s * GS_STAGE;
        #pragma unroll
        for (int i = 0; i < 2; i++) {
            const int ch = tid + i * 256;
            const int row = ch >> 2, q = ch & 3;
            const uint32_t d = st + row * 64 + (((q ^ ((row >> 1) & 3))) << 4);
            const size_t ga = (size_t)(m0 + row) * E_ + kb + q * 8;
            const size_t gb = (size_t)(n0 + row) * E_ + kb + q * 8;
            cp_async16(d,               Ah + ga);
            cp_async16(d + GS_TILE,     Al + ga);
            cp_async16(d + 2*GS_TILE,   Th + gb);
            cp_async16(d + 3*GS_TILE,   Tl + gb);
        }
        cp_commit();
    };

    float acc[4][4][4];
    #pragma unroll
    for (int i = 0; i < 4; i++)
        #pragma unroll
        for (int j = 0; j < 4; j++)
            #pragma unroll
            for (int r = 0; r < 4; r++) acc[i][j][r] = 0.f;

    const int NC = E_ / 32;
    load_stage(0, 0);
    load_stage(1, 1);

    for (int c = 0; c < NC; c++) {
        const int s = c % 3;
        if (c + 1 < NC) cp_wait1(); else cp_wait0();
        __syncthreads();
        if (c + 2 < NC) load_stage((c + 2) % 3, c + 2);

        const uint32_t st = smb + s * GS_STAGE;
        const uint32_t abase = st + (warp_m * 64 + lrow) * 64;
        const uint32_t bbase = st + 2*GS_TILE + (warp_n * 32 + lrow) * 64;

        #pragma unroll
        for (int h2 = 0; h2 < 2; h2++) {
            // swizzled 16B-chunk offset for this lane at this k-half
            const uint32_t co = (uint32_t)(((lchk + 2 * h2) ^ sel) << 4);
            uint32_t ah[4][4], al[4][4], bh[2][4], bl[2][4];
            #pragma unroll
            for (int i = 0; i < 4; i++) {
                ldsm_x4(ah[i], abase + i * 16 * 64 + co);
                ldsm_x4(al[i], abase + GS_TILE + i * 16 * 64 + co);
            }
            #pragma unroll
            for (int g = 0; g < 2; g++) {
                ldsm_x4(bh[g], bbase + g * 16 * 64 + co);
                ldsm_x4(bl[g], bbase + GS_TILE + g * 16 * 64 + co);
            }
            #pragma unroll
            for (int i = 0; i < 4; i++)
                #pragma unroll
                for (int j = 0; j < 4; j++)
                    mma_bf16(acc[i][j], ah[i], bh[j>>1][j&1], bh[j>>1][(j&1)+2]);
            #pragma unroll
            for (int i = 0; i < 4; i++)
                #pragma unroll
                for (int j = 0; j < 4; j++)
                    mma_bf16(acc[i][j], ah[i], bl[j>>1][j&1], bl[j>>1][(j&1)+2]);
            #pragma unroll
            for (int i = 0; i < 4; i++)
                #pragma unroll
                for (int j = 0; j < 4; j++)
                    mma_bf16(acc[i][j], al[i], bh[j>>1][j&1], bh[j>>1][(j&1)+2]);
        }
    }

    #pragma unroll
    for (int i = 0; i < 4; i++) {
        const int rmb = m0 + warp_m * 64 + i * 16 + group;
        #pragma unroll
        for (int j = 0; j < 4; j++) {
            const int cb = n0 + warp_n * 32 + j * 8 + tidg * 2;
            const float bx = bias[cb], by = bias[cb + 1];
            #pragma unroll
            for (int half = 0; half < 2; half++) {
                const int m = rmb + half * 8;
                const float vx = acc[i][j][half * 2 + 0] + bx;
                const float vy = acc[i][j][half * 2 + 1] + by;
                if (REORDER) {
                    const int b = m >> 11;
                    const int t = m & (T_ - 1);
                    const int h = cb >> 6;
                    const int d = cb & (HD_ - 1);
                    const size_t o = (((size_t)(b * H_ + h) * T_) + t) * HD_ + d;
                    __nv_bfloat16 hx, lx, hy, ly;
                    split_bf16(vx, hx, lx);
                    split_bf16(vy, hy, ly);
                    *(uint32_t*)&Ch[o] = pack_bf162(hx, hy);
                    *(uint32_t*)&Cl[o] = pack_bf162(lx, ly);
                } else {
                    float2 v; v.x = vx; v.y = vy;
                    *(float2*)&C[(size_t)m * E_ + cb] = v;
                }
            }
        }
    }
}

// ---------------------------------------------------------------------------
// Tensor-core flash attention (causal), bf16x3, online softmax (R9 version).
// 3-stage cp.async, single barrier per KV tile. Heavy blocks first.
// ---------------------------------------------------------------------------
#define AT_STRIDE 144
#define AT_TILE   (64*AT_STRIDE)     // 9216
#define AT_STAGE  (4*AT_TILE)        // 36864
#define AT_SMEM   (3*AT_STAGE)       // 110592 -> 2 CTAs/SM

__global__ void __launch_bounds__(256) attn_tc(
    const __nv_bfloat16* __restrict__ Qh, const __nv_bfloat16* __restrict__ Ql,
    const __nv_bfloat16* __restrict__ Kh, const __nv_bfloat16* __restrict__ Kl,
    const __nv_bfloat16* __restrict__ Vh, const __nv_bfloat16* __restrict__ Vl,
    __nv_bfloat16* __restrict__ Yh, __nv_bfloat16* __restrict__ Yl)
{
    extern __shared__ char sm[];
    const uint32_t smb = smem_u32(sm);

    const int tid  = threadIdx.x;
    const int warp = tid >> 5;
    const int lane = tid & 31;
    const int g    = lane >> 2;
    const int t4   = lane & 3;

    const int qb = (int)gridDim.x - 1 - (int)blockIdx.x;
    const int h  = blockIdx.y;
    const int b  = blockIdx.z;
    const int q0 = qb * 128;

    const size_t base = (size_t)(b * H_ + h) * T_ * HD_;
    const __nv_bfloat16* qh = Qh + base + (size_t)q0 * HD_;
    const __nv_bfloat16* ql = Ql + base + (size_t)q0 * HD_;
    const __nv_bfloat16* kh = Kh + base;
    const __nv_bfloat16* kl = Kl + base;
    const __nv_bfloat16* vh = Vh + base;
    const __nv_bfloat16* vl = Vl + base;

    const int arow = (lane & 7) + ((lane >> 3) & 1) * 8;
    const int achk = (lane >> 4) & 1;
    const int brow = (lane & 7) + ((lane >> 4) & 1) * 8;
    const int bchk = (lane >> 3) & 1;

    #pragma unroll
    for (int i = 0; i < 4; i++) {
        const int ch = tid + i * 256;
        const int row = ch >> 3, q = ch & 7;
        const uint32_t d = smb + (row >> 6) * AT_TILE + (row & 63) * AT_STRIDE + q * 16;
        cp_async16(d,               qh + (size_t)row * HD_ + q * 8);
        cp_async16(d + 2*AT_TILE,   ql + (size_t)row * HD_ + q * 8);
    }
    cp_commit(); cp_wait0();
    __syncthreads();

    uint32_t qfh[4][4], qfl[4][4];
    {
        const int wr = warp * 16;
        const uint32_t qbse = smb + (wr >> 6) * AT_TILE + (wr & 63) * AT_STRIDE
                            + arow * AT_STRIDE + achk * 16;
        #pragma unroll
        for (int kc = 0; kc < 4; kc++) {
            ldsm_x4(qfh[kc], qbse + kc * 32);
            ldsm_x4(qfl[kc], qbse + 2*AT_TILE + kc * 32);
        }
    }
    __syncthreads();

    auto load_stage = [&](int s, int kt) {
        const int kv0 = kt * 64;
        const uint32_t st = smb + s * AT_STAGE;
        #pragma unroll
        for (int i = 0; i < 2; i++) {
            const int ch = tid + i * 256;
            const int row = ch >> 3, q = ch & 7;
            const uint32_t d = st + row * AT_STRIDE + q * 16;
            const size_t go = (size_t)(kv0 + row) * HD_ + q * 8;
            cp_async16(d,               kh + go);
            cp_async16(d + AT_TILE,     kl + go);
            cp_async16(d + 2*AT_TILE,   vh + go);
            cp_async16(d + 3*AT_TILE,   vl + go);
        }
        cp_commit();
    };

    float O[8][4];
    #pragma unroll
    for (int j = 0; j < 8; j++)
        #pragma unroll
        for (int r = 0; r < 4; r++) O[j][r] = 0.f;
    float m0 = -1e30f, m1 = -1e30f, l0 = 0.f, l1 = 0.f;

    const int nt = 2 * (qb + 1);
    const int R  = q0 + warp * 16;

    load_stage(0, 0);
    if (nt > 1) load_stage(1, 1);

    for (int kt = 0; kt < nt; kt++) {
        const int s = kt % 3;
        const int kv0 = kt * 64;
        if (kt + 1 < nt) cp_wait1(); else cp_wait0();
        __syncthreads();
        if (kt + 2 < nt) load_stage((kt + 2) % 3, kt + 2);

        if (kv0 <= R + 15) {
            const uint32_t st = smb + s * AT_STAGE;

            float S[8][4];
            #pragma unroll
            for (int j = 0; j < 8; j++)
                #pragma unroll
                for (int r = 0; r < 4; r++) S[j][r] = 0.f;

            #pragma unroll
            for (int kc = 0; kc < 4; kc++) {
                uint32_t kfh[16], kfl[16];
                #pragma unroll
                for (int np = 0; np < 4; np++) {
                    const uint32_t a = st + (np * 16 + brow) * AT_STRIDE + bchk * 16 + kc * 32;
                    ldsm_x4(&kfh[np * 4], a);
                    ldsm_x4(&kfl[np * 4], a + AT_TILE);
                }
                #pragma unroll
                for (int j = 0; j < 8; j++) {
                    const int ix = (j >> 1) * 4 + (j & 1) * 2;
                    mma_bf16(S[j], qfh[kc], kfh[ix], kfh[ix + 1]);
                }
                #pragma unroll
                for (int j = 0; j < 8; j++) {
                    const int ix = (j >> 1) * 4 + (j & 1) * 2;
                    mma_bf16(S[j], qfh[kc], kfl[ix], kfl[ix + 1]);
                }
                #pragma unroll
                for (int j = 0; j < 8; j++) {
                    const int ix = (j >> 1) * 4 + (j & 1) * 2;
                    mma_bf16(S[j], qfl[kc], kfh[ix], kfh[ix + 1]);
                }
            }

            const int row0 = R + g, row1 = R + g + 8;
            const bool need_mask = (kv0 + 63 > R);
            #pragma unroll
            for (int j = 0; j < 8; j++) {
                #pragma unroll
                for (int r = 0; r < 4; r++) S[j][r] *= 0.125f;
                if (need_mask) {
                    const int c0 = kv0 + 8 * j + 2 * t4;
                    if (c0     > row0) S[j][0] = -1e30f;
                    if (c0 + 1 > row0) S[j][1] = -1e30f;
                    if (c0     > row1) S[j][2] = -1e30f;
                    if (c0 + 1 > row1) S[j][3] = -1e30f;
                }
            }

            float mx0 = -1e30f, mx1 = -1e30f;
            #pragma unroll
            for (int j = 0; j < 8; j++) {
                mx0 = fmaxf(mx0, fmaxf(S[j][0], S[j][1]));
                mx1 = fmaxf(mx1, fmaxf(S[j][2], S[j][3]));
            }
            mx0 = fmaxf(mx0, __shfl_xor_sync(0xffffffffu, mx0, 1));
            mx0 = fmaxf(mx0, __shfl_xor_sync(0xffffffffu, mx0, 2));
            mx1 = fmaxf(mx1, __shfl_xor_sync(0xffffffffu, mx1, 1));
            mx1 = fmaxf(mx1, __shfl_xor_sync(0xffffffffu, mx1, 2));

            const float nm0 = fmaxf(m0, mx0);
            const float nm1 = fmaxf(m1, mx1);
            const float cr0 = __expf(m0 - nm0);
            const float cr1 = __expf(m1 - nm1);

            float s0 = 0.f, s1 = 0.f;
            #pragma unroll
            for (int j = 0; j < 8; j++) {
                S[j][0] = __expf(S[j][0] - nm0);
                S[j][1] = __expf(S[j][1] - nm0);
                S[j][2] = __expf(S[j][2] - nm1);
                S[j][3] = __expf(S[j][3] - nm1);
                s0 += S[j][0] + S[j][1];
                s1 += S[j][2] + S[j][3];
            }
            s0 += __shfl_xor_sync(0xffffffffu, s0, 1);
            s0 += __shfl_xor_sync(0xffffffffu, s0, 2);
            s1 += __shfl_xor_sync(0xffffffffu, s1, 1);
            s1 += __shfl_xor_sync(0xffffffffu, s1, 2);

            l0 = l0 * cr0 + s0;  m0 = nm0;
            l1 = l1 * cr1 + s1;  m1 = nm1;

            #pragma unroll
            for (int j = 0; j < 8; j++) {
                O[j][0] *= cr0;  O[j][1] *= cr0;
                O[j][2] *= cr1;  O[j][3] *= cr1;
            }

            uint32_t ph[4][4], pl[4][4];
            #pragma unroll
            for (int kc = 0; kc < 4; kc++) {
                __nv_bfloat16 ha, la, hb, lb;
                split_bf16(S[2*kc][0], ha, la);  split_bf16(S[2*kc][1], hb, lb);
                ph[kc][0] = pack_bf162(ha, hb);  pl[kc][0] = pack_bf162(la, lb);
                split_bf16(S[2*kc][2], ha, la);  split_bf16(S[2*kc][3], hb, lb);
                ph[kc][1] = pack_bf162(ha, hb);  pl[kc][1] = pack_bf162(la, lb);
                split_bf16(S[2*kc+1][0], ha, la); split_bf16(S[2*kc+1][1], hb, lb);
                ph[kc][2] = pack_bf162(ha, hb);  pl[kc][2] = pack_bf162(la, lb);
                split_bf16(S[2*kc+1][2], ha, la); split_bf16(S[2*kc+1][3], hb, lb);
                ph[kc][3] = pack_bf162(ha, hb);  pl[kc][3] = pack_bf162(la, lb);
            }

            #pragma unroll
            for (int kc = 0; kc < 4; kc++) {
                uint32_t vfh[16], vfl[16];
                #pragma unroll
                for (int np = 0; np < 4; np++) {
                    const uint32_t a = st + 2*AT_TILE + (kc * 16 + arow) * AT_STRIDE
                                     + np * 32 + achk * 16;
                    ldsm_x4t(&vfh[np * 4], a);
                    ldsm_x4t(&vfl[np * 4], a + AT_TILE);
                }
                #pragma unroll
                for (int j = 0; j < 8; j++) {
                    const int ix = (j >> 1) * 4 + (j & 1) * 2;
                    mma_bf16(O[j], ph[kc], vfh[ix], vfh[ix + 1]);
                }
                #pragma unroll
                for (int j = 0; j < 8; j++) {
                    const int ix = (j >> 1) * 4 + (j & 1) * 2;
                    mma_bf16(O[j], pl[kc], vfh[ix], vfh[ix + 1]);
                }
                #pragma unroll
                for (int j = 0; j < 8; j++) {
                    const int ix = (j >> 1) * 4 + (j & 1) * 2;
                    mma_bf16(O[j], ph[kc], vfl[ix], vfl[ix + 1]);
                }
            }
        }
    }

    const float inv0 = 1.0f / l0;
    const float inv1 = 1.0f / l1;
    const int row0 = q0 + warp * 16 + g;
    const int row1 = row0 + 8;
    #pragma unroll
    for (int j = 0; j < 8; j++) {
        const int col = h * HD_ + 8 * j + 2 * t4;
        const size_t o0 = (size_t)(b * T_ + row0) * E_ + col;
        const size_t o1 = (size_t)(b * T_ + row1) * E_ + col;
        __nv_bfloat16 ha, la, hb, lb;
        split_bf16(O[j][0] * inv0, ha, la);
        split_bf16(O[j][1] * inv0, hb, lb);
        *(uint32_t*)&Yh[o0] = pack_bf162(ha, hb);
        *(uint32_t*)&Yl[o0] = pack_bf162(la, lb);
        split_bf16(O[j][2] * inv1, ha, la);
        split_bf16(O[j][3] * inv1, hb, lb);
        *(uint32_t*)&Yh[o1] = pack_bf162(ha, hb);
        *(uint32_t*)&Yl[o1] = pack_bf162(la, lb);
    }
}

// ---------------------------------------------------------------------------
extern "C" void kernel_launch(void* const* d_in, const int* in_sizes, int n_in,
                              void* d_out, int out_size)
{
    const float* x  = (const float*)d_in[0];
    const float* Wq = (const float*)d_in[2];
    const float* bq = (const float*)d_in[3];
    const float* Wk = (const float*)d_in[4];
    const float* bk = (const float*)d_in[5];
    const float* Wv = (const float*)d_in[6];
    const float* bv = (const float*)d_in[7];
    const float* Wp = (const float*)d_in[8];
    const float* bp = (const float*)d_in[9];
    float* out = (float*)d_out;

    __nv_bfloat16 *xh, *xl, *yh, *yl, *qh, *ql, *kh, *kl, *vh, *vl;
    __nv_bfloat16 *wqh, *wql, *wkh, *wkl, *wvh, *wvl, *wph, *wpl;
    cudaGetSymbolAddress((void**)&xh, g_xh);  cudaGetSymbolAddress((void**)&xl, g_xl);
    cudaGetSymbolAddress((void**)&yh, g_yh);  cudaGetSymbolAddress((void**)&yl, g_yl);
    cudaGetSymbolAddress((void**)&qh, g_qh);  cudaGetSymbolAddress((void**)&ql, g_ql);
    cudaGetSymbolAddress((void**)&kh, g_kh);  cudaGetSymbolAddress((void**)&kl, g_kl);
    cudaGetSymbolAddress((void**)&vh, g_vh);  cudaGetSymbolAddress((void**)&vl, g_vl);
    cudaGetSymbolAddress((void**)&wqh, g_wqh);  cudaGetSymbolAddress((void**)&wql, g_wql);
    cudaGetSymbolAddress((void**)&wkh, g_wkh);  cudaGetSymbolAddress((void**)&wkl, g_wkl);
    cudaGetSymbolAddress((void**)&wvh, g_wvh);  cudaGetSymbolAddress((void**)&wvl, g_wvl);
    cudaGetSymbolAddress((void**)&wph, g_wph);  cudaGetSymbolAddress((void**)&wpl, g_wpl);

    cudaFuncSetAttribute(gemm_bf16x3<true>,  cudaFuncAttributeMaxDynamicSharedMemorySize, GS_SMEM);
    cudaFuncSetAttribute(gemm_bf16x3<false>, cudaFuncAttributeMaxDynamicSharedMemorySize, GS_SMEM);
    cudaFuncSetAttribute(attn_tc, cudaFuncAttributeMaxDynamicSharedMemorySize, AT_SMEM);

    // Prep: split x, transpose+split weights
    split_kernel<<<(M_*E_/4 + 255)/256, 256>>>(x, xh, xl, M_*E_/4);
    dim3 tgrid(E_/32, E_/32), tblk(32, 8);
    tsplit_kernel<<<tgrid, tblk>>>(Wq, wqh, wql);
    tsplit_kernel<<<tgrid, tblk>>>(Wk, wkh, wkl);
    tsplit_kernel<<<tgrid, tblk>>>(Wv, wvh, wvl);
    tsplit_kernel<<<tgrid, tblk>>>(Wp, wph, wpl);

    dim3 gemm_grid(E_ / 128, M_ / 128);  // (8, 64)
    gemm_bf16x3<true><<<gemm_grid, 256, GS_SMEM>>>(xh, xl, wqh, wql, bq, nullptr, qh, ql);
    gemm_bf16x3<true><<<gemm_grid, 256, GS_SMEM>>>(xh, xl, wkh, wkl, bk, nullptr, kh, kl);
    gemm_bf16x3<true><<<gemm_grid, 256, GS_SMEM>>>(xh, xl, wvh, wvl, bv, nullptr, vh, vl);

    dim3 attn_grid(T_ / 128, H_, B_);    // (16, 16, 4)
    attn_tc<<<attn_grid, 256, AT_SMEM>>>(qh, ql, kh, kl, vh, vl, yh, yl);

    gemm_bf16x3<false><<<gemm_grid, 256, GS_SMEM>>>(yh, yl, wph, wpl, bp, out, nullptr, nullptr);
}

// round 11
// speedup vs baseline: 1.9492x; 1.0787x over previous
#include <cuda_runtime.h>
#include <cuda_bf16.h>
#include <stdint.h>
#include <math.h>

#define B_  4
#define T_  2048
#define E_  1024
#define H_  16
#define HD_ 64
#define M_  (B_*T_)   // 8192

// Scratch (device globals: allocation-free)
__device__ __nv_bfloat16 g_xh[M_*E_], g_xl[M_*E_];
__device__ __nv_bfloat16 g_yh[M_*E_], g_yl[M_*E_];
__device__ __nv_bfloat16 g_qh[M_*E_], g_ql[M_*E_];
__device__ __nv_bfloat16 g_kh[M_*E_], g_kl[M_*E_];
__device__ __nv_bfloat16 g_vh[M_*E_], g_vl[M_*E_];
__device__ __nv_bfloat16 g_wqh[E_*E_], g_wql[E_*E_];
__device__ __nv_bfloat16 g_wkh[E_*E_], g_wkl[E_*E_];
__device__ __nv_bfloat16 g_wvh[E_*E_], g_wvl[E_*E_];
__device__ __nv_bfloat16 g_wph[E_*E_], g_wpl[E_*E_];

// ---------------------------------------------------------------------------
// helpers
// ---------------------------------------------------------------------------
__device__ __forceinline__ uint32_t smem_u32(const void* p) {
    return (uint32_t)__cvta_generic_to_shared(p);
}
__device__ __forceinline__ void cp_async16(uint32_t dst, const void* src) {
    asm volatile("cp.async.cg.shared.global [%0], [%1], 16;\n" :: "r"(dst), "l"(src));
}
__device__ __forceinline__ void cp_commit() { asm volatile("cp.async.commit_group;\n"); }
__device__ __forceinline__ void cp_wait0() { asm volatile("cp.async.wait_group 0;\n"); }
__device__ __forceinline__ void cp_wait1() { asm volatile("cp.async.wait_group 1;\n"); }

__device__ __forceinline__ void mma_bf16(float c[4], const uint32_t a[4], uint32_t b0, uint32_t b1) {
    asm volatile(
        "mma.sync.aligned.m16n8k16.row.col.f32.bf16.bf16.f32 "
        "{%0,%1,%2,%3}, {%4,%5,%6,%7}, {%8,%9}, {%0,%1,%2,%3};\n"
        : "+f"(c[0]), "+f"(c[1]), "+f"(c[2]), "+f"(c[3])
        : "r"(a[0]), "r"(a[1]), "r"(a[2]), "r"(a[3]), "r"(b0), "r"(b1));
}
__device__ __forceinline__ void ldsm_x4(uint32_t r[4], uint32_t addr) {
    asm volatile("ldmatrix.sync.aligned.m8n8.x4.shared.b16 {%0,%1,%2,%3}, [%4];"
        : "=r"(r[0]), "=r"(r[1]), "=r"(r[2]), "=r"(r[3]) : "r"(addr));
}
__device__ __forceinline__ void ldsm_x4t(uint32_t r[4], uint32_t addr) {
    asm volatile("ldmatrix.sync.aligned.m8n8.x4.trans.shared.b16 {%0,%1,%2,%3}, [%4];"
        : "=r"(r[0]), "=r"(r[1]), "=r"(r[2]), "=r"(r[3]) : "r"(addr));
}
__device__ __forceinline__ void split_bf16(float v, __nv_bfloat16& h, __nv_bfloat16& l) {
    h = __float2bfloat16(v);
    l = __float2bfloat16(v - __bfloat162float(h));
}
__device__ __forceinline__ uint32_t pack_bf162(__nv_bfloat16 a, __nv_bfloat16 b) {
    __nv_bfloat162 p(a, b);
    return *(uint32_t*)&p;
}

// ---------------------------------------------------------------------------
// Prep: split fp32 -> bf16 hi/lo, same layout.
// ---------------------------------------------------------------------------
__global__ void split_kernel(const float* __restrict__ src,
                             __nv_bfloat16* __restrict__ hi,
                             __nv_bfloat16* __restrict__ lo, int n4)
{
    int i = blockIdx.x * blockDim.x + threadIdx.x;
    if (i >= n4) return;
    float4 v = ((const float4*)src)[i];
    __nv_bfloat16 h0,h1,h2,h3,l0,l1,l2,l3;
    split_bf16(v.x,h0,l0); split_bf16(v.y,h1,l1);
    split_bf16(v.z,h2,l2); split_bf16(v.w,h3,l3);
    ((__nv_bfloat162*)hi)[i*2+0] = __nv_bfloat162(h0,h1);
    ((__nv_bfloat162*)hi)[i*2+1] = __nv_bfloat162(h2,h3);
    ((__nv_bfloat162*)lo)[i*2+0] = __nv_bfloat162(l0,l1);
    ((__nv_bfloat162*)lo)[i*2+1] = __nv_bfloat162(l2,l3);
}

// ---------------------------------------------------------------------------
// Prep: transpose + split. W[K][N] fp32 -> Th/Tl[N][K] bf16.
// ---------------------------------------------------------------------------
__global__ void tsplit_kernel(const float* __restrict__ W,
                              __nv_bfloat16* __restrict__ Th,
                              __nv_bfloat16* __restrict__ Tl)
{
    __shared__ float t[32][33];
    const int n0 = blockIdx.x * 32, k0 = blockIdx.y * 32;
    const int tx = threadIdx.x, ty = threadIdx.y;   // (32, 8)
    #pragma unroll
    for (int i = 0; i < 4; i++)
        t[ty + 8*i][tx] = W[(size_t)(k0 + ty + 8*i) * E_ + n0 + tx];
    __syncthreads();
    #pragma unroll
    for (int i = 0; i < 4; i++) {
        const int row = ty + 8*i;
        const float v = t[tx][row];
        __nv_bfloat16 h, l;
        split_bf16(v, h, l);
        Th[(size_t)(n0 + row) * E_ + k0 + tx] = h;
        Tl[(size_t)(n0 + row) * E_ + k0 + tx] = l;
    }
}

// ---------------------------------------------------------------------------
// bf16x3 tensor-core GEMM body, 3-stage cp.async, single barrier/iter,
// XOR-swizzled smem (64B rows) -> 98304 B -> 2 CTAs/SM.
// ---------------------------------------------------------------------------
#define GS_TILE   8192
#define GS_STAGE  (4*GS_TILE)          // 32768 B
#define GS_SMEM   (3*GS_STAGE)         // 98304 B

template<bool REORDER>
__device__ __forceinline__ void gemm_body(
    const __nv_bfloat16* __restrict__ Ah, const __nv_bfloat16* __restrict__ Al,
    const __nv_bfloat16* __restrict__ Th, const __nv_bfloat16* __restrict__ Tl,
    const float* __restrict__ bias, float* __restrict__ C,
    __nv_bfloat16* __restrict__ Ch, __nv_bfloat16* __restrict__ Cl)
{
    extern __shared__ char sm[];
    const uint32_t smb = smem_u32(sm);

    const int tid  = threadIdx.x;
    const int warp = tid >> 5;
    const int lane = tid & 31;
    const int group = lane >> 2;
    const int tidg  = lane & 3;

    const int bn = blockIdx.x, bm = blockIdx.y;
    const int m0 = bm * 128, n0 = bn * 128;
    const int warp_m = warp & 1;
    const int warp_n = warp >> 1;

    const int lrow = (lane & 7) + ((lane >> 3) & 1) * 8;
    const int lchk = (lane >> 4) & 1;
    const int sel  = (lrow >> 1) & 3;

    auto load_stage = [&](int s, int c) {
        const int kb = c * 32;
        const uint32_t st = smb + s * GS_STAGE;
        #pragma unroll
        for (int i = 0; i < 2; i++) {
            const int ch = tid + i * 256;
            const int row = ch >> 2, q = ch & 3;
            const uint32_t d = st + row * 64 + (((q ^ ((row >> 1) & 3))) << 4);
            const size_t ga = (size_t)(m0 + row) * E_ + kb + q * 8;
            const size_t gb = (size_t)(n0 + row) * E_ + kb + q * 8;
            cp_async16(d,               Ah + ga);
            cp_async16(d + GS_TILE,     Al + ga);
            cp_async16(d + 2*GS_TILE,   Th + gb);
            cp_async16(d + 3*GS_TILE,   Tl + gb);
        }
        cp_commit();
    };

    float acc[4][4][4];
    #pragma unroll
    for (int i = 0; i < 4; i++)
        #pragma unroll
        for (int j = 0; j < 4; j++)
            #pragma unroll
            for (int r = 0; r < 4; r++) acc[i][j][r] = 0.f;

    const int NC = E_ / 32;
    load_stage(0, 0);
    load_stage(1, 1);

    for (int c = 0; c < NC; c++) {
        const int s = c % 3;
        if (c + 1 < NC) cp_wait1(); else cp_wait0();
        __syncthreads();
        if (c + 2 < NC) load_stage((c + 2) % 3, c + 2);

        const uint32_t st = smb + s * GS_STAGE;
        const uint32_t abase = st + (warp_m * 64 + lrow) * 64;
        const uint32_t bbase = st + 2*GS_TILE + (warp_n * 32 + lrow) * 64;

        #pragma unroll
        for (int h2 = 0; h2 < 2; h2++) {
            const uint32_t co = (uint32_t)(((lchk + 2 * h2) ^ sel) << 4);
            uint32_t ah[4][4], al[4][4], bh[2][4], bl[2][4];
            #pragma unroll
            for (int i = 0; i < 4; i++) {
                ldsm_x4(ah[i], abase + i * 16 * 64 + co);
                ldsm_x4(al[i], abase + GS_TILE + i * 16 * 64 + co);
            }
            #pragma unroll
            for (int g = 0; g < 2; g++) {
                ldsm_x4(bh[g], bbase + g * 16 * 64 + co);
                ldsm_x4(bl[g], bbase + GS_TILE + g * 16 * 64 + co);
            }
            #pragma unroll
            for (int i = 0; i < 4; i++)
                #pragma unroll
                for (int j = 0; j < 4; j++)
                    mma_bf16(acc[i][j], ah[i], bh[j>>1][j&1], bh[j>>1][(j&1)+2]);
            #pragma unroll
            for (int i = 0; i < 4; i++)
                #pragma unroll
                for (int j = 0; j < 4; j++)
                    mma_bf16(acc[i][j], ah[i], bl[j>>1][j&1], bl[j>>1][(j&1)+2]);
            #pragma unroll
            for (int i = 0; i < 4; i++)
                #pragma unroll
                for (int j = 0; j < 4; j++)
                    mma_bf16(acc[i][j], al[i], bh[j>>1][j&1], bh[j>>1][(j&1)+2]);
        }
    }

    #pragma unroll
    for (int i = 0; i < 4; i++) {
        const int rmb = m0 + warp_m * 64 + i * 16 + group;
        #pragma unroll
        for (int j = 0; j < 4; j++) {
            const int cb = n0 + warp_n * 32 + j * 8 + tidg * 2;
            const float bx = bias[cb], by = bias[cb + 1];
            #pragma unroll
            for (int half = 0; half < 2; half++) {
                const int m = rmb + half * 8;
                const float vx = acc[i][j][half * 2 + 0] + bx;
                const float vy = acc[i][j][half * 2 + 1] + by;
                if (REORDER) {
                    const int b = m >> 11;
                    const int t = m & (T_ - 1);
                    const int h = cb >> 6;
                    const int d = cb & (HD_ - 1);
                    const size_t o = (((size_t)(b * H_ + h) * T_) + t) * HD_ + d;
                    __nv_bfloat16 hx, lx, hy, ly;
                    split_bf16(vx, hx, lx);
                    split_bf16(vy, hy, ly);
                    *(uint32_t*)&Ch[o] = pack_bf162(hx, hy);
                    *(uint32_t*)&Cl[o] = pack_bf162(lx, ly);
                } else {
                    float2 v; v.x = vx; v.y = vy;
                    *(float2*)&C[(size_t)m * E_ + cb] = v;
                }
            }
        }
    }
}

// Fused QKV: blockIdx.z selects weight/bias/output.
__global__ void __launch_bounds__(256, 2) gemm_qkv(
    const __nv_bfloat16* __restrict__ xh, const __nv_bfloat16* __restrict__ xl,
    const __nv_bfloat16* __restrict__ wqh, const __nv_bfloat16* __restrict__ wql,
    const __nv_bfloat16* __restrict__ wkh, const __nv_bfloat16* __restrict__ wkl,
    const __nv_bfloat16* __restrict__ wvh, const __nv_bfloat16* __restrict__ wvl,
    const float* __restrict__ bq, const float* __restrict__ bk, const float* __restrict__ bv,
    __nv_bfloat16* __restrict__ qh, __nv_bfloat16* __restrict__ ql,
    __nv_bfloat16* __restrict__ kh, __nv_bfloat16* __restrict__ kl,
    __nv_bfloat16* __restrict__ vh, __nv_bfloat16* __restrict__ vl)
{
    const int z = blockIdx.z;
    const __nv_bfloat16* Th = (z == 0) ? wqh : (z == 1) ? wkh : wvh;
    const __nv_bfloat16* Tl = (z == 0) ? wql : (z == 1) ? wkl : wvl;
    const float* bias       = (z == 0) ? bq  : (z == 1) ? bk  : bv;
    __nv_bfloat16* Ch       = (z == 0) ? qh  : (z == 1) ? kh  : vh;
    __nv_bfloat16* Cl       = (z == 0) ? ql  : (z == 1) ? kl  : vl;
    gemm_body<true>(xh, xl, Th, Tl, bias, nullptr, Ch, Cl);
}

__global__ void __launch_bounds__(256, 2) gemm_proj(
    const __nv_bfloat16* __restrict__ yh, const __nv_bfloat16* __restrict__ yl,
    const __nv_bfloat16* __restrict__ wph, const __nv_bfloat16* __restrict__ wpl,
    const float* __restrict__ bp, float* __restrict__ out)
{
    gemm_body<false>(yh, yl, wph, wpl, bp, out, nullptr, nullptr);
}

// ---------------------------------------------------------------------------
// Tensor-core flash attention (causal), bf16x3, online softmax.
// 3-stage cp.async, single barrier per KV tile. Heavy blocks first.
// Fragment loads at per-np granularity (8 transient regs) + launch_bounds
// (256, 2) -> 2 CTAs/SM.
// ---------------------------------------------------------------------------
#define AT_STRIDE 144
#define AT_TILE   (64*AT_STRIDE)     // 9216
#define AT_STAGE  (4*AT_TILE)        // 36864
#define AT_SMEM   (3*AT_STAGE)       // 110592; x2 = 216 KB <= 228 KB/SM

__global__ void __launch_bounds__(256, 2) attn_tc(
    const __nv_bfloat16* __restrict__ Qh, const __nv_bfloat16* __restrict__ Ql,
    const __nv_bfloat16* __restrict__ Kh, const __nv_bfloat16* __restrict__ Kl,
    const __nv_bfloat16* __restrict__ Vh, const __nv_bfloat16* __restrict__ Vl,
    __nv_bfloat16* __restrict__ Yh, __nv_bfloat16* __restrict__ Yl)
{
    extern __shared__ char sm[];
    const uint32_t smb = smem_u32(sm);

    const int tid  = threadIdx.x;
    const int warp = tid >> 5;
    const int lane = tid & 31;
    const int g    = lane >> 2;
    const int t4   = lane & 3;

    const int qb = (int)gridDim.x - 1 - (int)blockIdx.x;
    const int h  = blockIdx.y;
    const int b  = blockIdx.z;
    const int q0 = qb * 128;

    const size_t base = (size_t)(b * H_ + h) * T_ * HD_;
    const __nv_bfloat16* qh = Qh + base + (size_t)q0 * HD_;
    const __nv_bfloat16* ql = Ql + base + (size_t)q0 * HD_;
    const __nv_bfloat16* kh = Kh + base;
    const __nv_bfloat16* kl = Kl + base;
    const __nv_bfloat16* vh = Vh + base;
    const __nv_bfloat16* vl = Vl + base;

    const int arow = (lane & 7) + ((lane >> 3) & 1) * 8;
    const int achk = (lane >> 4) & 1;
    const int brow = (lane & 7) + ((lane >> 4) & 1) * 8;
    const int bchk = (lane >> 3) & 1;

    #pragma unroll
    for (int i = 0; i < 4; i++) {
        const int ch = tid + i * 256;
        const int row = ch >> 3, q = ch & 7;
        const uint32_t d = smb + (row >> 6) * AT_TILE + (row & 63) * AT_STRIDE + q * 16;
        cp_async16(d,               qh + (size_t)row * HD_ + q * 8);
        cp_async16(d + 2*AT_TILE,   ql + (size_t)row * HD_ + q * 8);
    }
    cp_commit(); cp_wait0();
    __syncthreads();

    uint32_t qfh[4][4], qfl[4][4];
    {
        const int wr = warp * 16;
        const uint32_t qbse = smb + (wr >> 6) * AT_TILE + (wr & 63) * AT_STRIDE
                            + arow * AT_STRIDE + achk * 16;
        #pragma unroll
        for (int kc = 0; kc < 4; kc++) {
            ldsm_x4(qfh[kc], qbse + kc * 32);
            ldsm_x4(qfl[kc], qbse + 2*AT_TILE + kc * 32);
        }
    }
    __syncthreads();

    auto load_stage = [&](int s, int kt) {
        const int kv0 = kt * 64;
        const uint32_t st = smb + s * AT_STAGE;
        #pragma unroll
        for (int i = 0; i < 2; i++) {
            const int ch = tid + i * 256;
            const int row = ch >> 3, q = ch & 7;
            const uint32_t d = st + row * AT_STRIDE + q * 16;
            const size_t go = (size_t)(kv0 + row) * HD_ + q * 8;
            cp_async16(d,               kh + go);
            cp_async16(d + AT_TILE,     kl + go);
            cp_async16(d + 2*AT_TILE,   vh + go);
            cp_async16(d + 3*AT_TILE,   vl + go);
        }
        cp_commit();
    };

    float O[8][4];
    #pragma unroll
    for (int j = 0; j < 8; j++)
        #pragma unroll
        for (int r = 0; r < 4; r++) O[j][r] = 0.f;
    float m0 = -1e30f, m1 = -1e30f, l0 = 0.f, l1 = 0.f;

    const int nt = 2 * (qb + 1);
    const int R  = q0 + warp * 16;

    load_stage(0, 0);
    if (nt > 1) load_stage(1, 1);

    for (int kt = 0; kt < nt; kt++) {
        const int s = kt % 3;
        const int kv0 = kt * 64;
        if (kt + 1 < nt) cp_wait1(); else cp_wait0();
        __syncthreads();
        if (kt + 2 < nt) load_stage((kt + 2) % 3, kt + 2);

        if (kv0 <= R + 15) {
            const uint32_t st = smb + s * AT_STAGE;

            // ---- S = Q K^T (bf16x3), per-np fragment granularity ----
            float S[8][4];
            #pragma unroll
            for (int j = 0; j < 8; j++)
                #pragma unroll
                for (int r = 0; r < 4; r++) S[j][r] = 0.f;

            #pragma unroll
            for (int kc = 0; kc < 4; kc++) {
                #pragma unroll
                for (int np = 0; np < 4; np++) {
                    uint32_t kfh[4], kfl[4];
                    const uint32_t a = st + (np * 16 + brow) * AT_STRIDE + bchk * 16 + kc * 32;
                    ldsm_x4(kfh, a);
                    ldsm_x4(kfl, a + AT_TILE);
                    const int j0 = 2 * np;
                    mma_bf16(S[j0],     qfh[kc], kfh[0], kfh[1]);
                    mma_bf16(S[j0 + 1], qfh[kc], kfh[2], kfh[3]);
                    mma_bf16(S[j0],     qfh[kc], kfl[0], kfl[1]);
                    mma_bf16(S[j0 + 1], qfh[kc], kfl[2], kfl[3]);
                    mma_bf16(S[j0],     qfl[kc], kfh[0], kfh[1]);
                    mma_bf16(S[j0 + 1], qfl[kc], kfh[2], kfh[3]);
                }
            }

            const int row0 = R + g, row1 = R + g + 8;
            const bool need_mask = (kv0 + 63 > R);
            #pragma unroll
            for (int j = 0; j < 8; j++) {
                #pragma unroll
                for (int r = 0; r < 4; r++) S[j][r] *= 0.125f;
                if (need_mask) {
                    const int c0 = kv0 + 8 * j + 2 * t4;
                    if (c0     > row0) S[j][0] = -1e30f;
                    if (c0 + 1 > row0) S[j][1] = -1e30f;
                    if (c0     > row1) S[j][2] = -1e30f;
                    if (c0 + 1 > row1) S[j][3] = -1e30f;
                }
            }

            float mx0 = -1e30f, mx1 = -1e30f;
            #pragma unroll
            for (int j = 0; j < 8; j++) {
                mx0 = fmaxf(mx0, fmaxf(S[j][0], S[j][1]));
                mx1 = fmaxf(mx1, fmaxf(S[j][2], S[j][3]));
            }
            mx0 = fmaxf(mx0, __shfl_xor_sync(0xffffffffu, mx0, 1));
            mx0 = fmaxf(mx0, __shfl_xor_sync(0xffffffffu, mx0, 2));
            mx1 = fmaxf(mx1, __shfl_xor_sync(0xffffffffu, mx1, 1));
            mx1 = fmaxf(mx1, __shfl_xor_sync(0xffffffffu, mx1, 2));

            const float nm0 = fmaxf(m0, mx0);
            const float nm1 = fmaxf(m1, mx1);
            const float cr0 = __expf(m0 - nm0);
            const float cr1 = __expf(m1 - nm1);

            float s0 = 0.f, s1 = 0.f;
            #pragma unroll
            for (int j = 0; j < 8; j++) {
                S[j][0] = __expf(S[j][0] - nm0);
                S[j][1] = __expf(S[j][1] - nm0);
                S[j][2] = __expf(S[j][2] - nm1);
                S[j][3] = __expf(S[j][3] - nm1);
                s0 += S[j][0] + S[j][1];
                s1 += S[j][2] + S[j][3];
            }
            s0 += __shfl_xor_sync(0xffffffffu, s0, 1);
            s0 += __shfl_xor_sync(0xffffffffu, s0, 2);
            s1 += __shfl_xor_sync(0xffffffffu, s1, 1);
            s1 += __shfl_xor_sync(0xffffffffu, s1, 2);

            l0 = l0 * cr0 + s0;  m0 = nm0;
            l1 = l1 * cr1 + s1;  m1 = nm1;

            #pragma unroll
            for (int j = 0; j < 8; j++) {
                O[j][0] *= cr0;  O[j][1] *= cr0;
                O[j][2] *= cr1;  O[j][3] *= cr1;
            }

            uint32_t ph[4][4], pl[4][4];
            #pragma unroll
            for (int kc = 0; kc < 4; kc++) {
                __nv_bfloat16 ha, la, hb, lb;
                split_bf16(S[2*kc][0], ha, la);  split_bf16(S[2*kc][1], hb, lb);
                ph[kc][0] = pack_bf162(ha, hb);  pl[kc][0] = pack_bf162(la, lb);
                split_bf16(S[2*kc][2], ha, la);  split_bf16(S[2*kc][3], hb, lb);
                ph[kc][1] = pack_bf162(ha, hb);  pl[kc][1] = pack_bf162(la, lb);
                split_bf16(S[2*kc+1][0], ha, la); split_bf16(S[2*kc+1][1], hb, lb);
                ph[kc][2] = pack_bf162(ha, hb);  pl[kc][2] = pack_bf162(la, lb);
                split_bf16(S[2*kc+1][2], ha, la); split_bf16(S[2*kc+1][3], hb, lb);
                ph[kc][3] = pack_bf162(ha, hb);  pl[kc][3] = pack_bf162(la, lb);
            }

            // ---- O += P V (bf16x3), per-np fragment granularity ----
            #pragma unroll
            for (int kc = 0; kc < 4; kc++) {
                #pragma unroll
                for (int np = 0; np < 4; np++) {
                    uint32_t vfh[4], vfl[4];
                    const uint32_t a = st + 2*AT_TILE + (kc * 16 + arow) * AT_STRIDE
                                     + np * 32 + achk * 16;
                    ldsm_x4t(vfh, a);
                    ldsm_x4t(vfl, a + AT_TILE);
                    const int j0 = 2 * np;
                    mma_bf16(O[j0],     ph[kc], vfh[0], vfh[1]);
                    mma_bf16(O[j0 + 1], ph[kc], vfh[2], vfh[3]);
                    mma_bf16(O[j0],     pl[kc], vfh[0], vfh[1]);
                    mma_bf16(O[j0 + 1], pl[kc], vfh[2], vfh[3]);
                    mma_bf16(O[j0],     ph[kc], vfl[0], vfl[1]);
                    mma_bf16(O[j0 + 1], ph[kc], vfl[2], vfl[3]);
                }
            }
        }
    }

    const float inv0 = 1.0f / l0;
    const float inv1 = 1.0f / l1;
    const int row0 = q0 + warp * 16 + g;
    const int row1 = row0 + 8;
    #pragma unroll
    for (int j = 0; j < 8; j++) {
        const int col = h * HD_ + 8 * j + 2 * t4;
        const size_t o0 = (size_t)(b * T_ + row0) * E_ + col;
        const size_t o1 = (size_t)(b * T_ + row1) * E_ + col;
        __nv_bfloat16 ha, la, hb, lb;
        split_bf16(O[j][0] * inv0, ha, la);
        split_bf16(O[j][1] * inv0, hb, lb);
        *(uint32_t*)&Yh[o0] = pack_bf162(ha, hb);
        *(uint32_t*)&Yl[o0] = pack_bf162(la, lb);
        split_bf16(O[j][2] * inv1, ha, la);
        split_bf16(O[j][3] * inv1, hb, lb);
        *(uint32_t*)&Yh[o1] = pack_bf162(ha, hb);
        *(uint32_t*)&Yl[o1] = pack_bf162(la, lb);
    }
}

// ---------------------------------------------------------------------------
extern "C" void kernel_launch(void* const* d_in, const int* in_sizes, int n_in,
                              void* d_out, int out_size)
{
    const float* x  = (const float*)d_in[0];
    const float* Wq = (const float*)d_in[2];
    const float* bq = (const float*)d_in[3];
    const float* Wk = (const float*)d_in[4];
    const float* bk = (const float*)d_in[5];
    const float* Wv = (const float*)d_in[6];
    const float* bv = (const float*)d_in[7];
    const float* Wp = (const float*)d_in[8];
    const float* bp = (const float*)d_in[9];
    float* out = (float*)d_out;

    __nv_bfloat16 *xh, *xl, *yh, *yl, *qh, *ql, *kh, *kl, *vh, *vl;
    __nv_bfloat16 *wqh, *wql, *wkh, *wkl, *wvh, *wvl, *wph, *wpl;
    cudaGetSymbolAddress((void**)&xh, g_xh);  cudaGetSymbolAddress((void**)&xl, g_xl);
    cudaGetSymbolAddress((void**)&yh, g_yh);  cudaGetSymbolAddress((void**)&yl, g_yl);
    cudaGetSymbolAddress((void**)&qh, g_qh);  cudaGetSymbolAddress((void**)&ql, g_ql);
    cudaGetSymbolAddress((void**)&kh, g_kh);  cudaGetSymbolAddress((void**)&kl, g_kl);
    cudaGetSymbolAddress((void**)&vh, g_vh);  cudaGetSymbolAddress((void**)&vl, g_vl);
    cudaGetSymbolAddress((void**)&wqh, g_wqh);  cudaGetSymbolAddress((void**)&wql, g_wql);
    cudaGetSymbolAddress((void**)&wkh, g_wkh);  cudaGetSymbolAddress((void**)&wkl, g_wkl);
    cudaGetSymbolAddress((void**)&wvh, g_wvh);  cudaGetSymbolAddress((void**)&wvl, g_wvl);
    cudaGetSymbolAddress((void**)&wph, g_wph);  cudaGetSymbolAddress((void**)&wpl, g_wpl);

    cudaFuncSetAttribute(gemm_qkv,  cudaFuncAttributeMaxDynamicSharedMemorySize, GS_SMEM);
    cudaFuncSetAttribute(gemm_proj, cudaFuncAttributeMaxDynamicSharedMemorySize, GS_SMEM);
    cudaFuncSetAttribute(attn_tc,   cudaFuncAttributeMaxDynamicSharedMemorySize, AT_SMEM);

    // Prep: split x, transpose+split weights
    split_kernel<<<(M_*E_/4 + 255)/256, 256>>>(x, xh, xl, M_*E_/4);
    dim3 tgrid(E_/32, E_/32), tblk(32, 8);
    tsplit_kernel<<<tgrid, tblk>>>(Wq, wqh, wql);
    tsplit_kernel<<<tgrid, tblk>>>(Wk, wkh, wkl);
    tsplit_kernel<<<tgrid, tblk>>>(Wv, wvh, wvl);
    tsplit_kernel<<<tgrid, tblk>>>(Wp, wph, wpl);

    // Fused QKV projections
    dim3 qkv_grid(E_ / 128, M_ / 128, 3);   // (8, 64, 3)
    gemm_qkv<<<qkv_grid, 256, GS_SMEM>>>(xh, xl,
                                         wqh, wql, wkh, wkl, wvh, wvl,
                                         bq, bk, bv,
                                         qh, ql, kh, kl, vh, vl);

    dim3 attn_grid(T_ / 128, H_, B_);       // (16, 16, 4)
    attn_tc<<<attn_grid, 256, AT_SMEM>>>(qh, ql, kh, kl, vh, vl, yh, yl);

    dim3 proj_grid(E_ / 128, M_ / 128);     // (8, 64)
    gemm_proj<<<proj_grid, 256, GS_SMEM>>>(yh, yl, wph, wpl, bp, out);
}

// round 12
// speedup vs baseline: 2.0124x; 1.0324x over previous
#include <cuda_runtime.h>
#include <cuda_bf16.h>
#include <stdint.h>
#include <math.h>

#define B_  4
#define T_  2048
#define E_  1024
#define H_  16
#define HD_ 64
#define M_  (B_*T_)   // 8192

// q pre-scale: 0.125 (1/sqrt(hd)) * log2(e)  -> softmax via ex2
#define QSCALE 0.180336880f

// Scratch (device globals: allocation-free)
__device__ __nv_bfloat16 g_xh[M_*E_], g_xl[M_*E_];
__device__ __nv_bfloat16 g_yh[M_*E_], g_yl[M_*E_];
__device__ __nv_bfloat16 g_qh[M_*E_], g_ql[M_*E_];
__device__ __nv_bfloat16 g_kh[M_*E_], g_kl[M_*E_];
__device__ __nv_bfloat16 g_vh[M_*E_], g_vl[M_*E_];
__device__ __nv_bfloat16 g_wqh[E_*E_], g_wql[E_*E_];
__device__ __nv_bfloat16 g_wkh[E_*E_], g_wkl[E_*E_];
__device__ __nv_bfloat16 g_wvh[E_*E_], g_wvl[E_*E_];
__device__ __nv_bfloat16 g_wph[E_*E_], g_wpl[E_*E_];

// ---------------------------------------------------------------------------
// helpers
// ---------------------------------------------------------------------------
__device__ __forceinline__ uint32_t smem_u32(const void* p) {
    return (uint32_t)__cvta_generic_to_shared(p);
}
__device__ __forceinline__ void cp_async16(uint32_t dst, const void* src) {
    asm volatile("cp.async.cg.shared.global [%0], [%1], 16;\n" :: "r"(dst), "l"(src));
}
__device__ __forceinline__ void cp_commit() { asm volatile("cp.async.commit_group;\n"); }
__device__ __forceinline__ void cp_wait0() { asm volatile("cp.async.wait_group 0;\n"); }
__device__ __forceinline__ void cp_wait1() { asm volatile("cp.async.wait_group 1;\n"); }

__device__ __forceinline__ void mma_bf16(float c[4], const uint32_t a[4], uint32_t b0, uint32_t b1) {
    asm volatile(
        "mma.sync.aligned.m16n8k16.row.col.f32.bf16.bf16.f32 "
        "{%0,%1,%2,%3}, {%4,%5,%6,%7}, {%8,%9}, {%0,%1,%2,%3};\n"
        : "+f"(c[0]), "+f"(c[1]), "+f"(c[2]), "+f"(c[3])
        : "r"(a[0]), "r"(a[1]), "r"(a[2]), "r"(a[3]), "r"(b0), "r"(b1));
}
__device__ __forceinline__ void ldsm_x4(uint32_t r[4], uint32_t addr) {
    asm volatile("ldmatrix.sync.aligned.m8n8.x4.shared.b16 {%0,%1,%2,%3}, [%4];"
        : "=r"(r[0]), "=r"(r[1]), "=r"(r[2]), "=r"(r[3]) : "r"(addr));
}
__device__ __forceinline__ void ldsm_x4t(uint32_t r[4], uint32_t addr) {
    asm volatile("ldmatrix.sync.aligned.m8n8.x4.trans.shared.b16 {%0,%1,%2,%3}, [%4];"
        : "=r"(r[0]), "=r"(r[1]), "=r"(r[2]), "=r"(r[3]) : "r"(addr));
}
__device__ __forceinline__ void split_bf16(float v, __nv_bfloat16& h, __nv_bfloat16& l) {
    h = __float2bfloat16(v);
    l = __float2bfloat16(v - __bfloat162float(h));
}
__device__ __forceinline__ uint32_t pack_bf162(__nv_bfloat16 a, __nv_bfloat16 b) {
    __nv_bfloat162 p(a, b);
    return *(uint32_t*)&p;
}
// Packed split: (a,b) -> hi pair {a_lo16, b_hi16} and lo pair, a in low half.
__device__ __forceinline__ void split2(float a, float b, uint32_t& h2, uint32_t& l2) {
    uint32_t h;
    asm("cvt.rn.bf16x2.f32 %0, %1, %2;" : "=r"(h) : "f"(b), "f"(a));
    const float ha = __uint_as_float(h << 16);
    const float hb = __uint_as_float(h & 0xffff0000u);
    asm("cvt.rn.bf16x2.f32 %0, %1, %2;" : "=r"(l2) : "f"(b - hb), "f"(a - ha));
    h2 = h;
}
__device__ __forceinline__ float fast_ex2(float x) {
    float y;
    asm("ex2.approx.ftz.f32 %0, %1;" : "=f"(y) : "f"(x));
    return y;
}

// ---------------------------------------------------------------------------
// Prep: split fp32 -> bf16 hi/lo, same layout.
// ---------------------------------------------------------------------------
__global__ void split_kernel(const float* __restrict__ src,
                             __nv_bfloat16* __restrict__ hi,
                             __nv_bfloat16* __restrict__ lo, int n4)
{
    int i = blockIdx.x * blockDim.x + threadIdx.x;
    if (i >= n4) return;
    float4 v = ((const float4*)src)[i];
    __nv_bfloat16 h0,h1,h2,h3,l0,l1,l2,l3;
    split_bf16(v.x,h0,l0); split_bf16(v.y,h1,l1);
    split_bf16(v.z,h2,l2); split_bf16(v.w,h3,l3);
    ((__nv_bfloat162*)hi)[i*2+0] = __nv_bfloat162(h0,h1);
    ((__nv_bfloat162*)hi)[i*2+1] = __nv_bfloat162(h2,h3);
    ((__nv_bfloat162*)lo)[i*2+0] = __nv_bfloat162(l0,l1);
    ((__nv_bfloat162*)lo)[i*2+1] = __nv_bfloat162(l2,l3);
}

// ---------------------------------------------------------------------------
// Prep: transpose + split. W[K][N] fp32 -> Th/Tl[N][K] bf16.
// ---------------------------------------------------------------------------
__global__ void tsplit_kernel(const float* __restrict__ W,
                              __nv_bfloat16* __restrict__ Th,
                              __nv_bfloat16* __restrict__ Tl)
{
    __shared__ float t[32][33];
    const int n0 = blockIdx.x * 32, k0 = blockIdx.y * 32;
    const int tx = threadIdx.x, ty = threadIdx.y;   // (32, 8)
    #pragma unroll
    for (int i = 0; i < 4; i++)
        t[ty + 8*i][tx] = W[(size_t)(k0 + ty + 8*i) * E_ + n0 + tx];
    __syncthreads();
    #pragma unroll
    for (int i = 0; i < 4; i++) {
        const int row = ty + 8*i;
        const float v = t[tx][row];
        __nv_bfloat16 h, l;
        split_bf16(v, h, l);
        Th[(size_t)(n0 + row) * E_ + k0 + tx] = h;
        Tl[(size_t)(n0 + row) * E_ + k0 + tx] = l;
    }
}

// ---------------------------------------------------------------------------
// bf16x3 tensor-core GEMM body, 3-stage cp.async, single barrier/iter,
// XOR-swizzled smem (64B rows) -> 98304 B -> 2 CTAs/SM.
// oscale applied to outputs in the REORDER path (Q pre-scaling).
// ---------------------------------------------------------------------------
#define GS_TILE   8192
#define GS_STAGE  (4*GS_TILE)          // 32768 B
#define GS_SMEM   (3*GS_STAGE)         // 98304 B

template<bool REORDER>
__device__ __forceinline__ void gemm_body(
    const __nv_bfloat16* __restrict__ Ah, const __nv_bfloat16* __restrict__ Al,
    const __nv_bfloat16* __restrict__ Th, const __nv_bfloat16* __restrict__ Tl,
    const float* __restrict__ bias, float* __restrict__ C,
    __nv_bfloat16* __restrict__ Ch, __nv_bfloat16* __restrict__ Cl,
    float oscale)
{
    extern __shared__ char sm[];
    const uint32_t smb = smem_u32(sm);

    const int tid  = threadIdx.x;
    const int warp = tid >> 5;
    const int lane = tid & 31;
    const int group = lane >> 2;
    const int tidg  = lane & 3;

    const int bn = blockIdx.x, bm = blockIdx.y;
    const int m0 = bm * 128, n0 = bn * 128;
    const int warp_m = warp & 1;
    const int warp_n = warp >> 1;

    const int lrow = (lane & 7) + ((lane >> 3) & 1) * 8;
    const int lchk = (lane >> 4) & 1;
    const int sel  = (lrow >> 1) & 3;

    auto load_stage = [&](int s, int c) {
        const int kb = c * 32;
        const uint32_t st = smb + s * GS_STAGE;
        #pragma unroll
        for (int i = 0; i < 2; i++) {
            const int ch = tid + i * 256;
            const int row = ch >> 2, q = ch & 3;
            const uint32_t d = st + row * 64 + (((q ^ ((row >> 1) & 3))) << 4);
            const size_t ga = (size_t)(m0 + row) * E_ + kb + q * 8;
            const size_t gb = (size_t)(n0 + row) * E_ + kb + q * 8;
            cp_async16(d,               Ah + ga);
            cp_async16(d + GS_TILE,     Al + ga);
            cp_async16(d + 2*GS_TILE,   Th + gb);
            cp_async16(d + 3*GS_TILE,   Tl + gb);
        }
        cp_commit();
    };

    float acc[4][4][4];
    #pragma unroll
    for (int i = 0; i < 4; i++)
        #pragma unroll
        for (int j = 0; j < 4; j++)
            #pragma unroll
            for (int r = 0; r < 4; r++) acc[i][j][r] = 0.f;

    const int NC = E_ / 32;
    load_stage(0, 0);
    load_stage(1, 1);

    for (int c = 0; c < NC; c++) {
        const int s = c % 3;
        if (c + 1 < NC) cp_wait1(); else cp_wait0();
        __syncthreads();
        if (c + 2 < NC) load_stage((c + 2) % 3, c + 2);

        const uint32_t st = smb + s * GS_STAGE;
        const uint32_t abase = st + (warp_m * 64 + lrow) * 64;
        const uint32_t bbase = st + 2*GS_TILE + (warp_n * 32 + lrow) * 64;

        #pragma unroll
        for (int h2 = 0; h2 < 2; h2++) {
            const uint32_t co = (uint32_t)(((lchk + 2 * h2) ^ sel) << 4);
            uint32_t ah[4][4], al[4][4], bh[2][4], bl[2][4];
            #pragma unroll
            for (int i = 0; i < 4; i++) {
                ldsm_x4(ah[i], abase + i * 16 * 64 + co);
                ldsm_x4(al[i], abase + GS_TILE + i * 16 * 64 + co);
            }
            #pragma unroll
            for (int g = 0; g < 2; g++) {
                ldsm_x4(bh[g], bbase + g * 16 * 64 + co);
                ldsm_x4(bl[g], bbase + GS_TILE + g * 16 * 64 + co);
            }
            #pragma unroll
            for (int i = 0; i < 4; i++)
                #pragma unroll
                for (int j = 0; j < 4; j++)
                    mma_bf16(acc[i][j], ah[i], bh[j>>1][j&1], bh[j>>1][(j&1)+2]);
            #pragma unroll
            for (int i = 0; i < 4; i++)
                #pragma unroll
                for (int j = 0; j < 4; j++)
                    mma_bf16(acc[i][j], ah[i], bl[j>>1][j&1], bl[j>>1][(j&1)+2]);
            #pragma unroll
            for (int i = 0; i < 4; i++)
                #pragma unroll
                for (int j = 0; j < 4; j++)
                    mma_bf16(acc[i][j], al[i], bh[j>>1][j&1], bh[j>>1][(j&1)+2]);
        }
    }

    #pragma unroll
    for (int i = 0; i < 4; i++) {
        const int rmb = m0 + warp_m * 64 + i * 16 + group;
        #pragma unroll
        for (int j = 0; j < 4; j++) {
            const int cb = n0 + warp_n * 32 + j * 8 + tidg * 2;
            const float bx = bias[cb], by = bias[cb + 1];
            #pragma unroll
            for (int half = 0; half < 2; half++) {
                const int m = rmb + half * 8;
                const float vx = (acc[i][j][half * 2 + 0] + bx) * (REORDER ? oscale : 1.f);
                const float vy = (acc[i][j][half * 2 + 1] + by) * (REORDER ? oscale : 1.f);
                if (REORDER) {
                    const int b = m >> 11;
                    const int t = m & (T_ - 1);
                    const int h = cb >> 6;
                    const int d = cb & (HD_ - 1);
                    const size_t o = (((size_t)(b * H_ + h) * T_) + t) * HD_ + d;
                    uint32_t h2, l2;
                    split2(vx, vy, h2, l2);
                    *(uint32_t*)&Ch[o] = h2;
                    *(uint32_t*)&Cl[o] = l2;
                } else {
                    float2 v; v.x = vx; v.y = vy;
                    *(float2*)&C[(size_t)m * E_ + cb] = v;
                }
            }
        }
    }
}

// Fused QKV: blockIdx.z selects weight/bias/output. Q gets QSCALE.
__global__ void __launch_bounds__(256, 2) gemm_qkv(
    const __nv_bfloat16* __restrict__ xh, const __nv_bfloat16* __restrict__ xl,
    const __nv_bfloat16* __restrict__ wqh, const __nv_bfloat16* __restrict__ wql,
    const __nv_bfloat16* __restrict__ wkh, const __nv_bfloat16* __restrict__ wkl,
    const __nv_bfloat16* __restrict__ wvh, const __nv_bfloat16* __restrict__ wvl,
    const float* __restrict__ bq, const float* __restrict__ bk, const float* __restrict__ bv,
    __nv_bfloat16* __restrict__ qh, __nv_bfloat16* __restrict__ ql,
    __nv_bfloat16* __restrict__ kh, __nv_bfloat16* __restrict__ kl,
    __nv_bfloat16* __restrict__ vh, __nv_bfloat16* __restrict__ vl)
{
    const int z = blockIdx.z;
    const __nv_bfloat16* Th = (z == 0) ? wqh : (z == 1) ? wkh : wvh;
    const __nv_bfloat16* Tl = (z == 0) ? wql : (z == 1) ? wkl : wvl;
    const float* bias       = (z == 0) ? bq  : (z == 1) ? bk  : bv;
    __nv_bfloat16* Ch       = (z == 0) ? qh  : (z == 1) ? kh  : vh;
    __nv_bfloat16* Cl       = (z == 0) ? ql  : (z == 1) ? kl  : vl;
    const float oscale      = (z == 0) ? QSCALE : 1.0f;
    gemm_body<true>(xh, xl, Th, Tl, bias, nullptr, Ch, Cl, oscale);
}

__global__ void __launch_bounds__(256, 2) gemm_proj(
    const __nv_bfloat16* __restrict__ yh, const __nv_bfloat16* __restrict__ yl,
    const __nv_bfloat16* __restrict__ wph, const __nv_bfloat16* __restrict__ wpl,
    const float* __restrict__ bp, float* __restrict__ out)
{
    gemm_body<false>(yh, yl, wph, wpl, bp, out, nullptr, nullptr, 1.0f);
}

// ---------------------------------------------------------------------------
// Tensor-core flash attention (causal), bf16x3, online softmax in log2
// domain (Q pre-scaled by 0.125*log2e, P = 2^(S-m) via bare ex2.approx).
// 3-stage cp.async, single barrier per KV tile. Heavy blocks first.
// Per-np fragment granularity + launch_bounds(256, 2) -> 2 CTAs/SM.
// ---------------------------------------------------------------------------
#define AT_STRIDE 144
#define AT_TILE   (64*AT_STRIDE)     // 9216
#define AT_STAGE  (4*AT_TILE)        // 36864
#define AT_SMEM   (3*AT_STAGE)       // 110592; x2 = 216 KB <= 228 KB/SM

__global__ void __launch_bounds__(256, 2) attn_tc(
    const __nv_bfloat16* __restrict__ Qh, const __nv_bfloat16* __restrict__ Ql,
    const __nv_bfloat16* __restrict__ Kh, const __nv_bfloat16* __restrict__ Kl,
    const __nv_bfloat16* __restrict__ Vh, const __nv_bfloat16* __restrict__ Vl,
    __nv_bfloat16* __restrict__ Yh, __nv_bfloat16* __restrict__ Yl)
{
    extern __shared__ char sm[];
    const uint32_t smb = smem_u32(sm);

    const int tid  = threadIdx.x;
    const int warp = tid >> 5;
    const int lane = tid & 31;
    const int g    = lane >> 2;
    const int t4   = lane & 3;

    const int qb = (int)gridDim.x - 1 - (int)blockIdx.x;
    const int h  = blockIdx.y;
    const int b  = blockIdx.z;
    const int q0 = qb * 128;

    const size_t base = (size_t)(b * H_ + h) * T_ * HD_;
    const __nv_bfloat16* qh = Qh + base + (size_t)q0 * HD_;
    const __nv_bfloat16* ql = Ql + base + (size_t)q0 * HD_;
    const __nv_bfloat16* kh = Kh + base;
    const __nv_bfloat16* kl = Kl + base;
    const __nv_bfloat16* vh = Vh + base;
    const __nv_bfloat16* vl = Vl + base;

    const int arow = (lane & 7) + ((lane >> 3) & 1) * 8;
    const int achk = (lane >> 4) & 1;
    const int brow = (lane & 7) + ((lane >> 4) & 1) * 8;
    const int bchk = (lane >> 3) & 1;

    #pragma unroll
    for (int i = 0; i < 4; i++) {
        const int ch = tid + i * 256;
        const int row = ch >> 3, q = ch & 7;
        const uint32_t d = smb + (row >> 6) * AT_TILE + (row & 63) * AT_STRIDE + q * 16;
        cp_async16(d,               qh + (size_t)row * HD_ + q * 8);
        cp_async16(d + 2*AT_TILE,   ql + (size_t)row * HD_ + q * 8);
    }
    cp_commit(); cp_wait0();
    __syncthreads();

    uint32_t qfh[4][4], qfl[4][4];
    {
        const int wr = warp * 16;
        const uint32_t qbse = smb + (wr >> 6) * AT_TILE + (wr & 63) * AT_STRIDE
                            + arow * AT_STRIDE + achk * 16;
        #pragma unroll
        for (int kc = 0; kc < 4; kc++) {
            ldsm_x4(qfh[kc], qbse + kc * 32);
            ldsm_x4(qfl[kc], qbse + 2*AT_TILE + kc * 32);
        }
    }
    __syncthreads();

    auto load_stage = [&](int s, int kt) {
        const int kv0 = kt * 64;
        const uint32_t st = smb + s * AT_STAGE;
        #pragma unroll
        for (int i = 0; i < 2; i++) {
            const int ch = tid + i * 256;
            const int row = ch >> 3, q = ch & 7;
            const uint32_t d = st + row * AT_STRIDE + q * 16;
            const size_t go = (size_t)(kv0 + row) * HD_ + q * 8;
            cp_async16(d,               kh + go);
            cp_async16(d + AT_TILE,     kl + go);
            cp_async16(d + 2*AT_TILE,   vh + go);
            cp_async16(d + 3*AT_TILE,   vl + go);
        }
        cp_commit();
    };

    float O[8][4];
    #pragma unroll
    for (int j = 0; j < 8; j++)
        #pragma unroll
        for (int r = 0; r < 4; r++) O[j][r] = 0.f;
    float m0 = -1e30f, m1 = -1e30f, l0 = 0.f, l1 = 0.f;

    const int nt = 2 * (qb + 1);
    const int R  = q0 + warp * 16;

    load_stage(0, 0);
    if (nt > 1) load_stage(1, 1);

    for (int kt = 0; kt < nt; kt++) {
        const int s = kt % 3;
        const int kv0 = kt * 64;
        if (kt + 1 < nt) cp_wait1(); else cp_wait0();
        __syncthreads();
        if (kt + 2 < nt) load_stage((kt + 2) % 3, kt + 2);

        if (kv0 <= R + 15) {
            const uint32_t st = smb + s * AT_STAGE;

            // ---- S = Q K^T (bf16x3, Q pre-scaled) ----
            float S[8][4];
            #pragma unroll
            for (int j = 0; j < 8; j++)
                #pragma unroll
                for (int r = 0; r < 4; r++) S[j][r] = 0.f;

            #pragma unroll
            for (int kc = 0; kc < 4; kc++) {
                #pragma unroll
                for (int np = 0; np < 4; np++) {
                    uint32_t kfh[4], kfl[4];
                    const uint32_t a = st + (np * 16 + brow) * AT_STRIDE + bchk * 16 + kc * 32;
                    ldsm_x4(kfh, a);
                    ldsm_x4(kfl, a + AT_TILE);
                    const int j0 = 2 * np;
                    mma_bf16(S[j0],     qfh[kc], kfh[0], kfh[1]);
                    mma_bf16(S[j0 + 1], qfh[kc], kfh[2], kfh[3]);
                    mma_bf16(S[j0],     qfh[kc], kfl[0], kfl[1]);
                    mma_bf16(S[j0 + 1], qfh[kc], kfl[2], kfl[3]);
                    mma_bf16(S[j0],     qfl[kc], kfh[0], kfh[1]);
                    mma_bf16(S[j0 + 1], qfl[kc], kfh[2], kfh[3]);
                }
            }

            // ---- causal mask (no scale: folded into Q) ----
            const int row0 = R + g, row1 = R + g + 8;
            const bool need_mask = (kv0 + 63 > R);
            if (need_mask) {
                #pragma unroll
                for (int j = 0; j < 8; j++) {
                    const int c0 = kv0 + 8 * j + 2 * t4;
                    if (c0     > row0) S[j][0] = -1e30f;
                    if (c0 + 1 > row0) S[j][1] = -1e30f;
                    if (c0     > row1) S[j][2] = -1e30f;
                    if (c0 + 1 > row1) S[j][3] = -1e30f;
                }
            }

            float mx0 = -1e30f, mx1 = -1e30f;
            #pragma unroll
            for (int j = 0; j < 8; j++) {
                mx0 = fmaxf(mx0, fmaxf(S[j][0], S[j][1]));
                mx1 = fmaxf(mx1, fmaxf(S[j][2], S[j][3]));
            }
            mx0 = fmaxf(mx0, __shfl_xor_sync(0xffffffffu, mx0, 1));
            mx0 = fmaxf(mx0, __shfl_xor_sync(0xffffffffu, mx0, 2));
            mx1 = fmaxf(mx1, __shfl_xor_sync(0xffffffffu, mx1, 1));
            mx1 = fmaxf(mx1, __shfl_xor_sync(0xffffffffu, mx1, 2));

            const float nm0 = fmaxf(m0, mx0);
            const float nm1 = fmaxf(m1, mx1);
            const float cr0 = fast_ex2(m0 - nm0);
            const float cr1 = fast_ex2(m1 - nm1);

            float s0 = 0.f, s1 = 0.f;
            #pragma unroll
            for (int j = 0; j < 8; j++) {
                S[j][0] = fast_ex2(S[j][0] - nm0);
                S[j][1] = fast_ex2(S[j][1] - nm0);
                S[j][2] = fast_ex2(S[j][2] - nm1);
                S[j][3] = fast_ex2(S[j][3] - nm1);
                s0 += S[j][0] + S[j][1];
                s1 += S[j][2] + S[j][3];
            }
            s0 += __shfl_xor_sync(0xffffffffu, s0, 1);
            s0 += __shfl_xor_sync(0xffffffffu, s0, 2);
            s1 += __shfl_xor_sync(0xffffffffu, s1, 1);
            s1 += __shfl_xor_sync(0xffffffffu, s1, 2);

            l0 = l0 * cr0 + s0;  m0 = nm0;
            l1 = l1 * cr1 + s1;  m1 = nm1;

            #pragma unroll
            for (int j = 0; j < 8; j++) {
                O[j][0] *= cr0;  O[j][1] *= cr0;
                O[j][2] *= cr1;  O[j][3] *= cr1;
            }

            // ---- P fragments via packed splits ----
            uint32_t ph[4][4], pl[4][4];
            #pragma unroll
            for (int kc = 0; kc < 4; kc++) {
                split2(S[2*kc][0],   S[2*kc][1],   ph[kc][0], pl[kc][0]);
                split2(S[2*kc][2],   S[2*kc][3],   ph[kc][1], pl[kc][1]);
                split2(S[2*kc+1][0], S[2*kc+1][1], ph[kc][2], pl[kc][2]);
                split2(S[2*kc+1][2], S[2*kc+1][3], ph[kc][3], pl[kc][3]);
            }

            // ---- O += P V (bf16x3) ----
            #pragma unroll
            for (int kc = 0; kc < 4; kc++) {
                #pragma unroll
                for (int np = 0; np < 4; np++) {
                    uint32_t vfh[4], vfl[4];
                    const uint32_t a = st + 2*AT_TILE + (kc * 16 + arow) * AT_STRIDE
                                     + np * 32 + achk * 16;
                    ldsm_x4t(vfh, a);
                    ldsm_x4t(vfl, a + AT_TILE);
                    const int j0 = 2 * np;
                    mma_bf16(O[j0],     ph[kc], vfh[0], vfh[1]);
                    mma_bf16(O[j0 + 1], ph[kc], vfh[2], vfh[3]);
                    mma_bf16(O[j0],     pl[kc], vfh[0], vfh[1]);
                    mma_bf16(O[j0 + 1], pl[kc], vfh[2], vfh[3]);
                    mma_bf16(O[j0],     ph[kc], vfl[0], vfl[1]);
                    mma_bf16(O[j0 + 1], ph[kc], vfl[2], vfl[3]);
                }
            }
        }
    }

    const float inv0 = 1.0f / l0;
    const float inv1 = 1.0f / l1;
    const int row0 = q0 + warp * 16 + g;
    const int row1 = row0 + 8;
    #pragma unroll
    for (int j = 0; j < 8; j++) {
        const int col = h * HD_ + 8 * j + 2 * t4;
        const size_t o0 = (size_t)(b * T_ + row0) * E_ + col;
        const size_t o1 = (size_t)(b * T_ + row1) * E_ + col;
        uint32_t h2, l2;
        split2(O[j][0] * inv0, O[j][1] * inv0, h2, l2);
        *(uint32_t*)&Yh[o0] = h2;
        *(uint32_t*)&Yl[o0] = l2;
        split2(O[j][2] * inv1, O[j][3] * inv1, h2, l2);
        *(uint32_t*)&Yh[o1] = h2;
        *(uint32_t*)&Yl[o1] = l2;
    }
}

// ---------------------------------------------------------------------------
extern "C" void kernel_launch(void* const* d_in, const int* in_sizes, int n_in,
                              void* d_out, int out_size)
{
    const float* x  = (const float*)d_in[0];
    const float* Wq = (const float*)d_in[2];
    const float* bq = (const float*)d_in[3];
    const float* Wk = (const float*)d_in[4];
    const float* bk = (const float*)d_in[5];
    const float* Wv = (const float*)d_in[6];
    const float* bv = (const float*)d_in[7];
    const float* Wp = (const float*)d_in[8];
    const float* bp = (const float*)d_in[9];
    float* out = (float*)d_out;

    __nv_bfloat16 *xh, *xl, *yh, *yl, *qh, *ql, *kh, *kl, *vh, *vl;
    __nv_bfloat16 *wqh, *wql, *wkh, *wkl, *wvh, *wvl, *wph, *wpl;
    cudaGetSymbolAddress((void**)&xh, g_xh);  cudaGetSymbolAddress((void**)&xl, g_xl);
    cudaGetSymbolAddress((void**)&yh, g_yh);  cudaGetSymbolAddress((void**)&yl, g_yl);
    cudaGetSymbolAddress((void**)&qh, g_qh);  cudaGetSymbolAddress((void**)&ql, g_ql);
    cudaGetSymbolAddress((void**)&kh, g_kh);  cudaGetSymbolAddress((void**)&kl, g_kl);
    cudaGetSymbolAddress((void**)&vh, g_vh);  cudaGetSymbolAddress((void**)&vl, g_vl);
    cudaGetSymbolAddress((void**)&wqh, g_wqh);  cudaGetSymbolAddress((void**)&wql, g_wql);
    cudaGetSymbolAddress((void**)&wkh, g_wkh);  cudaGetSymbolAddress((void**)&wkl, g_wkl);
    cudaGetSymbolAddress((void**)&wvh, g_wvh);  cudaGetSymbolAddress((void**)&wvl, g_wvl);
    cudaGetSymbolAddress((void**)&wph, g_wph);  cudaGetSymbolAddress((void**)&wpl, g_wpl);

    cudaFuncSetAttribute(gemm_qkv,  cudaFuncAttributeMaxDynamicSharedMemorySize, GS_SMEM);
    cudaFuncSetAttribute(gemm_proj, cudaFuncAttributeMaxDynamicSharedMemorySize, GS_SMEM);
    cudaFuncSetAttribute(attn_tc,   cudaFuncAttributeMaxDynamicSharedMemorySize, AT_SMEM);

    // Prep: split x, transpose+split weights
    split_kernel<<<(M_*E_/4 + 255)/256, 256>>>(x, xh, xl, M_*E_/4);
    dim3 tgrid(E_/32, E_/32), tblk(32, 8);
    tsplit_kernel<<<tgrid, tblk>>>(Wq, wqh, wql);
    tsplit_kernel<<<tgrid, tblk>>>(Wk, wkh, wkl);
    tsplit_kernel<<<tgrid, tblk>>>(Wv, wvh, wvl);
    tsplit_kernel<<<tgrid, tblk>>>(Wp, wph, wpl);

    // Fused QKV projections
    dim3 qkv_grid(E_ / 128, M_ / 128, 3);   // (8, 64, 3)
    gemm_qkv<<<qkv_grid, 256, GS_SMEM>>>(xh, xl,
                                         wqh, wql, wkh, wkl, wvh, wvl,
                                         bq, bk, bv,
                                         qh, ql, kh, kl, vh, vl);

    dim3 attn_grid(T_ / 128, H_, B_);       // (16, 16, 4)
    attn_tc<<<attn_grid, 256, AT_SMEM>>>(qh, ql, kh, kl, vh, vl, yh, yl);

    dim3 proj_grid(E_ / 128, M_ / 128);     // (8, 64)
    gemm_proj<<<proj_grid, 256, GS_SMEM>>>(yh, yl, wph, wpl, bp, out);
}

// round 13
// speedup vs baseline: 2.0244x; 1.0060x over previous
#include <cuda_runtime.h>
#include <cuda_bf16.h>
#include <stdint.h>
#include <math.h>

#define B_  4
#define T_  2048
#define E_  1024
#define H_  16
#define HD_ 64
#define M_  (B_*T_)   // 8192

// q pre-scale: 0.125 (1/sqrt(hd)) * log2(e)  -> softmax via ex2
#define QSCALE 0.180336880f

// Scratch (device globals: allocation-free)
__device__ __nv_bfloat16 g_xh[M_*E_], g_xl[M_*E_];
__device__ __nv_bfloat16 g_yh[M_*E_], g_yl[M_*E_];
__device__ __nv_bfloat16 g_qh[M_*E_], g_ql[M_*E_];
__device__ __nv_bfloat16 g_kh[M_*E_], g_kl[M_*E_];
__device__ __nv_bfloat16 g_vh[M_*E_], g_vl[M_*E_];
__device__ __nv_bfloat16 g_wqh[E_*E_], g_wql[E_*E_];
__device__ __nv_bfloat16 g_wkh[E_*E_], g_wkl[E_*E_];
__device__ __nv_bfloat16 g_wvh[E_*E_], g_wvl[E_*E_];
__device__ __nv_bfloat16 g_wph[E_*E_], g_wpl[E_*E_];

// ---------------------------------------------------------------------------
// helpers
// ---------------------------------------------------------------------------
__device__ __forceinline__ uint32_t smem_u32(const void* p) {
    return (uint32_t)__cvta_generic_to_shared(p);
}
__device__ __forceinline__ void cp_async16(uint32_t dst, const void* src) {
    asm volatile("cp.async.cg.shared.global [%0], [%1], 16;\n" :: "r"(dst), "l"(src));
}
__device__ __forceinline__ void cp_commit() { asm volatile("cp.async.commit_group;\n"); }
__device__ __forceinline__ void cp_wait0() { asm volatile("cp.async.wait_group 0;\n"); }
__device__ __forceinline__ void cp_wait1() { asm volatile("cp.async.wait_group 1;\n"); }

__device__ __forceinline__ void mma_bf16(float c[4], const uint32_t a[4], uint32_t b0, uint32_t b1) {
    asm volatile(
        "mma.sync.aligned.m16n8k16.row.col.f32.bf16.bf16.f32 "
        "{%0,%1,%2,%3}, {%4,%5,%6,%7}, {%8,%9}, {%0,%1,%2,%3};\n"
        : "+f"(c[0]), "+f"(c[1]), "+f"(c[2]), "+f"(c[3])
        : "r"(a[0]), "r"(a[1]), "r"(a[2]), "r"(a[3]), "r"(b0), "r"(b1));
}
__device__ __forceinline__ void ldsm_x4(uint32_t r[4], uint32_t addr) {
    asm volatile("ldmatrix.sync.aligned.m8n8.x4.shared.b16 {%0,%1,%2,%3}, [%4];"
        : "=r"(r[0]), "=r"(r[1]), "=r"(r[2]), "=r"(r[3]) : "r"(addr));
}
__device__ __forceinline__ void ldsm_x4t(uint32_t r[4], uint32_t addr) {
    asm volatile("ldmatrix.sync.aligned.m8n8.x4.trans.shared.b16 {%0,%1,%2,%3}, [%4];"
        : "=r"(r[0]), "=r"(r[1]), "=r"(r[2]), "=r"(r[3]) : "r"(addr));
}
__device__ __forceinline__ void split_bf16(float v, __nv_bfloat16& h, __nv_bfloat16& l) {
    h = __float2bfloat16(v);
    l = __float2bfloat16(v - __bfloat162float(h));
}
// Packed split: (a,b) -> hi pair {a lo16, b hi16} and lo pair, a in low half.
__device__ __forceinline__ void split2(float a, float b, uint32_t& h2, uint32_t& l2) {
    uint32_t h;
    asm("cvt.rn.bf16x2.f32 %0, %1, %2;" : "=r"(h) : "f"(b), "f"(a));
    const float ha = __uint_as_float(h << 16);
    const float hb = __uint_as_float(h & 0xffff0000u);
    asm("cvt.rn.bf16x2.f32 %0, %1, %2;" : "=r"(l2) : "f"(b - hb), "f"(a - ha));
    h2 = h;
}
__device__ __forceinline__ float fast_ex2(float x) {
    float y;
    asm("ex2.approx.ftz.f32 %0, %1;" : "=f"(y) : "f"(x));
    return y;
}

// ---------------------------------------------------------------------------
// Prep: split fp32 -> bf16 hi/lo, same layout.
// ---------------------------------------------------------------------------
__global__ void split_kernel(const float* __restrict__ src,
                             __nv_bfloat16* __restrict__ hi,
                             __nv_bfloat16* __restrict__ lo, int n4)
{
    int i = blockIdx.x * blockDim.x + threadIdx.x;
    if (i >= n4) return;
    float4 v = ((const float4*)src)[i];
    __nv_bfloat16 h0,h1,h2,h3,l0,l1,l2,l3;
    split_bf16(v.x,h0,l0); split_bf16(v.y,h1,l1);
    split_bf16(v.z,h2,l2); split_bf16(v.w,h3,l3);
    ((__nv_bfloat162*)hi)[i*2+0] = __nv_bfloat162(h0,h1);
    ((__nv_bfloat162*)hi)[i*2+1] = __nv_bfloat162(h2,h3);
    ((__nv_bfloat162*)lo)[i*2+0] = __nv_bfloat162(l0,l1);
    ((__nv_bfloat162*)lo)[i*2+1] = __nv_bfloat162(l2,l3);
}

// ---------------------------------------------------------------------------
// Prep: transpose + split all 4 weights (blockIdx.z selects).
// ---------------------------------------------------------------------------
__global__ void tsplit4_kernel(
    const float* __restrict__ W0, const float* __restrict__ W1,
    const float* __restrict__ W2, const float* __restrict__ W3,
    __nv_bfloat16* __restrict__ T0h, __nv_bfloat16* __restrict__ T0l,
    __nv_bfloat16* __restrict__ T1h, __nv_bfloat16* __restrict__ T1l,
    __nv_bfloat16* __restrict__ T2h, __nv_bfloat16* __restrict__ T2l,
    __nv_bfloat16* __restrict__ T3h, __nv_bfloat16* __restrict__ T3l)
{
    const int z = blockIdx.z;
    const float* W = (z == 0) ? W0 : (z == 1) ? W1 : (z == 2) ? W2 : W3;
    __nv_bfloat16* Th = (z == 0) ? T0h : (z == 1) ? T1h : (z == 2) ? T2h : T3h;
    __nv_bfloat16* Tl = (z == 0) ? T0l : (z == 1) ? T1l : (z == 2) ? T2l : T3l;

    __shared__ float t[32][33];
    const int n0 = blockIdx.x * 32, k0 = blockIdx.y * 32;
    const int tx = threadIdx.x, ty = threadIdx.y;   // (32, 8)
    #pragma unroll
    for (int i = 0; i < 4; i++)
        t[ty + 8*i][tx] = W[(size_t)(k0 + ty + 8*i) * E_ + n0 + tx];
    __syncthreads();
    #pragma unroll
    for (int i = 0; i < 4; i++) {
        const int row = ty + 8*i;
        const float v = t[tx][row];
        __nv_bfloat16 h, l;
        split_bf16(v, h, l);
        Th[(size_t)(n0 + row) * E_ + k0 + tx] = h;
        Tl[(size_t)(n0 + row) * E_ + k0 + tx] = l;
    }
}

// ---------------------------------------------------------------------------
// bf16x3 tensor-core GEMM body, 3-stage cp.async, single barrier/iter,
// XOR-swizzled smem (64B rows) -> 98304 B -> 2 CTAs/SM.
// ---------------------------------------------------------------------------
#define GS_TILE   8192
#define GS_STAGE  (4*GS_TILE)          // 32768 B
#define GS_SMEM   (3*GS_STAGE)         // 98304 B

template<bool REORDER>
__device__ __forceinline__ void gemm_body(
    const __nv_bfloat16* __restrict__ Ah, const __nv_bfloat16* __restrict__ Al,
    const __nv_bfloat16* __restrict__ Th, const __nv_bfloat16* __restrict__ Tl,
    const float* __restrict__ bias, float* __restrict__ C,
    __nv_bfloat16* __restrict__ Ch, __nv_bfloat16* __restrict__ Cl,
    float oscale)
{
    extern __shared__ char sm[];
    const uint32_t smb = smem_u32(sm);

    const int tid  = threadIdx.x;
    const int warp = tid >> 5;
    const int lane = tid & 31;
    const int group = lane >> 2;
    const int tidg  = lane & 3;

    const int bn = blockIdx.x, bm = blockIdx.y;
    const int m0 = bm * 128, n0 = bn * 128;
    const int warp_m = warp & 1;
    const int warp_n = warp >> 1;

    const int lrow = (lane & 7) + ((lane >> 3) & 1) * 8;
    const int lchk = (lane >> 4) & 1;
    const int sel  = (lrow >> 1) & 3;

    auto load_stage = [&](int s, int c) {
        const int kb = c * 32;
        const uint32_t st = smb + s * GS_STAGE;
        #pragma unroll
        for (int i = 0; i < 2; i++) {
            const int ch = tid + i * 256;
            const int row = ch >> 2, q = ch & 3;
            const uint32_t d = st + row * 64 + (((q ^ ((row >> 1) & 3))) << 4);
            const size_t ga = (size_t)(m0 + row) * E_ + kb + q * 8;
            const size_t gb = (size_t)(n0 + row) * E_ + kb + q * 8;
            cp_async16(d,               Ah + ga);
            cp_async16(d + GS_TILE,     Al + ga);
            cp_async16(d + 2*GS_TILE,   Th + gb);
            cp_async16(d + 3*GS_TILE,   Tl + gb);
        }
        cp_commit();
    };

    float acc[4][4][4];
    #pragma unroll
    for (int i = 0; i < 4; i++)
        #pragma unroll
        for (int j = 0; j < 4; j++)
            #pragma unroll
            for (int r = 0; r < 4; r++) acc[i][j][r] = 0.f;

    const int NC = E_ / 32;
    load_stage(0, 0);
    load_stage(1, 1);

    for (int c = 0; c < NC; c++) {
        const int s = c % 3;
        if (c + 1 < NC) cp_wait1(); else cp_wait0();
        __syncthreads();
        if (c + 2 < NC) load_stage((c + 2) % 3, c + 2);

        const uint32_t st = smb + s * GS_STAGE;
        const uint32_t abase = st + (warp_m * 64 + lrow) * 64;
        const uint32_t bbase = st + 2*GS_TILE + (warp_n * 32 + lrow) * 64;

        #pragma unroll
        for (int h2 = 0; h2 < 2; h2++) {
            const uint32_t co = (uint32_t)(((lchk + 2 * h2) ^ sel) << 4);
            uint32_t ah[4][4], al[4][4], bh[2][4], bl[2][4];
            #pragma unroll
            for (int i = 0; i < 4; i++) {
                ldsm_x4(ah[i], abase + i * 16 * 64 + co);
                ldsm_x4(al[i], abase + GS_TILE + i * 16 * 64 + co);
            }
            #pragma unroll
            for (int g = 0; g < 2; g++) {
                ldsm_x4(bh[g], bbase + g * 16 * 64 + co);
                ldsm_x4(bl[g], bbase + GS_TILE + g * 16 * 64 + co);
            }
            #pragma unroll
            for (int i = 0; i < 4; i++)
                #pragma unroll
                for (int j = 0; j < 4; j++)
                    mma_bf16(acc[i][j], ah[i], bh[j>>1][j&1], bh[j>>1][(j&1)+2]);
            #pragma unroll
            for (int i = 0; i < 4; i++)
                #pragma unroll
                for (int j = 0; j < 4; j++)
                    mma_bf16(acc[i][j], ah[i], bl[j>>1][j&1], bl[j>>1][(j&1)+2]);
            #pragma unroll
            for (int i = 0; i < 4; i++)
                #pragma unroll
                for (int j = 0; j < 4; j++)
                    mma_bf16(acc[i][j], al[i], bh[j>>1][j&1], bh[j>>1][(j&1)+2]);
        }
    }

    #pragma unroll
    for (int i = 0; i < 4; i++) {
        const int rmb = m0 + warp_m * 64 + i * 16 + group;
        #pragma unroll
        for (int j = 0; j < 4; j++) {
            const int cb = n0 + warp_n * 32 + j * 8 + tidg * 2;
            const float bx = bias[cb], by = bias[cb + 1];
            #pragma unroll
            for (int half = 0; half < 2; half++) {
                const int m = rmb + half * 8;
                const float vx = (acc[i][j][half * 2 + 0] + bx) * (REORDER ? oscale : 1.f);
                const float vy = (acc[i][j][half * 2 + 1] + by) * (REORDER ? oscale : 1.f);
                if (REORDER) {
                    const int b = m >> 11;
                    const int t = m & (T_ - 1);
                    const int h = cb >> 6;
                    const int d = cb & (HD_ - 1);
                    const size_t o = (((size_t)(b * H_ + h) * T_) + t) * HD_ + d;
                    uint32_t h2, l2;
                    split2(vx, vy, h2, l2);
                    *(uint32_t*)&Ch[o] = h2;
                    *(uint32_t*)&Cl[o] = l2;
                } else {
                    float2 v; v.x = vx; v.y = vy;
                    *(float2*)&C[(size_t)m * E_ + cb] = v;
                }
            }
        }
    }
}

// Fused QKV: blockIdx.z selects weight/bias/output. Q gets QSCALE.
__global__ void __launch_bounds__(256, 2) gemm_qkv(
    const __nv_bfloat16* __restrict__ xh, const __nv_bfloat16* __restrict__ xl,
    const __nv_bfloat16* __restrict__ wqh, const __nv_bfloat16* __restrict__ wql,
    const __nv_bfloat16* __restrict__ wkh, const __nv_bfloat16* __restrict__ wkl,
    const __nv_bfloat16* __restrict__ wvh, const __nv_bfloat16* __restrict__ wvl,
    const float* __restrict__ bq, const float* __restrict__ bk, const float* __restrict__ bv,
    __nv_bfloat16* __restrict__ qh, __nv_bfloat16* __restrict__ ql,
    __nv_bfloat16* __restrict__ kh, __nv_bfloat16* __restrict__ kl,
    __nv_bfloat16* __restrict__ vh, __nv_bfloat16* __restrict__ vl)
{
    const int z = blockIdx.z;
    const __nv_bfloat16* Th = (z == 0) ? wqh : (z == 1) ? wkh : wvh;
    const __nv_bfloat16* Tl = (z == 0) ? wql : (z == 1) ? wkl : wvl;
    const float* bias       = (z == 0) ? bq  : (z == 1) ? bk  : bv;
    __nv_bfloat16* Ch       = (z == 0) ? qh  : (z == 1) ? kh  : vh;
    __nv_bfloat16* Cl       = (z == 0) ? ql  : (z == 1) ? kl  : vl;
    const float oscale      = (z == 0) ? QSCALE : 1.0f;
    gemm_body<true>(xh, xl, Th, Tl, bias, nullptr, Ch, Cl, oscale);
}

__global__ void __launch_bounds__(256, 2) gemm_proj(
    const __nv_bfloat16* __restrict__ yh, const __nv_bfloat16* __restrict__ yl,
    const __nv_bfloat16* __restrict__ wph, const __nv_bfloat16* __restrict__ wpl,
    const float* __restrict__ bp, float* __restrict__ out)
{
    gemm_body<false>(yh, yl, wph, wpl, bp, out, nullptr, nullptr, 1.0f);
}

// ---------------------------------------------------------------------------
// Tensor-core flash attention (causal), bf16x3, log2-domain online softmax.
// Deferred row-sum reduction (per-thread partials, reduced in epilogue),
// rescale skipped when the running max is unchanged, P-split interleaved
// into the PV kc-loop. 3-stage cp.async, single barrier per KV tile.
// ---------------------------------------------------------------------------
#define AT_STRIDE 144
#define AT_TILE   (64*AT_STRIDE)     // 9216
#define AT_STAGE  (4*AT_TILE)        // 36864
#define AT_SMEM   (3*AT_STAGE)       // 110592; x2 = 216 KB <= 228 KB/SM

__global__ void __launch_bounds__(256, 2) attn_tc(
    const __nv_bfloat16* __restrict__ Qh, const __nv_bfloat16* __restrict__ Ql,
    const __nv_bfloat16* __restrict__ Kh, const __nv_bfloat16* __restrict__ Kl,
    const __nv_bfloat16* __restrict__ Vh, const __nv_bfloat16* __restrict__ Vl,
    __nv_bfloat16* __restrict__ Yh, __nv_bfloat16* __restrict__ Yl)
{
    extern __shared__ char sm[];
    const uint32_t smb = smem_u32(sm);

    const int tid  = threadIdx.x;
    const int warp = tid >> 5;
    const int lane = tid & 31;
    const int g    = lane >> 2;
    const int t4   = lane & 3;

    const int qb = (int)gridDim.x - 1 - (int)blockIdx.x;
    const int h  = blockIdx.y;
    const int b  = blockIdx.z;
    const int q0 = qb * 128;

    const size_t base = (size_t)(b * H_ + h) * T_ * HD_;
    const __nv_bfloat16* qh = Qh + base + (size_t)q0 * HD_;
    const __nv_bfloat16* ql = Ql + base + (size_t)q0 * HD_;
    const __nv_bfloat16* kh = Kh + base;
    const __nv_bfloat16* kl = Kl + base;
    const __nv_bfloat16* vh = Vh + base;
    const __nv_bfloat16* vl = Vl + base;

    const int arow = (lane & 7) + ((lane >> 3) & 1) * 8;
    const int achk = (lane >> 4) & 1;
    const int brow = (lane & 7) + ((lane >> 4) & 1) * 8;
    const int bchk = (lane >> 3) & 1;

    #pragma unroll
    for (int i = 0; i < 4; i++) {
        const int ch = tid + i * 256;
        const int row = ch >> 3, q = ch & 7;
        const uint32_t d = smb + (row >> 6) * AT_TILE + (row & 63) * AT_STRIDE + q * 16;
        cp_async16(d,               qh + (size_t)row * HD_ + q * 8);
        cp_async16(d + 2*AT_TILE,   ql + (size_t)row * HD_ + q * 8);
    }
    cp_commit(); cp_wait0();
    __syncthreads();

    uint32_t qfh[4][4], qfl[4][4];
    {
        const int wr = warp * 16;
        const uint32_t qbse = smb + (wr >> 6) * AT_TILE + (wr & 63) * AT_STRIDE
                            + arow * AT_STRIDE + achk * 16;
        #pragma unroll
        for (int kc = 0; kc < 4; kc++) {
            ldsm_x4(qfh[kc], qbse + kc * 32);
            ldsm_x4(qfl[kc], qbse + 2*AT_TILE + kc * 32);
        }
    }
    __syncthreads();

    auto load_stage = [&](int s, int kt) {
        const int kv0 = kt * 64;
        const uint32_t st = smb + s * AT_STAGE;
        #pragma unroll
        for (int i = 0; i < 2; i++) {
            const int ch = tid + i * 256;
            const int row = ch >> 3, q = ch & 7;
            const uint32_t d = st + row * AT_STRIDE + q * 16;
            const size_t go = (size_t)(kv0 + row) * HD_ + q * 8;
            cp_async16(d,               kh + go);
            cp_async16(d + AT_TILE,     kl + go);
            cp_async16(d + 2*AT_TILE,   vh + go);
            cp_async16(d + 3*AT_TILE,   vl + go);
        }
        cp_commit();
    };

    float O[8][4];
    #pragma unroll
    for (int j = 0; j < 8; j++)
        #pragma unroll
        for (int r = 0; r < 4; r++) O[j][r] = 0.f;
    float m0 = -1e30f, m1 = -1e30f;
    float ps0 = 0.f, ps1 = 0.f;   // per-thread running sums in 2^(S-m) domain

    const int nt = 2 * (qb + 1);
    const int R  = q0 + warp * 16;

    load_stage(0, 0);
    if (nt > 1) load_stage(1, 1);

    for (int kt = 0; kt < nt; kt++) {
        const int s = kt % 3;
        const int kv0 = kt * 64;
        if (kt + 1 < nt) cp_wait1(); else cp_wait0();
        __syncthreads();
        if (kt + 2 < nt) load_stage((kt + 2) % 3, kt + 2);

        if (kv0 <= R + 15) {
            const uint32_t st = smb + s * AT_STAGE;

            // ---- S = Q K^T (bf16x3, Q pre-scaled) ----
            float S[8][4];
            #pragma unroll
            for (int j = 0; j < 8; j++)
                #pragma unroll
                for (int r = 0; r < 4; r++) S[j][r] = 0.f;

            #pragma unroll
            for (int kc = 0; kc < 4; kc++) {
                #pragma unroll
                for (int np = 0; np < 4; np++) {
                    uint32_t kfh[4], kfl[4];
                    const uint32_t a = st + (np * 16 + brow) * AT_STRIDE + bchk * 16 + kc * 32;
                    ldsm_x4(kfh, a);
                    ldsm_x4(kfl, a + AT_TILE);
                    const int j0 = 2 * np;
                    mma_bf16(S[j0],     qfh[kc], kfh[0], kfh[1]);
                    mma_bf16(S[j0 + 1], qfh[kc], kfh[2], kfh[3]);
                    mma_bf16(S[j0],     qfh[kc], kfl[0], kfl[1]);
                    mma_bf16(S[j0 + 1], qfh[kc], kfl[2], kfl[3]);
                    mma_bf16(S[j0],     qfl[kc], kfh[0], kfh[1]);
                    mma_bf16(S[j0 + 1], qfl[kc], kfh[2], kfh[3]);
                }
            }

            // ---- causal mask ----
            const int row0 = R + g, row1 = R + g + 8;
            const bool need_mask = (kv0 + 63 > R);
            if (need_mask) {
                #pragma unroll
                for (int j = 0; j < 8; j++) {
                    const int c0 = kv0 + 8 * j + 2 * t4;
                    if (c0     > row0) S[j][0] = -1e30f;
                    if (c0 + 1 > row0) S[j][1] = -1e30f;
                    if (c0     > row1) S[j][2] = -1e30f;
                    if (c0 + 1 > row1) S[j][3] = -1e30f;
                }
            }

            // ---- running max (only these 4 SHFLs remain per tile) ----
            float mx0 = -1e30f, mx1 = -1e30f;
            #pragma unroll
            for (int j = 0; j < 8; j++) {
                mx0 = fmaxf(mx0, fmaxf(S[j][0], S[j][1]));
                mx1 = fmaxf(mx1, fmaxf(S[j][2], S[j][3]));
            }
            mx0 = fmaxf(mx0, __shfl_xor_sync(0xffffffffu, mx0, 1));
            mx0 = fmaxf(mx0, __shfl_xor_sync(0xffffffffu, mx0, 2));
            mx1 = fmaxf(mx1, __shfl_xor_sync(0xffffffffu, mx1, 1));
            mx1 = fmaxf(mx1, __shfl_xor_sync(0xffffffffu, mx1, 2));

            const float nm0 = fmaxf(m0, mx0);
            const float nm1 = fmaxf(m1, mx1);
            if (nm0 != m0 || nm1 != m1) {
                const float cr0 = fast_ex2(m0 - nm0);
                const float cr1 = fast_ex2(m1 - nm1);
                ps0 *= cr0;  ps1 *= cr1;
                #pragma unroll
                for (int j = 0; j < 8; j++) {
                    O[j][0] *= cr0;  O[j][1] *= cr0;
                    O[j][2] *= cr1;  O[j][3] *= cr1;
                }
                m0 = nm0;  m1 = nm1;
            }

            // ---- P = 2^(S - m), per-thread sum accumulation (no shuffles) ----
            #pragma unroll
            for (int j = 0; j < 8; j++) {
                S[j][0] = fast_ex2(S[j][0] - m0);
                S[j][1] = fast_ex2(S[j][1] - m0);
                S[j][2] = fast_ex2(S[j][2] - m1);
                S[j][3] = fast_ex2(S[j][3] - m1);
                ps0 += S[j][0] + S[j][1];
                ps1 += S[j][2] + S[j][3];
            }

            // ---- O += P V (bf16x3), split interleaved per kc ----
            #pragma unroll
            for (int kc = 0; kc < 4; kc++) {
                uint32_t ph[4], pl[4];
                split2(S[2*kc][0],   S[2*kc][1],   ph[0], pl[0]);
                split2(S[2*kc][2],   S[2*kc][3],   ph[1], pl[1]);
                split2(S[2*kc+1][0], S[2*kc+1][1], ph[2], pl[2]);
                split2(S[2*kc+1][2], S[2*kc+1][3], ph[3], pl[3]);
                #pragma unroll
                for (int np = 0; np < 4; np++) {
                    uint32_t vfh[4], vfl[4];
                    const uint32_t a = st + 2*AT_TILE + (kc * 16 + arow) * AT_STRIDE
                                     + np * 32 + achk * 16;
                    ldsm_x4t(vfh, a);
                    ldsm_x4t(vfl, a + AT_TILE);
                    const int j0 = 2 * np;
                    mma_bf16(O[j0],     ph, vfh[0], vfh[1]);
                    mma_bf16(O[j0 + 1], ph, vfh[2], vfh[3]);
                    mma_bf16(O[j0],     pl, vfh[0], vfh[1]);
                    mma_bf16(O[j0 + 1], pl, vfh[2], vfh[3]);
                    mma_bf16(O[j0],     ph, vfl[0], vfl[1]);
                    mma_bf16(O[j0 + 1], ph, vfl[2], vfl[3]);
                }
            }
        }
    }

    // ---- one-time row-sum reduction + epilogue ----
    ps0 += __shfl_xor_sync(0xffffffffu, ps0, 1);
    ps0 += __shfl_xor_sync(0xffffffffu, ps0, 2);
    ps1 += __shfl_xor_sync(0xffffffffu, ps1, 1);
    ps1 += __shfl_xor_sync(0xffffffffu, ps1, 2);
    const float inv0 = 1.0f / ps0;
    const float inv1 = 1.0f / ps1;

    const int row0 = q0 + warp * 16 + g;
    const int row1 = row0 + 8;
    #pragma unroll
    for (int j = 0; j < 8; j++) {
        const int col = h * HD_ + 8 * j + 2 * t4;
        const size_t o0 = (size_t)(b * T_ + row0) * E_ + col;
        const size_t o1 = (size_t)(b * T_ + row1) * E_ + col;
        uint32_t h2, l2;
        split2(O[j][0] * inv0, O[j][1] * inv0, h2, l2);
        *(uint32_t*)&Yh[o0] = h2;
        *(uint32_t*)&Yl[o0] = l2;
        split2(O[j][2] * inv1, O[j][3] * inv1, h2, l2);
        *(uint32_t*)&Yh[o1] = h2;
        *(uint32_t*)&Yl[o1] = l2;
    }
}

// ---------------------------------------------------------------------------
extern "C" void kernel_launch(void* const* d_in, const int* in_sizes, int n_in,
                              void* d_out, int out_size)
{
    const float* x  = (const float*)d_in[0];
    const float* Wq = (const float*)d_in[2];
    const float* bq = (const float*)d_in[3];
    const float* Wk = (const float*)d_in[4];
    const float* bk = (const float*)d_in[5];
    const float* Wv = (const float*)d_in[6];
    const float* bv = (const float*)d_in[7];
    const float* Wp = (const float*)d_in[8];
    const float* bp = (const float*)d_in[9];
    float* out = (float*)d_out;

    __nv_bfloat16 *xh, *xl, *yh, *yl, *qh, *ql, *kh, *kl, *vh, *vl;
    __nv_bfloat16 *wqh, *wql, *wkh, *wkl, *wvh, *wvl, *wph, *wpl;
    cudaGetSymbolAddress((void**)&xh, g_xh);  cudaGetSymbolAddress((void**)&xl, g_xl);
    cudaGetSymbolAddress((void**)&yh, g_yh);  cudaGetSymbolAddress((void**)&yl, g_yl);
    cudaGetSymbolAddress((void**)&qh, g_qh);  cudaGetSymbolAddress((void**)&ql, g_ql);
    cudaGetSymbolAddress((void**)&kh, g_kh);  cudaGetSymbolAddress((void**)&kl, g_kl);
    cudaGetSymbolAddress((void**)&vh, g_vh);  cudaGetSymbolAddress((void**)&vl, g_vl);
    cudaGetSymbolAddress((void**)&wqh, g_wqh);  cudaGetSymbolAddress((void**)&wql, g_wql);
    cudaGetSymbolAddress((void**)&wkh, g_wkh);  cudaGetSymbolAddress((void**)&wkl, g_wkl);
    cudaGetSymbolAddress((void**)&wvh, g_wvh);  cudaGetSymbolAddress((void**)&wvl, g_wvl);
    cudaGetSymbolAddress((void**)&wph, g_wph);  cudaGetSymbolAddress((void**)&wpl, g_wpl);

    cudaFuncSetAttribute(gemm_qkv,  cudaFuncAttributeMaxDynamicSharedMemorySize, GS_SMEM);
    cudaFuncSetAttribute(gemm_proj, cudaFuncAttributeMaxDynamicSharedMemorySize, GS_SMEM);
    cudaFuncSetAttribute(attn_tc,   cudaFuncAttributeMaxDynamicSharedMemorySize, AT_SMEM);

    // Prep: split x, transpose+split all weights (one launch)
    split_kernel<<<(M_*E_/4 + 255)/256, 256>>>(x, xh, xl, M_*E_/4);
    dim3 tgrid(E_/32, E_/32, 4), tblk(32, 8);
    tsplit4_kernel<<<tgrid, tblk>>>(Wq, Wk, Wv, Wp,
                                    wqh, wql, wkh, wkl, wvh, wvl, wph, wpl);

    // Fused QKV projections
    dim3 qkv_grid(E_ / 128, M_ / 128, 3);   // (8, 64, 3)
    gemm_qkv<<<qkv_grid, 256, GS_SMEM>>>(xh, xl,
                                         wqh, wql, wkh, wkl, wvh, wvl,
                                         bq, bk, bv,
                                         qh, ql, kh, kl, vh, vl);

    dim3 attn_grid(T_ / 128, H_, B_);       // (16, 16, 4)
    attn_tc<<<attn_grid, 256, AT_SMEM>>>(qh, ql, kh, kl, vh, vl, yh, yl);

    dim3 proj_grid(E_ / 128, M_ / 128);     // (8, 64)
    gemm_proj<<<proj_grid, 256, GS_SMEM>>>(yh, yl, wph, wpl, bp, out);
}

// round 14
// speedup vs baseline: 2.1273x; 1.0508x over previous
#include <cuda_runtime.h>
#include <cuda_bf16.h>
#include <cuda_fp16.h>
#include <stdint.h>
#include <math.h>

#define B_  4
#define T_  2048
#define E_  1024
#define H_  16
#define HD_ 64
#define M_  (B_*T_)   // 8192

// q pre-scale: 0.125 (1/sqrt(hd)) * log2(e)  -> softmax via ex2
#define QSCALE 0.180336880f

// Scratch (device globals: allocation-free). g_vh/g_vl hold fp16 (bytes).
__device__ __nv_bfloat16 g_xh[M_*E_], g_xl[M_*E_];
__device__ __nv_bfloat16 g_yh[M_*E_], g_yl[M_*E_];
__device__ __nv_bfloat16 g_qh[M_*E_], g_ql[M_*E_];
__device__ __nv_bfloat16 g_kh[M_*E_], g_kl[M_*E_];
__device__ __nv_bfloat16 g_vh[M_*E_], g_vl[M_*E_];
__device__ __nv_bfloat16 g_wqh[E_*E_], g_wql[E_*E_];
__device__ __nv_bfloat16 g_wkh[E_*E_], g_wkl[E_*E_];
__device__ __nv_bfloat16 g_wvh[E_*E_], g_wvl[E_*E_];
__device__ __nv_bfloat16 g_wph[E_*E_], g_wpl[E_*E_];

// ---------------------------------------------------------------------------
// helpers
// ---------------------------------------------------------------------------
__device__ __forceinline__ uint32_t smem_u32(const void* p) {
    return (uint32_t)__cvta_generic_to_shared(p);
}
__device__ __forceinline__ void cp_async16(uint32_t dst, const void* src) {
    asm volatile("cp.async.cg.shared.global [%0], [%1], 16;\n" :: "r"(dst), "l"(src));
}
__device__ __forceinline__ void cp_commit() { asm volatile("cp.async.commit_group;\n"); }
__device__ __forceinline__ void cp_wait0() { asm volatile("cp.async.wait_group 0;\n"); }
__device__ __forceinline__ void cp_wait1() { asm volatile("cp.async.wait_group 1;\n"); }

__device__ __forceinline__ void mma_bf16(float c[4], const uint32_t a[4], uint32_t b0, uint32_t b1) {
    asm volatile(
        "mma.sync.aligned.m16n8k16.row.col.f32.bf16.bf16.f32 "
        "{%0,%1,%2,%3}, {%4,%5,%6,%7}, {%8,%9}, {%0,%1,%2,%3};\n"
        : "+f"(c[0]), "+f"(c[1]), "+f"(c[2]), "+f"(c[3])
        : "r"(a[0]), "r"(a[1]), "r"(a[2]), "r"(a[3]), "r"(b0), "r"(b1));
}
__device__ __forceinline__ void mma_f16(float c[4], const uint32_t a[4], uint32_t b0, uint32_t b1) {
    asm volatile(
        "mma.sync.aligned.m16n8k16.row.col.f32.f16.f16.f32 "
        "{%0,%1,%2,%3}, {%4,%5,%6,%7}, {%8,%9}, {%0,%1,%2,%3};\n"
        : "+f"(c[0]), "+f"(c[1]), "+f"(c[2]), "+f"(c[3])
        : "r"(a[0]), "r"(a[1]), "r"(a[2]), "r"(a[3]), "r"(b0), "r"(b1));
}
__device__ __forceinline__ void ldsm_x4(uint32_t r[4], uint32_t addr) {
    asm volatile("ldmatrix.sync.aligned.m8n8.x4.shared.b16 {%0,%1,%2,%3}, [%4];"
        : "=r"(r[0]), "=r"(r[1]), "=r"(r[2]), "=r"(r[3]) : "r"(addr));
}
__device__ __forceinline__ void ldsm_x4t(uint32_t r[4], uint32_t addr) {
    asm volatile("ldmatrix.sync.aligned.m8n8.x4.trans.shared.b16 {%0,%1,%2,%3}, [%4];"
        : "=r"(r[0]), "=r"(r[1]), "=r"(r[2]), "=r"(r[3]) : "r"(addr));
}
__device__ __forceinline__ void split_bf16(float v, __nv_bfloat16& h, __nv_bfloat16& l) {
    h = __float2bfloat16(v);
    l = __float2bfloat16(v - __bfloat162float(h));
}
// Packed bf16 split: (a,b) -> hi pair (a low half) + lo pair.
__device__ __forceinline__ void split2(float a, float b, uint32_t& h2, uint32_t& l2) {
    uint32_t h;
    asm("cvt.rn.bf16x2.f32 %0, %1, %2;" : "=r"(h) : "f"(b), "f"(a));
    const float ha = __uint_as_float(h << 16);
    const float hb = __uint_as_float(h & 0xffff0000u);
    asm("cvt.rn.bf16x2.f32 %0, %1, %2;" : "=r"(l2) : "f"(b - hb), "f"(a - ha));
    h2 = h;
}
// Packed fp16 split: (a,b) -> hi fp16 pair (a low half) + lo fp16 pair.
__device__ __forceinline__ void split2h(float a, float b, uint32_t& h2, uint32_t& l2) {
    uint32_t h;
    asm("cvt.rn.f16x2.f32 %0, %1, %2;" : "=r"(h) : "f"(b), "f"(a));
    const __half2 hp = *(__half2*)&h;
    const float ha = __half2float(__low2half(hp));
    const float hb = __half2float(__high2half(hp));
    asm("cvt.rn.f16x2.f32 %0, %1, %2;" : "=r"(l2) : "f"(b - hb), "f"(a - ha));
    h2 = h;
}
__device__ __forceinline__ uint32_t pack_f16x2(float a, float b) {
    uint32_t r;
    asm("cvt.rn.f16x2.f32 %0, %1, %2;" : "=r"(r) : "f"(b), "f"(a));
    return r;
}
__device__ __forceinline__ float fast_ex2(float x) {
    float y;
    asm("ex2.approx.ftz.f32 %0, %1;" : "=f"(y) : "f"(x));
    return y;
}

// ---------------------------------------------------------------------------
// Prep: split fp32 -> bf16 hi/lo, same layout.
// ---------------------------------------------------------------------------
__global__ void split_kernel(const float* __restrict__ src,
                             __nv_bfloat16* __restrict__ hi,
                             __nv_bfloat16* __restrict__ lo, int n4)
{
    int i = blockIdx.x * blockDim.x + threadIdx.x;
    if (i >= n4) return;
    float4 v = ((const float4*)src)[i];
    __nv_bfloat16 h0,h1,h2,h3,l0,l1,l2,l3;
    split_bf16(v.x,h0,l0); split_bf16(v.y,h1,l1);
    split_bf16(v.z,h2,l2); split_bf16(v.w,h3,l3);
    ((__nv_bfloat162*)hi)[i*2+0] = __nv_bfloat162(h0,h1);
    ((__nv_bfloat162*)hi)[i*2+1] = __nv_bfloat162(h2,h3);
    ((__nv_bfloat162*)lo)[i*2+0] = __nv_bfloat162(l0,l1);
    ((__nv_bfloat162*)lo)[i*2+1] = __nv_bfloat162(l2,l3);
}

// ---------------------------------------------------------------------------
// Prep: transpose + split all 4 weights (blockIdx.z selects).
// ---------------------------------------------------------------------------
__global__ void tsplit4_kernel(
    const float* __restrict__ W0, const float* __restrict__ W1,
    const float* __restrict__ W2, const float* __restrict__ W3,
    __nv_bfloat16* __restrict__ T0h, __nv_bfloat16* __restrict__ T0l,
    __nv_bfloat16* __restrict__ T1h, __nv_bfloat16* __restrict__ T1l,
    __nv_bfloat16* __restrict__ T2h, __nv_bfloat16* __restrict__ T2l,
    __nv_bfloat16* __restrict__ T3h, __nv_bfloat16* __restrict__ T3l)
{
    const int z = blockIdx.z;
    const float* W = (z == 0) ? W0 : (z == 1) ? W1 : (z == 2) ? W2 : W3;
    __nv_bfloat16* Th = (z == 0) ? T0h : (z == 1) ? T1h : (z == 2) ? T2h : T3h;
    __nv_bfloat16* Tl = (z == 0) ? T0l : (z == 1) ? T1l : (z == 2) ? T2l : T3l;

    __shared__ float t[32][33];
    const int n0 = blockIdx.x * 32, k0 = blockIdx.y * 32;
    const int tx = threadIdx.x, ty = threadIdx.y;   // (32, 8)
    #pragma unroll
    for (int i = 0; i < 4; i++)
        t[ty + 8*i][tx] = W[(size_t)(k0 + ty + 8*i) * E_ + n0 + tx];
    __syncthreads();
    #pragma unroll
    for (int i = 0; i < 4; i++) {
        const int row = ty + 8*i;
        const float v = t[tx][row];
        __nv_bfloat16 h, l;
        split_bf16(v, h, l);
        Th[(size_t)(n0 + row) * E_ + k0 + tx] = h;
        Tl[(size_t)(n0 + row) * E_ + k0 + tx] = l;
    }
}

// ---------------------------------------------------------------------------
// bf16x3 tensor-core GEMM body, 3-stage cp.async, single barrier/iter,
// XOR-swizzled smem -> 2 CTAs/SM. FP16OUT selects fp16 hi/lo epilogue (V).
// ---------------------------------------------------------------------------
#define GS_TILE   8192
#define GS_STAGE  (4*GS_TILE)          // 32768 B
#define GS_SMEM   (3*GS_STAGE)         // 98304 B

template<bool REORDER, bool FP16OUT>
__device__ __forceinline__ void gemm_body(
    const __nv_bfloat16* __restrict__ Ah, const __nv_bfloat16* __restrict__ Al,
    const __nv_bfloat16* __restrict__ Th, const __nv_bfloat16* __restrict__ Tl,
    const float* __restrict__ bias, float* __restrict__ C,
    __nv_bfloat16* __restrict__ Ch, __nv_bfloat16* __restrict__ Cl,
    float oscale)
{
    extern __shared__ char sm[];
    const uint32_t smb = smem_u32(sm);

    const int tid  = threadIdx.x;
    const int warp = tid >> 5;
    const int lane = tid & 31;
    const int group = lane >> 2;
    const int tidg  = lane & 3;

    const int bn = blockIdx.x, bm = blockIdx.y;
    const int m0 = bm * 128, n0 = bn * 128;
    const int warp_m = warp & 1;
    const int warp_n = warp >> 1;

    const int lrow = (lane & 7) + ((lane >> 3) & 1) * 8;
    const int lchk = (lane >> 4) & 1;
    const int sel  = (lrow >> 1) & 3;

    auto load_stage = [&](int s, int c) {
        const int kb = c * 32;
        const uint32_t st = smb + s * GS_STAGE;
        #pragma unroll
        for (int i = 0; i < 2; i++) {
            const int ch = tid + i * 256;
            const int row = ch >> 2, q = ch & 3;
            const uint32_t d = st + row * 64 + (((q ^ ((row >> 1) & 3))) << 4);
            const size_t ga = (size_t)(m0 + row) * E_ + kb + q * 8;
            const size_t gb = (size_t)(n0 + row) * E_ + kb + q * 8;
            cp_async16(d,               Ah + ga);
            cp_async16(d + GS_TILE,     Al + ga);
            cp_async16(d + 2*GS_TILE,   Th + gb);
            cp_async16(d + 3*GS_TILE,   Tl + gb);
        }
        cp_commit();
    };

    float acc[4][4][4];
    #pragma unroll
    for (int i = 0; i < 4; i++)
        #pragma unroll
        for (int j = 0; j < 4; j++)
            #pragma unroll
            for (int r = 0; r < 4; r++) acc[i][j][r] = 0.f;

    const int NC = E_ / 32;
    load_stage(0, 0);
    load_stage(1, 1);

    for (int c = 0; c < NC; c++) {
        const int s = c % 3;
        if (c + 1 < NC) cp_wait1(); else cp_wait0();
        __syncthreads();
        if (c + 2 < NC) load_stage((c + 2) % 3, c + 2);

        const uint32_t st = smb + s * GS_STAGE;
        const uint32_t abase = st + (warp_m * 64 + lrow) * 64;
        const uint32_t bbase = st + 2*GS_TILE + (warp_n * 32 + lrow) * 64;

        #pragma unroll
        for (int h2 = 0; h2 < 2; h2++) {
            const uint32_t co = (uint32_t)(((lchk + 2 * h2) ^ sel) << 4);
            uint32_t ah[4][4], al[4][4], bh[2][4], bl[2][4];
            #pragma unroll
            for (int i = 0; i < 4; i++) {
                ldsm_x4(ah[i], abase + i * 16 * 64 + co);
                ldsm_x4(al[i], abase + GS_TILE + i * 16 * 64 + co);
            }
            #pragma unroll
            for (int g = 0; g < 2; g++) {
                ldsm_x4(bh[g], bbase + g * 16 * 64 + co);
                ldsm_x4(bl[g], bbase + GS_TILE + g * 16 * 64 + co);
            }
            #pragma unroll
            for (int i = 0; i < 4; i++)
                #pragma unroll
                for (int j = 0; j < 4; j++)
                    mma_bf16(acc[i][j], ah[i], bh[j>>1][j&1], bh[j>>1][(j&1)+2]);
            #pragma unroll
            for (int i = 0; i < 4; i++)
                #pragma unroll
                for (int j = 0; j < 4; j++)
                    mma_bf16(acc[i][j], ah[i], bl[j>>1][j&1], bl[j>>1][(j&1)+2]);
            #pragma unroll
            for (int i = 0; i < 4; i++)
                #pragma unroll
                for (int j = 0; j < 4; j++)
                    mma_bf16(acc[i][j], al[i], bh[j>>1][j&1], bh[j>>1][(j&1)+2]);
        }
    }

    #pragma unroll
    for (int i = 0; i < 4; i++) {
        const int rmb = m0 + warp_m * 64 + i * 16 + group;
        #pragma unroll
        for (int j = 0; j < 4; j++) {
            const int cb = n0 + warp_n * 32 + j * 8 + tidg * 2;
            const float bx = bias[cb], by = bias[cb + 1];
            #pragma unroll
            for (int half = 0; half < 2; half++) {
                const int m = rmb + half * 8;
                const float vx = (acc[i][j][half * 2 + 0] + bx) * (REORDER ? oscale : 1.f);
                const float vy = (acc[i][j][half * 2 + 1] + by) * (REORDER ? oscale : 1.f);
                if (REORDER) {
                    const int b = m >> 11;
                    const int t = m & (T_ - 1);
                    const int h = cb >> 6;
                    const int d = cb & (HD_ - 1);
                    const size_t o = (((size_t)(b * H_ + h) * T_) + t) * HD_ + d;
                    uint32_t h2, l2;
                    if (FP16OUT) split2h(vx, vy, h2, l2);
                    else         split2(vx, vy, h2, l2);
                    *(uint32_t*)&Ch[o] = h2;
                    *(uint32_t*)&Cl[o] = l2;
                } else {
                    float2 v; v.x = vx; v.y = vy;
                    *(float2*)&C[(size_t)m * E_ + cb] = v;
                }
            }
        }
    }
}

// Fused QKV: blockIdx.z selects weight/bias/output. Q gets QSCALE; V is fp16.
__global__ void __launch_bounds__(256, 2) gemm_qkv(
    const __nv_bfloat16* __restrict__ xh, const __nv_bfloat16* __restrict__ xl,
    const __nv_bfloat16* __restrict__ wqh, const __nv_bfloat16* __restrict__ wql,
    const __nv_bfloat16* __restrict__ wkh, const __nv_bfloat16* __restrict__ wkl,
    const __nv_bfloat16* __restrict__ wvh, const __nv_bfloat16* __restrict__ wvl,
    const float* __restrict__ bq, const float* __restrict__ bk, const float* __restrict__ bv,
    __nv_bfloat16* __restrict__ qh, __nv_bfloat16* __restrict__ ql,
    __nv_bfloat16* __restrict__ kh, __nv_bfloat16* __restrict__ kl,
    __nv_bfloat16* __restrict__ vh, __nv_bfloat16* __restrict__ vl)
{
    const int z = blockIdx.z;
    if (z == 2) {
        gemm_body<true, true>(xh, xl, wvh, wvl, bv, nullptr, vh, vl, 1.0f);
    } else {
        const __nv_bfloat16* Th = (z == 0) ? wqh : wkh;
        const __nv_bfloat16* Tl = (z == 0) ? wql : wkl;
        const float* bias       = (z == 0) ? bq  : bk;
        __nv_bfloat16* Ch       = (z == 0) ? qh  : kh;
        __nv_bfloat16* Cl       = (z == 0) ? ql  : kl;
        const float oscale      = (z == 0) ? QSCALE : 1.0f;
        gemm_body<true, false>(xh, xl, Th, Tl, bias, nullptr, Ch, Cl, oscale);
    }
}

__global__ void __launch_bounds__(256, 2) gemm_proj(
    const __nv_bfloat16* __restrict__ yh, const __nv_bfloat16* __restrict__ yl,
    const __nv_bfloat16* __restrict__ wph, const __nv_bfloat16* __restrict__ wpl,
    const float* __restrict__ bp, float* __restrict__ out)
{
    gemm_body<false, false>(yh, yl, wph, wpl, bp, out, nullptr, nullptr, 1.0f);
}

// ---------------------------------------------------------------------------
// Tensor-core flash attention (causal). QK: bf16x3. PV: fp16, P single +
// V hi/lo (2 products). Log2-domain online softmax, deferred row-sum,
// rescale skip. 3-stage cp.async, single barrier per KV tile.
// ---------------------------------------------------------------------------
#define AT_STRIDE 144
#define AT_TILE   (64*AT_STRIDE)     // 9216
#define AT_STAGE  (4*AT_TILE)        // 36864
#define AT_SMEM   (3*AT_STAGE)       // 110592; x2 = 216 KB <= 228 KB/SM

__global__ void __launch_bounds__(256, 2) attn_tc(
    const __nv_bfloat16* __restrict__ Qh, const __nv_bfloat16* __restrict__ Ql,
    const __nv_bfloat16* __restrict__ Kh, const __nv_bfloat16* __restrict__ Kl,
    const __nv_bfloat16* __restrict__ Vh, const __nv_bfloat16* __restrict__ Vl,
    __nv_bfloat16* __restrict__ Yh, __nv_bfloat16* __restrict__ Yl)
{
    extern __shared__ char sm[];
    const uint32_t smb = smem_u32(sm);

    const int tid  = threadIdx.x;
    const int warp = tid >> 5;
    const int lane = tid & 31;
    const int g    = lane >> 2;
    const int t4   = lane & 3;

    const int qb = (int)gridDim.x - 1 - (int)blockIdx.x;
    const int h  = blockIdx.y;
    const int b  = blockIdx.z;
    const int q0 = qb * 128;

    const size_t base = (size_t)(b * H_ + h) * T_ * HD_;
    const __nv_bfloat16* qh = Qh + base + (size_t)q0 * HD_;
    const __nv_bfloat16* ql = Ql + base + (size_t)q0 * HD_;
    const __nv_bfloat16* kh = Kh + base;
    const __nv_bfloat16* kl = Kl + base;
    const __nv_bfloat16* vh = Vh + base;   // fp16 payload (bytes)
    const __nv_bfloat16* vl = Vl + base;   // fp16 payload (bytes)

    const int arow = (lane & 7) + ((lane >> 3) & 1) * 8;
    const int achk = (lane >> 4) & 1;
    const int brow = (lane & 7) + ((lane >> 4) & 1) * 8;
    const int bchk = (lane >> 3) & 1;

    #pragma unroll
    for (int i = 0; i < 4; i++) {
        const int ch = tid + i * 256;
        const int row = ch >> 3, q = ch & 7;
        const uint32_t d = smb + (row >> 6) * AT_TILE + (row & 63) * AT_STRIDE + q * 16;
        cp_async16(d,               qh + (size_t)row * HD_ + q * 8);
        cp_async16(d + 2*AT_TILE,   ql + (size_t)row * HD_ + q * 8);
    }
    cp_commit(); cp_wait0();
    __syncthreads();

    uint32_t qfh[4][4], qfl[4][4];
    {
        const int wr = warp * 16;
        const uint32_t qbse = smb + (wr >> 6) * AT_TILE + (wr & 63) * AT_STRIDE
                            + arow * AT_STRIDE + achk * 16;
        #pragma unroll
        for (int kc = 0; kc < 4; kc++) {
            ldsm_x4(qfh[kc], qbse + kc * 32);
            ldsm_x4(qfl[kc], qbse + 2*AT_TILE + kc * 32);
        }
    }
    __syncthreads();

    auto load_stage = [&](int s, int kt) {
        const int kv0 = kt * 64;
        const uint32_t st = smb + s * AT_STAGE;
        #pragma unroll
        for (int i = 0; i < 2; i++) {
            const int ch = tid + i * 256;
            const int row = ch >> 3, q = ch & 7;
            const uint32_t d = st + row * AT_STRIDE + q * 16;
            const size_t go = (size_t)(kv0 + row) * HD_ + q * 8;
            cp_async16(d,               kh + go);
            cp_async16(d + AT_TILE,     kl + go);
            cp_async16(d + 2*AT_TILE,   vh + go);
            cp_async16(d + 3*AT_TILE,   vl + go);
        }
        cp_commit();
    };

    float O[8][4];
    #pragma unroll
    for (int j = 0; j < 8; j++)
        #pragma unroll
        for (int r = 0; r < 4; r++) O[j][r] = 0.f;
    float m0 = -1e30f, m1 = -1e30f;
    float ps0 = 0.f, ps1 = 0.f;

    const int nt = 2 * (qb + 1);
    const int R  = q0 + warp * 16;

    load_stage(0, 0);
    if (nt > 1) load_stage(1, 1);

    for (int kt = 0; kt < nt; kt++) {
        const int s = kt % 3;
        const int kv0 = kt * 64;
        if (kt + 1 < nt) cp_wait1(); else cp_wait0();
        __syncthreads();
        if (kt + 2 < nt) load_stage((kt + 2) % 3, kt + 2);

        if (kv0 <= R + 15) {
            const uint32_t st = smb + s * AT_STAGE;

            // ---- S = Q K^T (bf16x3, Q pre-scaled) ----
            float S[8][4];
            #pragma unroll
            for (int j = 0; j < 8; j++)
                #pragma unroll
                for (int r = 0; r < 4; r++) S[j][r] = 0.f;

            #pragma unroll
            for (int kc = 0; kc < 4; kc++) {
                #pragma unroll
                for (int np = 0; np < 4; np++) {
                    uint32_t kfh[4], kfl[4];
                    const uint32_t a = st + (np * 16 + brow) * AT_STRIDE + bchk * 16 + kc * 32;
                    ldsm_x4(kfh, a);
                    ldsm_x4(kfl, a + AT_TILE);
                    const int j0 = 2 * np;
                    mma_bf16(S[j0],     qfh[kc], kfh[0], kfh[1]);
                    mma_bf16(S[j0 + 1], qfh[kc], kfh[2], kfh[3]);
                    mma_bf16(S[j0],     qfh[kc], kfl[0], kfl[1]);
                    mma_bf16(S[j0 + 1], qfh[kc], kfl[2], kfl[3]);
                    mma_bf16(S[j0],     qfl[kc], kfh[0], kfh[1]);
                    mma_bf16(S[j0 + 1], qfl[kc], kfh[2], kfh[3]);
                }
            }

            // ---- causal mask ----
            const int row0 = R + g, row1 = R + g + 8;
            const bool need_mask = (kv0 + 63 > R);
            if (need_mask) {
                #pragma unroll
                for (int j = 0; j < 8; j++) {
                    const int c0 = kv0 + 8 * j + 2 * t4;
                    if (c0     > row0) S[j][0] = -1e30f;
                    if (c0 + 1 > row0) S[j][1] = -1e30f;
                    if (c0     > row1) S[j][2] = -1e30f;
                    if (c0 + 1 > row1) S[j][3] = -1e30f;
                }
            }

            // ---- running max ----
            float mx0 = -1e30f, mx1 = -1e30f;
            #pragma unroll
            for (int j = 0; j < 8; j++) {
                mx0 = fmaxf(mx0, fmaxf(S[j][0], S[j][1]));
                mx1 = fmaxf(mx1, fmaxf(S[j][2], S[j][3]));
            }
            mx0 = fmaxf(mx0, __shfl_xor_sync(0xffffffffu, mx0, 1));
            mx0 = fmaxf(mx0, __shfl_xor_sync(0xffffffffu, mx0, 2));
            mx1 = fmaxf(mx1, __shfl_xor_sync(0xffffffffu, mx1, 1));
            mx1 = fmaxf(mx1, __shfl_xor_sync(0xffffffffu, mx1, 2));

            const float nm0 = fmaxf(m0, mx0);
            const float nm1 = fmaxf(m1, mx1);
            if (nm0 != m0 || nm1 != m1) {
                const float cr0 = fast_ex2(m0 - nm0);
                const float cr1 = fast_ex2(m1 - nm1);
                ps0 *= cr0;  ps1 *= cr1;
                #pragma unroll
                for (int j = 0; j < 8; j++) {
                    O[j][0] *= cr0;  O[j][1] *= cr0;
                    O[j][2] *= cr1;  O[j][3] *= cr1;
                }
                m0 = nm0;  m1 = nm1;
            }

            // ---- P = 2^(S - m), per-thread sum accumulation ----
            #pragma unroll
            for (int j = 0; j < 8; j++) {
                S[j][0] = fast_ex2(S[j][0] - m0);
                S[j][1] = fast_ex2(S[j][1] - m0);
                S[j][2] = fast_ex2(S[j][2] - m1);
                S[j][3] = fast_ex2(S[j][3] - m1);
                ps0 += S[j][0] + S[j][1];
                ps1 += S[j][2] + S[j][3];
            }

            // ---- O += P V (fp16: P single + V hi/lo, 2 products) ----
            #pragma unroll
            for (int kc = 0; kc < 4; kc++) {
                uint32_t ph[4];
                ph[0] = pack_f16x2(S[2*kc][0],   S[2*kc][1]);
                ph[1] = pack_f16x2(S[2*kc][2],   S[2*kc][3]);
                ph[2] = pack_f16x2(S[2*kc+1][0], S[2*kc+1][1]);
                ph[3] = pack_f16x2(S[2*kc+1][2], S[2*kc+1][3]);
                #pragma unroll
                for (int np = 0; np < 4; np++) {
                    uint32_t vfh[4], vfl[4];
                    const uint32_t a = st + 2*AT_TILE + (kc * 16 + arow) * AT_STRIDE
                                     + np * 32 + achk * 16;
                    ldsm_x4t(vfh, a);
                    ldsm_x4t(vfl, a + AT_TILE);
                    const int j0 = 2 * np;
                    mma_f16(O[j0],     ph, vfh[0], vfh[1]);
                    mma_f16(O[j0 + 1], ph, vfh[2], vfh[3]);
                    mma_f16(O[j0],     ph, vfl[0], vfl[1]);
                    mma_f16(O[j0 + 1], ph, vfl[2], vfl[3]);
                }
            }
        }
    }

    // ---- one-time row-sum reduction + epilogue ----
    ps0 += __shfl_xor_sync(0xffffffffu, ps0, 1);
    ps0 += __shfl_xor_sync(0xffffffffu, ps0, 2);
    ps1 += __shfl_xor_sync(0xffffffffu, ps1, 1);
    ps1 += __shfl_xor_sync(0xffffffffu, ps1, 2);
    const float inv0 = 1.0f / ps0;
    const float inv1 = 1.0f / ps1;

    const int row0 = q0 + warp * 16 + g;
    const int row1 = row0 + 8;
    #pragma unroll
    for (int j = 0; j < 8; j++) {
        const int col = h * HD_ + 8 * j + 2 * t4;
        const size_t o0 = (size_t)(b * T_ + row0) * E_ + col;
        const size_t o1 = (size_t)(b * T_ + row1) * E_ + col;
        uint32_t h2, l2;
        split2(O[j][0] * inv0, O[j][1] * inv0, h2, l2);
        *(uint32_t*)&Yh[o0] = h2;
        *(uint32_t*)&Yl[o0] = l2;
        split2(O[j][2] * inv1, O[j][3] * inv1, h2, l2);
        *(uint32_t*)&Yh[o1] = h2;
        *(uint32_t*)&Yl[o1] = l2;
    }
}

// ---------------------------------------------------------------------------
extern "C" void kernel_launch(void* const* d_in, const int* in_sizes, int n_in,
                              void* d_out, int out_size)
{
    const float* x  = (const float*)d_in[0];
    const float* Wq = (const float*)d_in[2];
    const float* bq = (const float*)d_in[3];
    const float* Wk = (const float*)d_in[4];
    const float* bk = (const float*)d_in[5];
    const float* Wv = (const float*)d_in[6];
    const float* bv = (const float*)d_in[7];
    const float* Wp = (const float*)d_in[8];
    const float* bp = (const float*)d_in[9];
    float* out = (float*)d_out;

    __nv_bfloat16 *xh, *xl, *yh, *yl, *qh, *ql, *kh, *kl, *vh, *vl;
    __nv_bfloat16 *wqh, *wql, *wkh, *wkl, *wvh, *wvl, *wph, *wpl;
    cudaGetSymbolAddress((void**)&xh, g_xh);  cudaGetSymbolAddress((void**)&xl, g_xl);
    cudaGetSymbolAddress((void**)&yh, g_yh);  cudaGetSymbolAddress((void**)&yl, g_yl);
    cudaGetSymbolAddress((void**)&qh, g_qh);  cudaGetSymbolAddress((void**)&ql, g_ql);
    cudaGetSymbolAddress((void**)&kh, g_kh);  cudaGetSymbolAddress((void**)&kl, g_kl);
    cudaGetSymbolAddress((void**)&vh, g_vh);  cudaGetSymbolAddress((void**)&vl, g_vl);
    cudaGetSymbolAddress((void**)&wqh, g_wqh);  cudaGetSymbolAddress((void**)&wql, g_wql);
    cudaGetSymbolAddress((void**)&wkh, g_wkh);  cudaGetSymbolAddress((void**)&wkl, g_wkl);
    cudaGetSymbolAddress((void**)&wvh, g_wvh);  cudaGetSymbolAddress((void**)&wvl, g_wvl);
    cudaGetSymbolAddress((void**)&wph, g_wph);  cudaGetSymbolAddress((void**)&wpl, g_wpl);

    cudaFuncSetAttribute(gemm_qkv,  cudaFuncAttributeMaxDynamicSharedMemorySize, GS_SMEM);
    cudaFuncSetAttribute(gemm_proj, cudaFuncAttributeMaxDynamicSharedMemorySize, GS_SMEM);
    cudaFuncSetAttribute(attn_tc,   cudaFuncAttributeMaxDynamicSharedMemorySize, AT_SMEM);

    // Prep: split x, transpose+split all weights (one launch)
    split_kernel<<<(M_*E_/4 + 255)/256, 256>>>(x, xh, xl, M_*E_/4);
    dim3 tgrid(E_/32, E_/32, 4), tblk(32, 8);
    tsplit4_kernel<<<tgrid, tblk>>>(Wq, Wk, Wv, Wp,
                                    wqh, wql, wkh, wkl, wvh, wvl, wph, wpl);

    // Fused QKV projections
    dim3 qkv_grid(E_ / 128, M_ / 128, 3);   // (8, 64, 3)
    gemm_qkv<<<qkv_grid, 256, GS_SMEM>>>(xh, xl,
                                         wqh, wql, wkh, wkl, wvh, wvl,
                                         bq, bk, bv,
                                         qh, ql, kh, kl, vh, vl);

    dim3 attn_grid(T_ / 128, H_, B_);       // (16, 16, 4)
    attn_tc<<<attn_grid, 256, AT_SMEM>>>(qh, ql, kh, kl, vh, vl, yh, yl);

    dim3 proj_grid(E_ / 128, M_ / 128);     // (8, 64)
    gemm_proj<<<proj_grid, 256, GS_SMEM>>>(yh, yl, wph, wpl, bp, out);
}

// round 15
// speedup vs baseline: 2.2490x; 1.0572x over previous
#include <cuda_runtime.h>
#include <cuda_bf16.h>
#include <cuda_fp16.h>
#include <stdint.h>
#include <math.h>

#define B_  4
#define T_  2048
#define E_  1024
#define H_  16
#define HD_ 64
#define M_  (B_*T_)   // 8192

// q pre-scale: 0.125 (1/sqrt(hd)) * log2(e)  -> softmax via ex2
#define QSCALE 0.180336880f

// Scratch (device globals). g_q*/g_k*/g_v* hold fp16 payload (bytes).
__device__ __nv_bfloat16 g_xh[M_*E_], g_xl[M_*E_];
__device__ __nv_bfloat16 g_yh[M_*E_], g_yl[M_*E_];
__device__ __nv_bfloat16 g_qh[M_*E_], g_ql[M_*E_];
__device__ __nv_bfloat16 g_kh[M_*E_], g_kl[M_*E_];
__device__ __nv_bfloat16 g_vh[M_*E_], g_vl[M_*E_];
__device__ __nv_bfloat16 g_wqh[E_*E_], g_wql[E_*E_];
__device__ __nv_bfloat16 g_wkh[E_*E_], g_wkl[E_*E_];
__device__ __nv_bfloat16 g_wvh[E_*E_], g_wvl[E_*E_];
__device__ __nv_bfloat16 g_wph[E_*E_], g_wpl[E_*E_];

// ---------------------------------------------------------------------------
// helpers
// ---------------------------------------------------------------------------
__device__ __forceinline__ uint32_t smem_u32(const void* p) {
    return (uint32_t)__cvta_generic_to_shared(p);
}
__device__ __forceinline__ void cp_async16(uint32_t dst, const void* src) {
    asm volatile("cp.async.cg.shared.global [%0], [%1], 16;\n" :: "r"(dst), "l"(src));
}
__device__ __forceinline__ void cp_commit() { asm volatile("cp.async.commit_group;\n"); }
__device__ __forceinline__ void cp_wait0() { asm volatile("cp.async.wait_group 0;\n"); }
__device__ __forceinline__ void cp_wait1() { asm volatile("cp.async.wait_group 1;\n"); }

__device__ __forceinline__ void mma_bf16(float c[4], const uint32_t a[4], uint32_t b0, uint32_t b1) {
    asm volatile(
        "mma.sync.aligned.m16n8k16.row.col.f32.bf16.bf16.f32 "
        "{%0,%1,%2,%3}, {%4,%5,%6,%7}, {%8,%9}, {%0,%1,%2,%3};\n"
        : "+f"(c[0]), "+f"(c[1]), "+f"(c[2]), "+f"(c[3])
        : "r"(a[0]), "r"(a[1]), "r"(a[2]), "r"(a[3]), "r"(b0), "r"(b1));
}
__device__ __forceinline__ void mma_f16(float c[4], const uint32_t a[4], uint32_t b0, uint32_t b1) {
    asm volatile(
        "mma.sync.aligned.m16n8k16.row.col.f32.f16.f16.f32 "
        "{%0,%1,%2,%3}, {%4,%5,%6,%7}, {%8,%9}, {%0,%1,%2,%3};\n"
        : "+f"(c[0]), "+f"(c[1]), "+f"(c[2]), "+f"(c[3])
        : "r"(a[0]), "r"(a[1]), "r"(a[2]), "r"(a[3]), "r"(b0), "r"(b1));
}
__device__ __forceinline__ void ldsm_x4(uint32_t r[4], uint32_t addr) {
    asm volatile("ldmatrix.sync.aligned.m8n8.x4.shared.b16 {%0,%1,%2,%3}, [%4];"
        : "=r"(r[0]), "=r"(r[1]), "=r"(r[2]), "=r"(r[3]) : "r"(addr));
}
__device__ __forceinline__ void ldsm_x4t(uint32_t r[4], uint32_t addr) {
    asm volatile("ldmatrix.sync.aligned.m8n8.x4.trans.shared.b16 {%0,%1,%2,%3}, [%4];"
        : "=r"(r[0]), "=r"(r[1]), "=r"(r[2]), "=r"(r[3]) : "r"(addr));
}
__device__ __forceinline__ void split_bf16(float v, __nv_bfloat16& h, __nv_bfloat16& l) {
    h = __float2bfloat16(v);
    l = __float2bfloat16(v - __bfloat162float(h));
}
// Packed bf16 split: (a,b) -> hi pair (a low half) + lo pair.
__device__ __forceinline__ void split2(float a, float b, uint32_t& h2, uint32_t& l2) {
    uint32_t h;
    asm("cvt.rn.bf16x2.f32 %0, %1, %2;" : "=r"(h) : "f"(b), "f"(a));
    const float ha = __uint_as_float(h << 16);
    const float hb = __uint_as_float(h & 0xffff0000u);
    asm("cvt.rn.bf16x2.f32 %0, %1, %2;" : "=r"(l2) : "f"(b - hb), "f"(a - ha));
    h2 = h;
}
// Packed fp16 split: (a,b) -> hi fp16 pair (a low half) + lo fp16 pair.
__device__ __forceinline__ void split2h(float a, float b, uint32_t& h2, uint32_t& l2) {
    uint32_t h;
    asm("cvt.rn.f16x2.f32 %0, %1, %2;" : "=r"(h) : "f"(b), "f"(a));
    const __half2 hp = *(__half2*)&h;
    const float ha = __half2float(__low2half(hp));
    const float hb = __half2float(__high2half(hp));
    asm("cvt.rn.f16x2.f32 %0, %1, %2;" : "=r"(l2) : "f"(b - hb), "f"(a - ha));
    h2 = h;
}
__device__ __forceinline__ uint32_t pack_f16x2(float a, float b) {
    uint32_t r;
    asm("cvt.rn.f16x2.f32 %0, %1, %2;" : "=r"(r) : "f"(b), "f"(a));
    return r;
}
__device__ __forceinline__ float fast_ex2(float x) {
    float y;
    asm("ex2.approx.ftz.f32 %0, %1;" : "=f"(y) : "f"(x));
    return y;
}

// ---------------------------------------------------------------------------
// Prep: split fp32 -> bf16 hi/lo, same layout.
// ---------------------------------------------------------------------------
__global__ void split_kernel(const float* __restrict__ src,
                             __nv_bfloat16* __restrict__ hi,
                             __nv_bfloat16* __restrict__ lo, int n4)
{
    int i = blockIdx.x * blockDim.x + threadIdx.x;
    if (i >= n4) return;
    float4 v = ((const float4*)src)[i];
    __nv_bfloat16 h0,h1,h2,h3,l0,l1,l2,l3;
    split_bf16(v.x,h0,l0); split_bf16(v.y,h1,l1);
    split_bf16(v.z,h2,l2); split_bf16(v.w,h3,l3);
    ((__nv_bfloat162*)hi)[i*2+0] = __nv_bfloat162(h0,h1);
    ((__nv_bfloat162*)hi)[i*2+1] = __nv_bfloat162(h2,h3);
    ((__nv_bfloat162*)lo)[i*2+0] = __nv_bfloat162(l0,l1);
    ((__nv_bfloat162*)lo)[i*2+1] = __nv_bfloat162(l2,l3);
}

// ---------------------------------------------------------------------------
// Prep: transpose + split all 4 weights (blockIdx.z selects).
// ---------------------------------------------------------------------------
__global__ void tsplit4_kernel(
    const float* __restrict__ W0, const float* __restrict__ W1,
    const float* __restrict__ W2, const float* __restrict__ W3,
    __nv_bfloat16* __restrict__ T0h, __nv_bfloat16* __restrict__ T0l,
    __nv_bfloat16* __restrict__ T1h, __nv_bfloat16* __restrict__ T1l,
    __nv_bfloat16* __restrict__ T2h, __nv_bfloat16* __restrict__ T2l,
    __nv_bfloat16* __restrict__ T3h, __nv_bfloat16* __restrict__ T3l)
{
    const int z = blockIdx.z;
    const float* W = (z == 0) ? W0 : (z == 1) ? W1 : (z == 2) ? W2 : W3;
    __nv_bfloat16* Th = (z == 0) ? T0h : (z == 1) ? T1h : (z == 2) ? T2h : T3h;
    __nv_bfloat16* Tl = (z == 0) ? T0l : (z == 1) ? T1l : (z == 2) ? T2l : T3l;

    __shared__ float t[32][33];
    const int n0 = blockIdx.x * 32, k0 = blockIdx.y * 32;
    const int tx = threadIdx.x, ty = threadIdx.y;   // (32, 8)
    #pragma unroll
    for (int i = 0; i < 4; i++)
        t[ty + 8*i][tx] = W[(size_t)(k0 + ty + 8*i) * E_ + n0 + tx];
    __syncthreads();
    #pragma unroll
    for (int i = 0; i < 4; i++) {
        const int row = ty + 8*i;
        const float v = t[tx][row];
        __nv_bfloat16 h, l;
        split_bf16(v, h, l);
        Th[(size_t)(n0 + row) * E_ + k0 + tx] = h;
        Tl[(size_t)(n0 + row) * E_ + k0 + tx] = l;
    }
}

// ---------------------------------------------------------------------------
// bf16x3 tensor-core GEMM body, 3-stage cp.async, single barrier/iter,
// XOR-swizzled smem -> 2 CTAs/SM. FP16OUT selects fp16 hi/lo epilogue.
// ---------------------------------------------------------------------------
#define GS_TILE   8192
#define GS_STAGE  (4*GS_TILE)          // 32768 B
#define GS_SMEM   (3*GS_STAGE)         // 98304 B

template<bool REORDER, bool FP16OUT>
__device__ __forceinline__ void gemm_body(
    const __nv_bfloat16* __restrict__ Ah, const __nv_bfloat16* __restrict__ Al,
    const __nv_bfloat16* __restrict__ Th, const __nv_bfloat16* __restrict__ Tl,
    const float* __restrict__ bias, float* __restrict__ C,
    __nv_bfloat16* __restrict__ Ch, __nv_bfloat16* __restrict__ Cl,
    float oscale)
{
    extern __shared__ char sm[];
    const uint32_t smb = smem_u32(sm);

    const int tid  = threadIdx.x;
    const int warp = tid >> 5;
    const int lane = tid & 31;
    const int group = lane >> 2;
    const int tidg  = lane & 3;

    const int bn = blockIdx.x, bm = blockIdx.y;
    const int m0 = bm * 128, n0 = bn * 128;
    const int warp_m = warp & 1;
    const int warp_n = warp >> 1;

    const int lrow = (lane & 7) + ((lane >> 3) & 1) * 8;
    const int lchk = (lane >> 4) & 1;
    const int sel  = (lrow >> 1) & 3;

    auto load_stage = [&](int s, int c) {
        const int kb = c * 32;
        const uint32_t st = smb + s * GS_STAGE;
        #pragma unroll
        for (int i = 0; i < 2; i++) {
            const int ch = tid + i * 256;
            const int row = ch >> 2, q = ch & 3;
            const uint32_t d = st + row * 64 + (((q ^ ((row >> 1) & 3))) << 4);
            const size_t ga = (size_t)(m0 + row) * E_ + kb + q * 8;
            const size_t gb = (size_t)(n0 + row) * E_ + kb + q * 8;
            cp_async16(d,               Ah + ga);
            cp_async16(d + GS_TILE,     Al + ga);
            cp_async16(d + 2*GS_TILE,   Th + gb);
            cp_async16(d + 3*GS_TILE,   Tl + gb);
        }
        cp_commit();
    };

    float acc[4][4][4];
    #pragma unroll
    for (int i = 0; i < 4; i++)
        #pragma unroll
        for (int j = 0; j < 4; j++)
            #pragma unroll
            for (int r = 0; r < 4; r++) acc[i][j][r] = 0.f;

    const int NC = E_ / 32;
    load_stage(0, 0);
    load_stage(1, 1);

    for (int c = 0; c < NC; c++) {
        const int s = c % 3;
        if (c + 1 < NC) cp_wait1(); else cp_wait0();
        __syncthreads();
        if (c + 2 < NC) load_stage((c + 2) % 3, c + 2);

        const uint32_t st = smb + s * GS_STAGE;
        const uint32_t abase = st + (warp_m * 64 + lrow) * 64;
        const uint32_t bbase = st + 2*GS_TILE + (warp_n * 32 + lrow) * 64;

        #pragma unroll
        for (int h2 = 0; h2 < 2; h2++) {
            const uint32_t co = (uint32_t)(((lchk + 2 * h2) ^ sel) << 4);
            uint32_t ah[4][4], al[4][4], bh[2][4], bl[2][4];
            #pragma unroll
            for (int i = 0; i < 4; i++) {
                ldsm_x4(ah[i], abase + i * 16 * 64 + co);
                ldsm_x4(al[i], abase + GS_TILE + i * 16 * 64 + co);
            }
            #pragma unroll
            for (int g = 0; g < 2; g++) {
                ldsm_x4(bh[g], bbase + g * 16 * 64 + co);
                ldsm_x4(bl[g], bbase + GS_TILE + g * 16 * 64 + co);
            }
            #pragma unroll
            for (int i = 0; i < 4; i++)
                #pragma unroll
                for (int j = 0; j < 4; j++)
                    mma_bf16(acc[i][j], ah[i], bh[j>>1][j&1], bh[j>>1][(j&1)+2]);
            #pragma unroll
            for (int i = 0; i < 4; i++)
                #pragma unroll
                for (int j = 0; j < 4; j++)
                    mma_bf16(acc[i][j], ah[i], bl[j>>1][j&1], bl[j>>1][(j&1)+2]);
            #pragma unroll
            for (int i = 0; i < 4; i++)
                #pragma unroll
                for (int j = 0; j < 4; j++)
                    mma_bf16(acc[i][j], al[i], bh[j>>1][j&1], bh[j>>1][(j&1)+2]);
        }
    }

    #pragma unroll
    for (int i = 0; i < 4; i++) {
        const int rmb = m0 + warp_m * 64 + i * 16 + group;
        #pragma unroll
        for (int j = 0; j < 4; j++) {
            const int cb = n0 + warp_n * 32 + j * 8 + tidg * 2;
            const float bx = bias[cb], by = bias[cb + 1];
            #pragma unroll
            for (int half = 0; half < 2; half++) {
                const int m = rmb + half * 8;
                const float vx = (acc[i][j][half * 2 + 0] + bx) * (REORDER ? oscale : 1.f);
                const float vy = (acc[i][j][half * 2 + 1] + by) * (REORDER ? oscale : 1.f);
                if (REORDER) {
                    const int b = m >> 11;
                    const int t = m & (T_ - 1);
                    const int h = cb >> 6;
                    const int d = cb & (HD_ - 1);
                    const size_t o = (((size_t)(b * H_ + h) * T_) + t) * HD_ + d;
                    uint32_t h2, l2;
                    if (FP16OUT) split2h(vx, vy, h2, l2);
                    else         split2(vx, vy, h2, l2);
                    *(uint32_t*)&Ch[o] = h2;
                    *(uint32_t*)&Cl[o] = l2;
                } else {
                    float2 v; v.x = vx; v.y = vy;
                    *(float2*)&C[(size_t)m * E_ + cb] = v;
                }
            }
        }
    }
}

// Fused QKV: blockIdx.z selects. All outputs fp16 hi/lo; Q gets QSCALE.
__global__ void __launch_bounds__(256, 2) gemm_qkv(
    const __nv_bfloat16* __restrict__ xh, const __nv_bfloat16* __restrict__ xl,
    const __nv_bfloat16* __restrict__ wqh, const __nv_bfloat16* __restrict__ wql,
    const __nv_bfloat16* __restrict__ wkh, const __nv_bfloat16* __restrict__ wkl,
    const __nv_bfloat16* __restrict__ wvh, const __nv_bfloat16* __restrict__ wvl,
    const float* __restrict__ bq, const float* __restrict__ bk, const float* __restrict__ bv,
    __nv_bfloat16* __restrict__ qh, __nv_bfloat16* __restrict__ ql,
    __nv_bfloat16* __restrict__ kh, __nv_bfloat16* __restrict__ kl,
    __nv_bfloat16* __restrict__ vh, __nv_bfloat16* __restrict__ vl)
{
    const int z = blockIdx.z;
    const __nv_bfloat16* Th = (z == 0) ? wqh : (z == 1) ? wkh : wvh;
    const __nv_bfloat16* Tl = (z == 0) ? wql : (z == 1) ? wkl : wvl;
    const float* bias       = (z == 0) ? bq  : (z == 1) ? bk  : bv;
    __nv_bfloat16* Ch       = (z == 0) ? qh  : (z == 1) ? kh  : vh;
    __nv_bfloat16* Cl       = (z == 0) ? ql  : (z == 1) ? kl  : vl;
    const float oscale      = (z == 0) ? QSCALE : 1.0f;
    gemm_body<true, true>(xh, xl, Th, Tl, bias, nullptr, Ch, Cl, oscale);
}

__global__ void __launch_bounds__(256, 2) gemm_proj(
    const __nv_bfloat16* __restrict__ yh, const __nv_bfloat16* __restrict__ yl,
    const __nv_bfloat16* __restrict__ wph, const __nv_bfloat16* __restrict__ wpl,
    const float* __restrict__ bp, float* __restrict__ out)
{
    gemm_body<false, false>(yh, yl, wph, wpl, bp, out, nullptr, nullptr, 1.0f);
}

// ---------------------------------------------------------------------------
// Tensor-core flash attention (causal), all-fp16 MMA.
// QK: Q hi/lo x K single (2 products). PV: P single x V hi/lo (2 products).
// Log2-domain online softmax, deferred row-sum, rescale skip.
// Stage = Kh, Vh, Vl (3 tiles). 3-stage cp.async, single barrier per tile.
// ---------------------------------------------------------------------------
#define AT_STRIDE 144
#define AT_TILE   (64*AT_STRIDE)     // 9216
#define AT_STAGE  (3*AT_TILE)        // 27648
#define AT_SMEM   (3*AT_STAGE)       // 82944; x2 = 162 KB <= 228 KB/SM

__global__ void __launch_bounds__(256, 2) attn_tc(
    const __nv_bfloat16* __restrict__ Qh, const __nv_bfloat16* __restrict__ Ql,
    const __nv_bfloat16* __restrict__ Kh,
    const __nv_bfloat16* __restrict__ Vh, const __nv_bfloat16* __restrict__ Vl,
    __nv_bfloat16* __restrict__ Yh, __nv_bfloat16* __restrict__ Yl)
{
    extern __shared__ char sm[];
    const uint32_t smb = smem_u32(sm);

    const int tid  = threadIdx.x;
    const int warp = tid >> 5;
    const int lane = tid & 31;
    const int g    = lane >> 2;
    const int t4   = lane & 3;

    const int qb = (int)gridDim.x - 1 - (int)blockIdx.x;
    const int h  = blockIdx.y;
    const int b  = blockIdx.z;
    const int q0 = qb * 128;

    const size_t base = (size_t)(b * H_ + h) * T_ * HD_;
    const __nv_bfloat16* qh = Qh + base + (size_t)q0 * HD_;
    const __nv_bfloat16* ql = Ql + base + (size_t)q0 * HD_;
    const __nv_bfloat16* kh = Kh + base;
    const __nv_bfloat16* vh = Vh + base;
    const __nv_bfloat16* vl = Vl + base;

    const int arow = (lane & 7) + ((lane >> 3) & 1) * 8;
    const int achk = (lane >> 4) & 1;
    const int brow = (lane & 7) + ((lane >> 4) & 1) * 8;
    const int bchk = (lane >> 3) & 1;

    // ---- load Q (fp16 hi/lo) into first two stage regions, grab fragments ----
    #pragma unroll
    for (int i = 0; i < 4; i++) {
        const int ch = tid + i * 256;
        const int row = ch >> 3, q = ch & 7;
        const uint32_t d = smb + (row >> 6) * AT_TILE + (row & 63) * AT_STRIDE + q * 16;
        cp_async16(d,               qh + (size_t)row * HD_ + q * 8);
        cp_async16(d + 2*AT_TILE,   ql + (size_t)row * HD_ + q * 8);
    }
    cp_commit(); cp_wait0();
    __syncthreads();

    uint32_t qfh[4][4], qfl[4][4];
    {
        const int wr = warp * 16;
        const uint32_t qbse = smb + (wr >> 6) * AT_TILE + (wr & 63) * AT_STRIDE
                            + arow * AT_STRIDE + achk * 16;
        #pragma unroll
        for (int kc = 0; kc < 4; kc++) {
            ldsm_x4(qfh[kc], qbse + kc * 32);
            ldsm_x4(qfl[kc], qbse + 2*AT_TILE + kc * 32);
        }
    }
    __syncthreads();

    auto load_stage = [&](int s, int kt) {
        const int kv0 = kt * 64;
        const uint32_t st = smb + s * AT_STAGE;
        #pragma unroll
        for (int i = 0; i < 2; i++) {
            const int ch = tid + i * 256;
            const int row = ch >> 3, q = ch & 7;
            const uint32_t d = st + row * AT_STRIDE + q * 16;
            const size_t go = (size_t)(kv0 + row) * HD_ + q * 8;
            cp_async16(d,               kh + go);
            cp_async16(d + AT_TILE,     vh + go);
            cp_async16(d + 2*AT_TILE,   vl + go);
        }
        cp_commit();
    };

    float O[8][4];
    #pragma unroll
    for (int j = 0; j < 8; j++)
        #pragma unroll
        for (int r = 0; r < 4; r++) O[j][r] = 0.f;
    float m0 = -1e30f, m1 = -1e30f;
    float ps0 = 0.f, ps1 = 0.f;

    const int nt = 2 * (qb + 1);
    const int R  = q0 + warp * 16;

    load_stage(0, 0);
    if (nt > 1) load_stage(1, 1);

    for (int kt = 0; kt < nt; kt++) {
        const int s = kt % 3;
        const int kv0 = kt * 64;
        if (kt + 1 < nt) cp_wait1(); else cp_wait0();
        __syncthreads();
        if (kt + 2 < nt) load_stage((kt + 2) % 3, kt + 2);

        if (kv0 <= R + 15) {
            const uint32_t st = smb + s * AT_STAGE;

            // ---- S = Q K^T (fp16: Q hi/lo x K single) ----
            float S[8][4];
            #pragma unroll
            for (int j = 0; j < 8; j++)
                #pragma unroll
                for (int r = 0; r < 4; r++) S[j][r] = 0.f;

            #pragma unroll
            for (int kc = 0; kc < 4; kc++) {
                #pragma unroll
                for (int np = 0; np < 4; np++) {
                    uint32_t kf[4];
                    const uint32_t a = st + (np * 16 + brow) * AT_STRIDE + bchk * 16 + kc * 32;
                    ldsm_x4(kf, a);
                    const int j0 = 2 * np;
                    mma_f16(S[j0],     qfh[kc], kf[0], kf[1]);
                    mma_f16(S[j0 + 1], qfh[kc], kf[2], kf[3]);
                    mma_f16(S[j0],     qfl[kc], kf[0], kf[1]);
                    mma_f16(S[j0 + 1], qfl[kc], kf[2], kf[3]);
                }
            }

            // ---- causal mask ----
            const int row0 = R + g, row1 = R + g + 8;
            const bool need_mask = (kv0 + 63 > R);
            if (need_mask) {
                #pragma unroll
                for (int j = 0; j < 8; j++) {
                    const int c0 = kv0 + 8 * j + 2 * t4;
                    if (c0     > row0) S[j][0] = -1e30f;
                    if (c0 + 1 > row0) S[j][1] = -1e30f;
                    if (c0     > row1) S[j][2] = -1e30f;
                    if (c0 + 1 > row1) S[j][3] = -1e30f;
                }
            }

            // ---- running max ----
            float mx0 = -1e30f, mx1 = -1e30f;
            #pragma unroll
            for (int j = 0; j < 8; j++) {
                mx0 = fmaxf(mx0, fmaxf(S[j][0], S[j][1]));
                mx1 = fmaxf(mx1, fmaxf(S[j][2], S[j][3]));
            }
            mx0 = fmaxf(mx0, __shfl_xor_sync(0xffffffffu, mx0, 1));
            mx0 = fmaxf(mx0, __shfl_xor_sync(0xffffffffu, mx0, 2));
            mx1 = fmaxf(mx1, __shfl_xor_sync(0xffffffffu, mx1, 1));
            mx1 = fmaxf(mx1, __shfl_xor_sync(0xffffffffu, mx1, 2));

            const float nm0 = fmaxf(m0, mx0);
            const float nm1 = fmaxf(m1, mx1);
            if (nm0 != m0 || nm1 != m1) {
                const float cr0 = fast_ex2(m0 - nm0);
                const float cr1 = fast_ex2(m1 - nm1);
                ps0 *= cr0;  ps1 *= cr1;
                #pragma unroll
                for (int j = 0; j < 8; j++) {
                    O[j][0] *= cr0;  O[j][1] *= cr0;
                    O[j][2] *= cr1;  O[j][3] *= cr1;
                }
                m0 = nm0;  m1 = nm1;
            }

            // ---- P = 2^(S - m), per-thread sum accumulation ----
            #pragma unroll
            for (int j = 0; j < 8; j++) {
                S[j][0] = fast_ex2(S[j][0] - m0);
                S[j][1] = fast_ex2(S[j][1] - m0);
                S[j][2] = fast_ex2(S[j][2] - m1);
                S[j][3] = fast_ex2(S[j][3] - m1);
                ps0 += S[j][0] + S[j][1];
                ps1 += S[j][2] + S[j][3];
            }

            // ---- O += P V (fp16: P single x V hi/lo) ----
            #pragma unroll
            for (int kc = 0; kc < 4; kc++) {
                uint32_t ph[4];
                ph[0] = pack_f16x2(S[2*kc][0],   S[2*kc][1]);
                ph[1] = pack_f16x2(S[2*kc][2],   S[2*kc][3]);
                ph[2] = pack_f16x2(S[2*kc+1][0], S[2*kc+1][1]);
                ph[3] = pack_f16x2(S[2*kc+1][2], S[2*kc+1][3]);
                #pragma unroll
                for (int np = 0; np < 4; np++) {
                    uint32_t vfh[4], vfl[4];
                    const uint32_t a = st + AT_TILE + (kc * 16 + arow) * AT_STRIDE
                                     + np * 32 + achk * 16;
                    ldsm_x4t(vfh, a);
                    ldsm_x4t(vfl, a + AT_TILE);
                    const int j0 = 2 * np;
                    mma_f16(O[j0],     ph, vfh[0], vfh[1]);
                    mma_f16(O[j0 + 1], ph, vfh[2], vfh[3]);
                    mma_f16(O[j0],     ph, vfl[0], vfl[1]);
                    mma_f16(O[j0 + 1], ph, vfl[2], vfl[3]);
                }
            }
        }
    }

    // ---- one-time row-sum reduction + epilogue ----
    ps0 += __shfl_xor_sync(0xffffffffu, ps0, 1);
    ps0 += __shfl_xor_sync(0xffffffffu, ps0, 2);
    ps1 += __shfl_xor_sync(0xffffffffu, ps1, 1);
    ps1 += __shfl_xor_sync(0xffffffffu, ps1, 2);
    const float inv0 = 1.0f / ps0;
    const float inv1 = 1.0f / ps1;

    const int row0 = q0 + warp * 16 + g;
    const int row1 = row0 + 8;
    #pragma unroll
    for (int j = 0; j < 8; j++) {
        const int col = h * HD_ + 8 * j + 2 * t4;
        const size_t o0 = (size_t)(b * T_ + row0) * E_ + col;
        const size_t o1 = (size_t)(b * T_ + row1) * E_ + col;
        uint32_t h2, l2;
        split2(O[j][0] * inv0, O[j][1] * inv0, h2, l2);
        *(uint32_t*)&Yh[o0] = h2;
        *(uint32_t*)&Yl[o0] = l2;
        split2(O[j][2] * inv1, O[j][3] * inv1, h2, l2);
        *(uint32_t*)&Yh[o1] = h2;
        *(uint32_t*)&Yl[o1] = l2;
    }
}

// ---------------------------------------------------------------------------
extern "C" void kernel_launch(void* const* d_in, const int* in_sizes, int n_in,
                              void* d_out, int out_size)
{
    const float* x  = (const float*)d_in[0];
    const float* Wq = (const float*)d_in[2];
    const float* bq = (const float*)d_in[3];
    const float* Wk = (const float*)d_in[4];
    const float* bk = (const float*)d_in[5];
    const float* Wv = (const float*)d_in[6];
    const float* bv = (const float*)d_in[7];
    const float* Wp = (const float*)d_in[8];
    const float* bp = (const float*)d_in[9];
    float* out = (float*)d_out;

    __nv_bfloat16 *xh, *xl, *yh, *yl, *qh, *ql, *kh, *kl, *vh, *vl;
    __nv_bfloat16 *wqh, *wql, *wkh, *wkl, *wvh, *wvl, *wph, *wpl;
    cudaGetSymbolAddress((void**)&xh, g_xh);  cudaGetSymbolAddress((void**)&xl, g_xl);
    cudaGetSymbolAddress((void**)&yh, g_yh);  cudaGetSymbolAddress((void**)&yl, g_yl);
    cudaGetSymbolAddress((void**)&qh, g_qh);  cudaGetSymbolAddress((void**)&ql, g_ql);
    cudaGetSymbolAddress((void**)&kh, g_kh);  cudaGetSymbolAddress((void**)&kl, g_kl);
    cudaGetSymbolAddress((void**)&vh, g_vh);  cudaGetSymbolAddress((void**)&vl, g_vl);
    cudaGetSymbolAddress((void**)&wqh, g_wqh);  cudaGetSymbolAddress((void**)&wql, g_wql);
    cudaGetSymbolAddress((void**)&wkh, g_wkh);  cudaGetSymbolAddress((void**)&wkl, g_wkl);
    cudaGetSymbolAddress((void**)&wvh, g_wvh);  cudaGetSymbolAddress((void**)&wvl, g_wvl);
    cudaGetSymbolAddress((void**)&wph, g_wph);  cudaGetSymbolAddress((void**)&wpl, g_wpl);

    cudaFuncSetAttribute(gemm_qkv,  cudaFuncAttributeMaxDynamicSharedMemorySize, GS_SMEM);
    cudaFuncSetAttribute(gemm_proj, cudaFuncAttributeMaxDynamicSharedMemorySize, GS_SMEM);
    cudaFuncSetAttribute(attn_tc,   cudaFuncAttributeMaxDynamicSharedMemorySize, AT_SMEM);

    // Prep: split x, transpose+split all weights (one launch)
    split_kernel<<<(M_*E_/4 + 255)/256, 256>>>(x, xh, xl, M_*E_/4);
    dim3 tgrid(E_/32, E_/32, 4), tblk(32, 8);
    tsplit4_kernel<<<tgrid, tblk>>>(Wq, Wk, Wv, Wp,
                                    wqh, wql, wkh, wkl, wvh, wvl, wph, wpl);

    // Fused QKV projections
    dim3 qkv_grid(E_ / 128, M_ / 128, 3);   // (8, 64, 3)
    gemm_qkv<<<qkv_grid, 256, GS_SMEM>>>(xh, xl,
                                         wqh, wql, wkh, wkl, wvh, wvl,
                                         bq, bk, bv,
                                         qh, ql, kh, kl, vh, vl);

    dim3 attn_grid(T_ / 128, H_, B_);       // (16, 16, 4)
    attn_tc<<<attn_grid, 256, AT_SMEM>>>(qh, ql, kh, vh, vl, yh, yl);

    dim3 proj_grid(E_ / 128, M_ / 128);     // (8, 64)
    gemm_proj<<<proj_grid, 256, GS_SMEM>>>(yh, yl, wph, wpl, bp, out);
}

// round 16
// speedup vs baseline: 2.8345x; 1.2603x over previous
#include <cuda_runtime.h>
#include <cuda_bf16.h>
#include <cuda_fp16.h>
#include <stdint.h>
#include <math.h>

#define B_  4
#define T_  2048
#define E_  1024
#define H_  16
#define HD_ 64
#define M_  (B_*T_)   // 8192

// q pre-scale: 0.125 (1/sqrt(hd)) * log2(e)  -> softmax via ex2
#define QSCALE 0.180336880f

// Scratch (device globals). All activation/weight buffers hold fp16 payload.
__device__ __half g_xh[M_*E_], g_xl[M_*E_];
__device__ __half g_yh[M_*E_], g_yl[M_*E_];
__device__ __half g_qh[M_*E_], g_ql[M_*E_];
__device__ __half g_kh[M_*E_];
__device__ __half g_vh[M_*E_], g_vl[M_*E_];
__device__ __half g_wq[E_*E_], g_wk[E_*E_], g_wv[E_*E_], g_wp[E_*E_];

// ---------------------------------------------------------------------------
// helpers
// ---------------------------------------------------------------------------
__device__ __forceinline__ uint32_t smem_u32(const void* p) {
    return (uint32_t)__cvta_generic_to_shared(p);
}
__device__ __forceinline__ void cp_async16(uint32_t dst, const void* src) {
    asm volatile("cp.async.cg.shared.global [%0], [%1], 16;\n" :: "r"(dst), "l"(src));
}
__device__ __forceinline__ void cp_commit() { asm volatile("cp.async.commit_group;\n"); }
__device__ __forceinline__ void cp_wait0() { asm volatile("cp.async.wait_group 0;\n"); }
__device__ __forceinline__ void cp_wait1() { asm volatile("cp.async.wait_group 1;\n"); }

__device__ __forceinline__ void mma_f16(float c[4], const uint32_t a[4], uint32_t b0, uint32_t b1) {
    asm volatile(
        "mma.sync.aligned.m16n8k16.row.col.f32.f16.f16.f32 "
        "{%0,%1,%2,%3}, {%4,%5,%6,%7}, {%8,%9}, {%0,%1,%2,%3};\n"
        : "+f"(c[0]), "+f"(c[1]), "+f"(c[2]), "+f"(c[3])
        : "r"(a[0]), "r"(a[1]), "r"(a[2]), "r"(a[3]), "r"(b0), "r"(b1));
}
__device__ __forceinline__ void ldsm_x4(uint32_t r[4], uint32_t addr) {
    asm volatile("ldmatrix.sync.aligned.m8n8.x4.shared.b16 {%0,%1,%2,%3}, [%4];"
        : "=r"(r[0]), "=r"(r[1]), "=r"(r[2]), "=r"(r[3]) : "r"(addr));
}
__device__ __forceinline__ void ldsm_x4t(uint32_t r[4], uint32_t addr) {
    asm volatile("ldmatrix.sync.aligned.m8n8.x4.trans.shared.b16 {%0,%1,%2,%3}, [%4];"
        : "=r"(r[0]), "=r"(r[1]), "=r"(r[2]), "=r"(r[3]) : "r"(addr));
}
// Packed fp16 split: (a,b) -> hi fp16 pair (a low half) + lo fp16 pair.
__device__ __forceinline__ void split2h(float a, float b, uint32_t& h2, uint32_t& l2) {
    uint32_t h;
    asm("cvt.rn.f16x2.f32 %0, %1, %2;" : "=r"(h) : "f"(b), "f"(a));
    const __half2 hp = *(__half2*)&h;
    const float ha = __half2float(__low2half(hp));
    const float hb = __half2float(__high2half(hp));
    asm("cvt.rn.f16x2.f32 %0, %1, %2;" : "=r"(l2) : "f"(b - hb), "f"(a - ha));
    h2 = h;
}
__device__ __forceinline__ uint32_t pack_f16x2(float a, float b) {
    uint32_t r;
    asm("cvt.rn.f16x2.f32 %0, %1, %2;" : "=r"(r) : "f"(b), "f"(a));
    return r;
}
__device__ __forceinline__ float fast_ex2(float x) {
    float y;
    asm("ex2.approx.ftz.f32 %0, %1;" : "=f"(y) : "f"(x));
    return y;
}

// ---------------------------------------------------------------------------
// Prep: split fp32 -> fp16 hi/lo, same layout.
// ---------------------------------------------------------------------------
__global__ void split_kernel(const float* __restrict__ src,
                             __half* __restrict__ hi,
                             __half* __restrict__ lo, int n4)
{
    int i = blockIdx.x * blockDim.x + threadIdx.x;
    if (i >= n4) return;
    float4 v = ((const float4*)src)[i];
    uint32_t h0, l0, h1, l1;
    split2h(v.x, v.y, h0, l0);
    split2h(v.z, v.w, h1, l1);
    ((uint32_t*)hi)[i*2+0] = h0;
    ((uint32_t*)hi)[i*2+1] = h1;
    ((uint32_t*)lo)[i*2+0] = l0;
    ((uint32_t*)lo)[i*2+1] = l1;
}

// ---------------------------------------------------------------------------
// Prep: transpose all 4 weights to single fp16 [N][K] (blockIdx.z selects).
// ---------------------------------------------------------------------------
__global__ void tsplit4_kernel(
    const float* __restrict__ W0, const float* __restrict__ W1,
    const float* __restrict__ W2, const float* __restrict__ W3,
    __half* __restrict__ T0, __half* __restrict__ T1,
    __half* __restrict__ T2, __half* __restrict__ T3)
{
    const int z = blockIdx.z;
    const float* W = (z == 0) ? W0 : (z == 1) ? W1 : (z == 2) ? W2 : W3;
    __half* Tw = (z == 0) ? T0 : (z == 1) ? T1 : (z == 2) ? T2 : T3;

    __shared__ float t[32][33];
    const int n0 = blockIdx.x * 32, k0 = blockIdx.y * 32;
    const int tx = threadIdx.x, ty = threadIdx.y;   // (32, 8)
    #pragma unroll
    for (int i = 0; i < 4; i++)
        t[ty + 8*i][tx] = W[(size_t)(k0 + ty + 8*i) * E_ + n0 + tx];
    __syncthreads();
    #pragma unroll
    for (int i = 0; i < 4; i++) {
        const int row = ty + 8*i;
        Tw[(size_t)(n0 + row) * E_ + k0 + tx] = __float2half(t[tx][row]);
    }
}

// ---------------------------------------------------------------------------
// fp16x2 tensor-core GEMM body: C = (Ah + Al) @ W^T, W single fp16.
// 3-stage cp.async, single barrier/iter, XOR-swizzled smem (64B rows).
// Stage = Ah, Al, B tiles -> 24576 B; 3 stages = 73728 B -> 2 CTAs/SM.
// ---------------------------------------------------------------------------
#define GS_TILE   8192
#define GS_STAGE  (3*GS_TILE)          // 24576 B
#define GS_SMEM   (3*GS_STAGE)         // 73728 B

template<bool REORDER>
__device__ __forceinline__ void gemm_body(
    const __half* __restrict__ Ah, const __half* __restrict__ Al,
    const __half* __restrict__ Tw,
    const float* __restrict__ bias, float* __restrict__ C,
    __half* __restrict__ Ch, __half* __restrict__ Cl,
    float oscale)
{
    extern __shared__ char sm[];
    const uint32_t smb = smem_u32(sm);

    const int tid  = threadIdx.x;
    const int warp = tid >> 5;
    const int lane = tid & 31;
    const int group = lane >> 2;
    const int tidg  = lane & 3;

    const int bn = blockIdx.x, bm = blockIdx.y;
    const int m0 = bm * 128, n0 = bn * 128;
    const int warp_m = warp & 1;
    const int warp_n = warp >> 1;

    const int lrow = (lane & 7) + ((lane >> 3) & 1) * 8;
    const int lchk = (lane >> 4) & 1;
    const int sel  = (lrow >> 1) & 3;

    auto load_stage = [&](int s, int c) {
        const int kb = c * 32;
        const uint32_t st = smb + s * GS_STAGE;
        #pragma unroll
        for (int i = 0; i < 2; i++) {
            const int ch = tid + i * 256;
            const int row = ch >> 2, q = ch & 3;
            const uint32_t d = st + row * 64 + (((q ^ ((row >> 1) & 3))) << 4);
            const size_t ga = (size_t)(m0 + row) * E_ + kb + q * 8;
            const size_t gb = (size_t)(n0 + row) * E_ + kb + q * 8;
            cp_async16(d,               Ah + ga);
            cp_async16(d + GS_TILE,     Al + ga);
            cp_async16(d + 2*GS_TILE,   Tw + gb);
        }
        cp_commit();
    };

    float acc[4][4][4];
    #pragma unroll
    for (int i = 0; i < 4; i++)
        #pragma unroll
        for (int j = 0; j < 4; j++)
            #pragma unroll
            for (int r = 0; r < 4; r++) acc[i][j][r] = 0.f;

    const int NC = E_ / 32;
    load_stage(0, 0);
    load_stage(1, 1);

    for (int c = 0; c < NC; c++) {
        const int s = c % 3;
        if (c + 1 < NC) cp_wait1(); else cp_wait0();
        __syncthreads();
        if (c + 2 < NC) load_stage((c + 2) % 3, c + 2);

        const uint32_t st = smb + s * GS_STAGE;
        const uint32_t abase = st + (warp_m * 64 + lrow) * 64;
        const uint32_t bbase = st + 2*GS_TILE + (warp_n * 32 + lrow) * 64;

        #pragma unroll
        for (int h2 = 0; h2 < 2; h2++) {
            const uint32_t co = (uint32_t)(((lchk + 2 * h2) ^ sel) << 4);
            uint32_t ah[4][4], al[4][4], bf[2][4];
            #pragma unroll
            for (int i = 0; i < 4; i++) {
                ldsm_x4(ah[i], abase + i * 16 * 64 + co);
                ldsm_x4(al[i], abase + GS_TILE + i * 16 * 64 + co);
            }
            #pragma unroll
            for (int g = 0; g < 2; g++)
                ldsm_x4(bf[g], bbase + g * 16 * 64 + co);
            #pragma unroll
            for (int i = 0; i < 4; i++)
                #pragma unroll
                for (int j = 0; j < 4; j++)
                    mma_f16(acc[i][j], ah[i], bf[j>>1][j&1], bf[j>>1][(j&1)+2]);
            #pragma unroll
            for (int i = 0; i < 4; i++)
                #pragma unroll
                for (int j = 0; j < 4; j++)
                    mma_f16(acc[i][j], al[i], bf[j>>1][j&1], bf[j>>1][(j&1)+2]);
        }
    }

    #pragma unroll
    for (int i = 0; i < 4; i++) {
        const int rmb = m0 + warp_m * 64 + i * 16 + group;
        #pragma unroll
        for (int j = 0; j < 4; j++) {
            const int cb = n0 + warp_n * 32 + j * 8 + tidg * 2;
            const float bx = bias[cb], by = bias[cb + 1];
            #pragma unroll
            for (int half = 0; half < 2; half++) {
                const int m = rmb + half * 8;
                const float vx = (acc[i][j][half * 2 + 0] + bx) * (REORDER ? oscale : 1.f);
                const float vy = (acc[i][j][half * 2 + 1] + by) * (REORDER ? oscale : 1.f);
                if (REORDER) {
                    const int b = m >> 11;
                    const int t = m & (T_ - 1);
                    const int h = cb >> 6;
                    const int d = cb & (HD_ - 1);
                    const size_t o = (((size_t)(b * H_ + h) * T_) + t) * HD_ + d;
                    uint32_t h2, l2;
                    split2h(vx, vy, h2, l2);
                    *(uint32_t*)&Ch[o] = h2;
                    if (Cl) *(uint32_t*)&Cl[o] = l2;
                } else {
                    float2 v; v.x = vx; v.y = vy;
                    *(float2*)&C[(size_t)m * E_ + cb] = v;
                }
            }
        }
    }
}

// Fused QKV: blockIdx.z selects. Q gets QSCALE; K stores hi only.
__global__ void __launch_bounds__(256, 2) gemm_qkv(
    const __half* __restrict__ xh, const __half* __restrict__ xl,
    const __half* __restrict__ wq, const __half* __restrict__ wk,
    const __half* __restrict__ wv,
    const float* __restrict__ bq, const float* __restrict__ bk, const float* __restrict__ bv,
    __half* __restrict__ qh, __half* __restrict__ ql,
    __half* __restrict__ kh,
    __half* __restrict__ vh, __half* __restrict__ vl)
{
    const int z = blockIdx.z;
    const __half* Tw   = (z == 0) ? wq : (z == 1) ? wk : wv;
    const float* bias  = (z == 0) ? bq : (z == 1) ? bk : bv;
    __half* Ch         = (z == 0) ? qh : (z == 1) ? kh : vh;
    __half* Cl         = (z == 0) ? ql : (z == 1) ? nullptr : vl;
    const float oscale = (z == 0) ? QSCALE : 1.0f;
    gemm_body<true>(xh, xl, Tw, bias, nullptr, Ch, Cl, oscale);
}

__global__ void __launch_bounds__(256, 2) gemm_proj(
    const __half* __restrict__ yh, const __half* __restrict__ yl,
    const __half* __restrict__ wp,
    const float* __restrict__ bp, float* __restrict__ out)
{
    gemm_body<false>(yh, yl, wp, bp, out, nullptr, nullptr, 1.0f);
}

// ---------------------------------------------------------------------------
// Tensor-core flash attention (causal), all-fp16 MMA (unchanged from R15).
// QK: Q hi/lo x K single. PV: P single x V hi/lo.
// ---------------------------------------------------------------------------
#define AT_STRIDE 144
#define AT_TILE   (64*AT_STRIDE)     // 9216
#define AT_STAGE  (3*AT_TILE)        // 27648
#define AT_SMEM   (3*AT_STAGE)       // 82944; x2 = 162 KB <= 228 KB/SM

__global__ void __launch_bounds__(256, 2) attn_tc(
    const __half* __restrict__ Qh, const __half* __restrict__ Ql,
    const __half* __restrict__ Kh,
    const __half* __restrict__ Vh, const __half* __restrict__ Vl,
    __half* __restrict__ Yh, __half* __restrict__ Yl)
{
    extern __shared__ char sm[];
    const uint32_t smb = smem_u32(sm);

    const int tid  = threadIdx.x;
    const int warp = tid >> 5;
    const int lane = tid & 31;
    const int g    = lane >> 2;
    const int t4   = lane & 3;

    const int qb = (int)gridDim.x - 1 - (int)blockIdx.x;
    const int h  = blockIdx.y;
    const int b  = blockIdx.z;
    const int q0 = qb * 128;

    const size_t base = (size_t)(b * H_ + h) * T_ * HD_;
    const __half* qh = Qh + base + (size_t)q0 * HD_;
    const __half* ql = Ql + base + (size_t)q0 * HD_;
    const __half* kh = Kh + base;
    const __half* vh = Vh + base;
    const __half* vl = Vl + base;

    const int arow = (lane & 7) + ((lane >> 3) & 1) * 8;
    const int achk = (lane >> 4) & 1;
    const int brow = (lane & 7) + ((lane >> 4) & 1) * 8;
    const int bchk = (lane >> 3) & 1;

    #pragma unroll
    for (int i = 0; i < 4; i++) {
        const int ch = tid + i * 256;
        const int row = ch >> 3, q = ch & 7;
        const uint32_t d = smb + (row >> 6) * AT_TILE + (row & 63) * AT_STRIDE + q * 16;
        cp_async16(d,               qh + (size_t)row * HD_ + q * 8);
        cp_async16(d + 2*AT_TILE,   ql + (size_t)row * HD_ + q * 8);
    }
    cp_commit(); cp_wait0();
    __syncthreads();

    uint32_t qfh[4][4], qfl[4][4];
    {
        const int wr = warp * 16;
        const uint32_t qbse = smb + (wr >> 6) * AT_TILE + (wr & 63) * AT_STRIDE
                            + arow * AT_STRIDE + achk * 16;
        #pragma unroll
        for (int kc = 0; kc < 4; kc++) {
            ldsm_x4(qfh[kc], qbse + kc * 32);
            ldsm_x4(qfl[kc], qbse + 2*AT_TILE + kc * 32);
        }
    }
    __syncthreads();

    auto load_stage = [&](int s, int kt) {
        const int kv0 = kt * 64;
        const uint32_t st = smb + s * AT_STAGE;
        #pragma unroll
        for (int i = 0; i < 2; i++) {
            const int ch = tid + i * 256;
            const int row = ch >> 3, q = ch & 7;
            const uint32_t d = st + row * AT_STRIDE + q * 16;
            const size_t go = (size_t)(kv0 + row) * HD_ + q * 8;
            cp_async16(d,               kh + go);
            cp_async16(d + AT_TILE,     vh + go);
            cp_async16(d + 2*AT_TILE,   vl + go);
        }
        cp_commit();
    };

    float O[8][4];
    #pragma unroll
    for (int j = 0; j < 8; j++)
        #pragma unroll
        for (int r = 0; r < 4; r++) O[j][r] = 0.f;
    float m0 = -1e30f, m1 = -1e30f;
    float ps0 = 0.f, ps1 = 0.f;

    const int nt = 2 * (qb + 1);
    const int R  = q0 + warp * 16;

    load_stage(0, 0);
    if (nt > 1) load_stage(1, 1);

    for (int kt = 0; kt < nt; kt++) {
        const int s = kt % 3;
        const int kv0 = kt * 64;
        if (kt + 1 < nt) cp_wait1(); else cp_wait0();
        __syncthreads();
        if (kt + 2 < nt) load_stage((kt + 2) % 3, kt + 2);

        if (kv0 <= R + 15) {
            const uint32_t st = smb + s * AT_STAGE;

            float S[8][4];
            #pragma unroll
            for (int j = 0; j < 8; j++)
                #pragma unroll
                for (int r = 0; r < 4; r++) S[j][r] = 0.f;

            #pragma unroll
            for (int kc = 0; kc < 4; kc++) {
                #pragma unroll
                for (int np = 0; np < 4; np++) {
                    uint32_t kf[4];
                    const uint32_t a = st + (np * 16 + brow) * AT_STRIDE + bchk * 16 + kc * 32;
                    ldsm_x4(kf, a);
                    const int j0 = 2 * np;
                    mma_f16(S[j0],     qfh[kc], kf[0], kf[1]);
                    mma_f16(S[j0 + 1], qfh[kc], kf[2], kf[3]);
                    mma_f16(S[j0],     qfl[kc], kf[0], kf[1]);
                    mma_f16(S[j0 + 1], qfl[kc], kf[2], kf[3]);
                }
            }

            const int row0 = R + g, row1 = R + g + 8;
            const bool need_mask = (kv0 + 63 > R);
            if (need_mask) {
                #pragma unroll
                for (int j = 0; j < 8; j++) {
                    const int c0 = kv0 + 8 * j + 2 * t4;
                    if (c0     > row0) S[j][0] = -1e30f;
                    if (c0 + 1 > row0) S[j][1] = -1e30f;
                    if (c0     > row1) S[j][2] = -1e30f;
                    if (c0 + 1 > row1) S[j][3] = -1e30f;
                }
            }

            float mx0 = -1e30f, mx1 = -1e30f;
            #pragma unroll
            for (int j = 0; j < 8; j++) {
                mx0 = fmaxf(mx0, fmaxf(S[j][0], S[j][1]));
                mx1 = fmaxf(mx1, fmaxf(S[j][2], S[j][3]));
            }
            mx0 = fmaxf(mx0, __shfl_xor_sync(0xffffffffu, mx0, 1));
            mx0 = fmaxf(mx0, __shfl_xor_sync(0xffffffffu, mx0, 2));
            mx1 = fmaxf(mx1, __shfl_xor_sync(0xffffffffu, mx1, 1));
            mx1 = fmaxf(mx1, __shfl_xor_sync(0xffffffffu, mx1, 2));

            const float nm0 = fmaxf(m0, mx0);
            const float nm1 = fmaxf(m1, mx1);
            if (nm0 != m0 || nm1 != m1) {
                const float cr0 = fast_ex2(m0 - nm0);
                const float cr1 = fast_ex2(m1 - nm1);
                ps0 *= cr0;  ps1 *= cr1;
                #pragma unroll
                for (int j = 0; j < 8; j++) {
                    O[j][0] *= cr0;  O[j][1] *= cr0;
                    O[j][2] *= cr1;  O[j][3] *= cr1;
                }
                m0 = nm0;  m1 = nm1;
            }

            #pragma unroll
            for (int j = 0; j < 8; j++) {
                S[j][0] = fast_ex2(S[j][0] - m0);
                S[j][1] = fast_ex2(S[j][1] - m0);
                S[j][2] = fast_ex2(S[j][2] - m1);
                S[j][3] = fast_ex2(S[j][3] - m1);
                ps0 += S[j][0] + S[j][1];
                ps1 += S[j][2] + S[j][3];
            }

            #pragma unroll
            for (int kc = 0; kc < 4; kc++) {
                uint32_t ph[4];
                ph[0] = pack_f16x2(S[2*kc][0],   S[2*kc][1]);
                ph[1] = pack_f16x2(S[2*kc][2],   S[2*kc][3]);
                ph[2] = pack_f16x2(S[2*kc+1][0], S[2*kc+1][1]);
                ph[3] = pack_f16x2(S[2*kc+1][2], S[2*kc+1][3]);
                #pragma unroll
                for (int np = 0; np < 4; np++) {
                    uint32_t vfh[4], vfl[4];
                    const uint32_t a = st + AT_TILE + (kc * 16 + arow) * AT_STRIDE
                                     + np * 32 + achk * 16;
                    ldsm_x4t(vfh, a);
                    ldsm_x4t(vfl, a + AT_TILE);
                    const int j0 = 2 * np;
                    mma_f16(O[j0],     ph, vfh[0], vfh[1]);
                    mma_f16(O[j0 + 1], ph, vfh[2], vfh[3]);
                    mma_f16(O[j0],     ph, vfl[0], vfl[1]);
                    mma_f16(O[j0 + 1], ph, vfl[2], vfl[3]);
                }
            }
        }
    }

    ps0 += __shfl_xor_sync(0xffffffffu, ps0, 1);
    ps0 += __shfl_xor_sync(0xffffffffu, ps0, 2);
    ps1 += __shfl_xor_sync(0xffffffffu, ps1, 1);
    ps1 += __shfl_xor_sync(0xffffffffu, ps1, 2);
    const float inv0 = 1.0f / ps0;
    const float inv1 = 1.0f / ps1;

    const int row0 = q0 + warp * 16 + g;
    const int row1 = row0 + 8;
    #pragma unroll
    for (int j = 0; j < 8; j++) {
        const int col = h * HD_ + 8 * j + 2 * t4;
        const size_t o0 = (size_t)(b * T_ + row0) * E_ + col;
        const size_t o1 = (size_t)(b * T_ + row1) * E_ + col;
        uint32_t h2, l2;
        split2h(O[j][0] * inv0, O[j][1] * inv0, h2, l2);
        *(uint32_t*)&Yh[o0] = h2;
        *(uint32_t*)&Yl[o0] = l2;
        split2h(O[j][2] * inv1, O[j][3] * inv1, h2, l2);
        *(uint32_t*)&Yh[o1] = h2;
        *(uint32_t*)&Yl[o1] = l2;
    }
}

// ---------------------------------------------------------------------------
extern "C" void kernel_launch(void* const* d_in, const int* in_sizes, int n_in,
                              void* d_out, int out_size)
{
    const float* x  = (const float*)d_in[0];
    const float* Wq = (const float*)d_in[2];
    const float* bq = (const float*)d_in[3];
    const float* Wk = (const float*)d_in[4];
    const float* bk = (const float*)d_in[5];
    const float* Wv = (const float*)d_in[6];
    const float* bv = (const float*)d_in[7];
    const float* Wp = (const float*)d_in[8];
    const float* bp = (const float*)d_in[9];
    float* out = (float*)d_out;

    __half *xh, *xl, *yh, *yl, *qh, *ql, *kh, *vh, *vl;
    __half *wq, *wk, *wv, *wp;
    cudaGetSymbolAddress((void**)&xh, g_xh);  cudaGetSymbolAddress((void**)&xl, g_xl);
    cudaGetSymbolAddress((void**)&yh, g_yh);  cudaGetSymbolAddress((void**)&yl, g_yl);
    cudaGetSymbolAddress((void**)&qh, g_qh);  cudaGetSymbolAddress((void**)&ql, g_ql);
    cudaGetSymbolAddress((void**)&kh, g_kh);
    cudaGetSymbolAddress((void**)&vh, g_vh);  cudaGetSymbolAddress((void**)&vl, g_vl);
    cudaGetSymbolAddress((void**)&wq, g_wq);  cudaGetSymbolAddress((void**)&wk, g_wk);
    cudaGetSymbolAddress((void**)&wv, g_wv);  cudaGetSymbolAddress((void**)&wp, g_wp);

    cudaFuncSetAttribute(gemm_qkv,  cudaFuncAttributeMaxDynamicSharedMemorySize, GS_SMEM);
    cudaFuncSetAttribute(gemm_proj, cudaFuncAttributeMaxDynamicSharedMemorySize, GS_SMEM);
    cudaFuncSetAttribute(attn_tc,   cudaFuncAttributeMaxDynamicSharedMemorySize, AT_SMEM);

    // Prep: split x (fp16 hi/lo), transpose weights (single fp16)
    split_kernel<<<(M_*E_/4 + 255)/256, 256>>>(x, xh, xl, M_*E_/4);
    dim3 tgrid(E_/32, E_/32, 4), tblk(32, 8);
    tsplit4_kernel<<<tgrid, tblk>>>(Wq, Wk, Wv, Wp, wq, wk, wv, wp);

    // Fused QKV projections
    dim3 qkv_grid(E_ / 128, M_ / 128, 3);   // (8, 64, 3)
    gemm_qkv<<<qkv_grid, 256, GS_SMEM>>>(xh, xl, wq, wk, wv,
                                         bq, bk, bv,
                                         qh, ql, kh, vh, vl);

    dim3 attn_grid(T_ / 128, H_, B_);       // (16, 16, 4)
    attn_tc<<<attn_grid, 256, AT_SMEM>>>(qh, ql, kh, vh, vl, yh, yl);

    dim3 proj_grid(E_ / 128, M_ / 128);     // (8, 64)
    gemm_proj<<<proj_grid, 256, GS_SMEM>>>(yh, yl, wp, bp, out);
}

// round 17
// speedup vs baseline: 3.0581x; 1.0789x over previous
#include <cuda_runtime.h>
#include <cuda_bf16.h>
#include <cuda_fp16.h>
#include <stdint.h>
#include <math.h>

#define B_  4
#define T_  2048
#define E_  1024
#define H_  16
#define HD_ 64
#define M_  (B_*T_)   // 8192

// q pre-scale: 0.125 (1/sqrt(hd)) * log2(e)  -> softmax via ex2
#define QSCALE 0.180336880f

// Scratch (device globals). All activation/weight buffers hold fp16 payload.
__device__ __half g_xh[M_*E_], g_xl[M_*E_];
__device__ __half g_yh[M_*E_], g_yl[M_*E_];
__device__ __half g_qh[M_*E_], g_ql[M_*E_];
__device__ __half g_kh[M_*E_];
__device__ __half g_vh[M_*E_];
__device__ __half g_wq[E_*E_], g_wk[E_*E_], g_wv[E_*E_], g_wp[E_*E_];

// ---------------------------------------------------------------------------
// helpers
// ---------------------------------------------------------------------------
__device__ __forceinline__ uint32_t smem_u32(const void* p) {
    return (uint32_t)__cvta_generic_to_shared(p);
}
__device__ __forceinline__ void cp_async16(uint32_t dst, const void* src) {
    asm volatile("cp.async.cg.shared.global [%0], [%1], 16;\n" :: "r"(dst), "l"(src));
}
__device__ __forceinline__ void cp_commit() { asm volatile("cp.async.commit_group;\n"); }
__device__ __forceinline__ void cp_wait0() { asm volatile("cp.async.wait_group 0;\n"); }
__device__ __forceinline__ void cp_wait1() { asm volatile("cp.async.wait_group 1;\n"); }

__device__ __forceinline__ void mma_f16(float c[4], const uint32_t a[4], uint32_t b0, uint32_t b1) {
    asm volatile(
        "mma.sync.aligned.m16n8k16.row.col.f32.f16.f16.f32 "
        "{%0,%1,%2,%3}, {%4,%5,%6,%7}, {%8,%9}, {%0,%1,%2,%3};\n"
        : "+f"(c[0]), "+f"(c[1]), "+f"(c[2]), "+f"(c[3])
        : "r"(a[0]), "r"(a[1]), "r"(a[2]), "r"(a[3]), "r"(b0), "r"(b1));
}
__device__ __forceinline__ void ldsm_x4(uint32_t r[4], uint32_t addr) {
    asm volatile("ldmatrix.sync.aligned.m8n8.x4.shared.b16 {%0,%1,%2,%3}, [%4];"
        : "=r"(r[0]), "=r"(r[1]), "=r"(r[2]), "=r"(r[3]) : "r"(addr));
}
__device__ __forceinline__ void ldsm_x4t(uint32_t r[4], uint32_t addr) {
    asm volatile("ldmatrix.sync.aligned.m8n8.x4.trans.shared.b16 {%0,%1,%2,%3}, [%4];"
        : "=r"(r[0]), "=r"(r[1]), "=r"(r[2]), "=r"(r[3]) : "r"(addr));
}
// Packed fp16 split: (a,b) -> hi fp16 pair (a low half) + lo fp16 pair.
__device__ __forceinline__ void split2h(float a, float b, uint32_t& h2, uint32_t& l2) {
    uint32_t h;
    asm("cvt.rn.f16x2.f32 %0, %1, %2;" : "=r"(h) : "f"(b), "f"(a));
    const __half2 hp = *(__half2*)&h;
    const float ha = __half2float(__low2half(hp));
    const float hb = __half2float(__high2half(hp));
    asm("cvt.rn.f16x2.f32 %0, %1, %2;" : "=r"(l2) : "f"(b - hb), "f"(a - ha));
    h2 = h;
}
__device__ __forceinline__ uint32_t pack_f16x2(float a, float b) {
    uint32_t r;
    asm("cvt.rn.f16x2.f32 %0, %1, %2;" : "=r"(r) : "f"(b), "f"(a));
    return r;
}
__device__ __forceinline__ float fast_ex2(float x) {
    float y;
    asm("ex2.approx.ftz.f32 %0, %1;" : "=f"(y) : "f"(x));
    return y;
}

// ---------------------------------------------------------------------------
// Prep: split fp32 -> fp16 hi/lo, same layout.
// ---------------------------------------------------------------------------
__global__ void split_kernel(const float* __restrict__ src,
                             __half* __restrict__ hi,
                             __half* __restrict__ lo, int n4)
{
    int i = blockIdx.x * blockDim.x + threadIdx.x;
    if (i >= n4) return;
    float4 v = ((const float4*)src)[i];
    uint32_t h0, l0, h1, l1;
    split2h(v.x, v.y, h0, l0);
    split2h(v.z, v.w, h1, l1);
    ((uint32_t*)hi)[i*2+0] = h0;
    ((uint32_t*)hi)[i*2+1] = h1;
    ((uint32_t*)lo)[i*2+0] = l0;
    ((uint32_t*)lo)[i*2+1] = l1;
}

// ---------------------------------------------------------------------------
// Prep: transpose all 4 weights to single fp16 [N][K] (blockIdx.z selects).
// ---------------------------------------------------------------------------
__global__ void tsplit4_kernel(
    const float* __restrict__ W0, const float* __restrict__ W1,
    const float* __restrict__ W2, const float* __restrict__ W3,
    __half* __restrict__ T0, __half* __restrict__ T1,
    __half* __restrict__ T2, __half* __restrict__ T3)
{
    const int z = blockIdx.z;
    const float* W = (z == 0) ? W0 : (z == 1) ? W1 : (z == 2) ? W2 : W3;
    __half* Tw = (z == 0) ? T0 : (z == 1) ? T1 : (z == 2) ? T2 : T3;

    __shared__ float t[32][33];
    const int n0 = blockIdx.x * 32, k0 = blockIdx.y * 32;
    const int tx = threadIdx.x, ty = threadIdx.y;   // (32, 8)
    #pragma unroll
    for (int i = 0; i < 4; i++)
        t[ty + 8*i][tx] = W[(size_t)(k0 + ty + 8*i) * E_ + n0 + tx];
    __syncthreads();
    #pragma unroll
    for (int i = 0; i < 4; i++) {
        const int row = ty + 8*i;
        Tw[(size_t)(n0 + row) * E_ + k0 + tx] = __float2half(t[tx][row]);
    }
}

// ---------------------------------------------------------------------------
// fp16x2 tensor-core GEMM body: C = (Ah + Al) @ W^T, W single fp16.
// 3-stage cp.async, single barrier/iter, XOR-swizzled smem (64B rows).
// Stage = Ah, Al, B tiles -> 24576 B; 3 stages = 73728 B -> 2 CTAs/SM.
// ---------------------------------------------------------------------------
#define GS_TILE   8192
#define GS_STAGE  (3*GS_TILE)          // 24576 B
#define GS_SMEM   (3*GS_STAGE)         // 73728 B

template<bool REORDER>
__device__ __forceinline__ void gemm_body(
    const __half* __restrict__ Ah, const __half* __restrict__ Al,
    const __half* __restrict__ Tw,
    const float* __restrict__ bias, float* __restrict__ C,
    __half* __restrict__ Ch, __half* __restrict__ Cl,
    float oscale)
{
    extern __shared__ char sm[];
    const uint32_t smb = smem_u32(sm);

    const int tid  = threadIdx.x;
    const int warp = tid >> 5;
    const int lane = tid & 31;
    const int group = lane >> 2;
    const int tidg  = lane & 3;

    const int bn = blockIdx.x, bm = blockIdx.y;
    const int m0 = bm * 128, n0 = bn * 128;
    const int warp_m = warp & 1;
    const int warp_n = warp >> 1;

    const int lrow = (lane & 7) + ((lane >> 3) & 1) * 8;
    const int lchk = (lane >> 4) & 1;
    const int sel  = (lrow >> 1) & 3;

    auto load_stage = [&](int s, int c) {
        const int kb = c * 32;
        const uint32_t st = smb + s * GS_STAGE;
        #pragma unroll
        for (int i = 0; i < 2; i++) {
            const int ch = tid + i * 256;
            const int row = ch >> 2, q = ch & 3;
            const uint32_t d = st + row * 64 + (((q ^ ((row >> 1) & 3))) << 4);
            const size_t ga = (size_t)(m0 + row) * E_ + kb + q * 8;
            const size_t gb = (size_t)(n0 + row) * E_ + kb + q * 8;
            cp_async16(d,               Ah + ga);
            cp_async16(d + GS_TILE,     Al + ga);
            cp_async16(d + 2*GS_TILE,   Tw + gb);
        }
        cp_commit();
    };

    float acc[4][4][4];
    #pragma unroll
    for (int i = 0; i < 4; i++)
        #pragma unroll
        for (int j = 0; j < 4; j++)
            #pragma unroll
            for (int r = 0; r < 4; r++) acc[i][j][r] = 0.f;

    const int NC = E_ / 32;
    load_stage(0, 0);
    load_stage(1, 1);

    for (int c = 0; c < NC; c++) {
        const int s = c % 3;
        if (c + 1 < NC) cp_wait1(); else cp_wait0();
        __syncthreads();
        if (c + 2 < NC) load_stage((c + 2) % 3, c + 2);

        const uint32_t st = smb + s * GS_STAGE;
        const uint32_t abase = st + (warp_m * 64 + lrow) * 64;
        const uint32_t bbase = st + 2*GS_TILE + (warp_n * 32 + lrow) * 64;

        #pragma unroll
        for (int h2 = 0; h2 < 2; h2++) {
            const uint32_t co = (uint32_t)(((lchk + 2 * h2) ^ sel) << 4);
            uint32_t ah[4][4], al[4][4], bf[2][4];
            #pragma unroll
            for (int i = 0; i < 4; i++) {
                ldsm_x4(ah[i], abase + i * 16 * 64 + co);
                ldsm_x4(al[i], abase + GS_TILE + i * 16 * 64 + co);
            }
            #pragma unroll
            for (int g = 0; g < 2; g++)
                ldsm_x4(bf[g], bbase + g * 16 * 64 + co);
            #pragma unroll
            for (int i = 0; i < 4; i++)
                #pragma unroll
                for (int j = 0; j < 4; j++)
                    mma_f16(acc[i][j], ah[i], bf[j>>1][j&1], bf[j>>1][(j&1)+2]);
            #pragma unroll
            for (int i = 0; i < 4; i++)
                #pragma unroll
                for (int j = 0; j < 4; j++)
                    mma_f16(acc[i][j], al[i], bf[j>>1][j&1], bf[j>>1][(j&1)+2]);
        }
    }

    #pragma unroll
    for (int i = 0; i < 4; i++) {
        const int rmb = m0 + warp_m * 64 + i * 16 + group;
        #pragma unroll
        for (int j = 0; j < 4; j++) {
            const int cb = n0 + warp_n * 32 + j * 8 + tidg * 2;
            const float bx = bias[cb], by = bias[cb + 1];
            #pragma unroll
            for (int half = 0; half < 2; half++) {
                const int m = rmb + half * 8;
                const float vx = (acc[i][j][half * 2 + 0] + bx) * (REORDER ? oscale : 1.f);
                const float vy = (acc[i][j][half * 2 + 1] + by) * (REORDER ? oscale : 1.f);
                if (REORDER) {
                    const int b = m >> 11;
                    const int t = m & (T_ - 1);
                    const int h = cb >> 6;
                    const int d = cb & (HD_ - 1);
                    const size_t o = (((size_t)(b * H_ + h) * T_) + t) * HD_ + d;
                    uint32_t h2, l2;
                    split2h(vx, vy, h2, l2);
                    *(uint32_t*)&Ch[o] = h2;
                    if (Cl) *(uint32_t*)&Cl[o] = l2;
                } else {
                    float2 v; v.x = vx; v.y = vy;
                    *(float2*)&C[(size_t)m * E_ + cb] = v;
                }
            }
        }
    }
}

// Fused QKV: blockIdx.z selects. Q gets QSCALE; K and V store hi only.
__global__ void __launch_bounds__(256, 2) gemm_qkv(
    const __half* __restrict__ xh, const __half* __restrict__ xl,
    const __half* __restrict__ wq, const __half* __restrict__ wk,
    const __half* __restrict__ wv,
    const float* __restrict__ bq, const float* __restrict__ bk, const float* __restrict__ bv,
    __half* __restrict__ qh, __half* __restrict__ ql,
    __half* __restrict__ kh, __half* __restrict__ vh)
{
    const int z = blockIdx.z;
    const __half* Tw   = (z == 0) ? wq : (z == 1) ? wk : wv;
    const float* bias  = (z == 0) ? bq : (z == 1) ? bk : bv;
    __half* Ch         = (z == 0) ? qh : (z == 1) ? kh : vh;
    __half* Cl         = (z == 0) ? ql : nullptr;
    const float oscale = (z == 0) ? QSCALE : 1.0f;
    gemm_body<true>(xh, xl, Tw, bias, nullptr, Ch, Cl, oscale);
}

__global__ void __launch_bounds__(256, 2) gemm_proj(
    const __half* __restrict__ yh, const __half* __restrict__ yl,
    const __half* __restrict__ wp,
    const float* __restrict__ bp, float* __restrict__ out)
{
    gemm_body<false>(yh, yl, wp, bp, out, nullptr, nullptr, 1.0f);
}

// ---------------------------------------------------------------------------
// Tensor-core flash attention (causal), all-fp16 MMA.
// QK: Q hi/lo x K single (2 products). PV: P single x V single (1 product).
// Log2-domain online softmax, deferred row-sum, rescale skip.
// Stage = K, V (2 tiles). 3-stage cp.async, single barrier per tile.
// ---------------------------------------------------------------------------
#define AT_STRIDE 144
#define AT_TILE   (64*AT_STRIDE)     // 9216
#define AT_STAGE  (2*AT_TILE)        // 18432
#define AT_SMEM   (3*AT_STAGE)       // 55296; x2 = 108 KB <= 228 KB/SM

__global__ void __launch_bounds__(256, 2) attn_tc(
    const __half* __restrict__ Qh, const __half* __restrict__ Ql,
    const __half* __restrict__ Kh, const __half* __restrict__ Vh,
    __half* __restrict__ Yh, __half* __restrict__ Yl)
{
    extern __shared__ char sm[];
    const uint32_t smb = smem_u32(sm);

    const int tid  = threadIdx.x;
    const int warp = tid >> 5;
    const int lane = tid & 31;
    const int g    = lane >> 2;
    const int t4   = lane & 3;

    const int qb = (int)gridDim.x - 1 - (int)blockIdx.x;
    const int h  = blockIdx.y;
    const int b  = blockIdx.z;
    const int q0 = qb * 128;

    const size_t base = (size_t)(b * H_ + h) * T_ * HD_;
    const __half* qh = Qh + base + (size_t)q0 * HD_;
    const __half* ql = Ql + base + (size_t)q0 * HD_;
    const __half* kh = Kh + base;
    const __half* vh = Vh + base;

    const int arow = (lane & 7) + ((lane >> 3) & 1) * 8;
    const int achk = (lane >> 4) & 1;
    const int brow = (lane & 7) + ((lane >> 4) & 1) * 8;
    const int bchk = (lane >> 3) & 1;

    // ---- load Q (fp16 hi/lo) into stage regions 0..1, grab fragments ----
    #pragma unroll
    for (int i = 0; i < 4; i++) {
        const int ch = tid + i * 256;
        const int row = ch >> 3, q = ch & 7;
        const uint32_t d = smb + (row >> 6) * AT_TILE + (row & 63) * AT_STRIDE + q * 16;
        cp_async16(d,               qh + (size_t)row * HD_ + q * 8);
        cp_async16(d + 2*AT_TILE,   ql + (size_t)row * HD_ + q * 8);
    }
    cp_commit(); cp_wait0();
    __syncthreads();

    uint32_t qfh[4][4], qfl[4][4];
    {
        const int wr = warp * 16;
        const uint32_t qbse = smb + (wr >> 6) * AT_TILE + (wr & 63) * AT_STRIDE
                            + arow * AT_STRIDE + achk * 16;
        #pragma unroll
        for (int kc = 0; kc < 4; kc++) {
            ldsm_x4(qfh[kc], qbse + kc * 32);
            ldsm_x4(qfl[kc], qbse + 2*AT_TILE + kc * 32);
        }
    }
    __syncthreads();

    auto load_stage = [&](int s, int kt) {
        const int kv0 = kt * 64;
        const uint32_t st = smb + s * AT_STAGE;
        #pragma unroll
        for (int i = 0; i < 2; i++) {
            const int ch = tid + i * 256;
            const int row = ch >> 3, q = ch & 7;
            const uint32_t d = st + row * AT_STRIDE + q * 16;
            const size_t go = (size_t)(kv0 + row) * HD_ + q * 8;
            cp_async16(d,             kh + go);
            cp_async16(d + AT_TILE,   vh + go);
        }
        cp_commit();
    };

    float O[8][4];
    #pragma unroll
    for (int j = 0; j < 8; j++)
        #pragma unroll
        for (int r = 0; r < 4; r++) O[j][r] = 0.f;
    float m0 = -1e30f, m1 = -1e30f;
    float ps0 = 0.f, ps1 = 0.f;

    const int nt = 2 * (qb + 1);
    const int R  = q0 + warp * 16;

    load_stage(0, 0);
    if (nt > 1) load_stage(1, 1);

    for (int kt = 0; kt < nt; kt++) {
        const int s = kt % 3;
        const int kv0 = kt * 64;
        if (kt + 1 < nt) cp_wait1(); else cp_wait0();
        __syncthreads();
        if (kt + 2 < nt) load_stage((kt + 2) % 3, kt + 2);

        if (kv0 <= R + 15) {
            const uint32_t st = smb + s * AT_STAGE;

            // ---- S = Q K^T (fp16: Q hi/lo x K single) ----
            float S[8][4];
            #pragma unroll
            for (int j = 0; j < 8; j++)
                #pragma unroll
                for (int r = 0; r < 4; r++) S[j][r] = 0.f;

            #pragma unroll
            for (int kc = 0; kc < 4; kc++) {
                #pragma unroll
                for (int np = 0; np < 4; np++) {
                    uint32_t kf[4];
                    const uint32_t a = st + (np * 16 + brow) * AT_STRIDE + bchk * 16 + kc * 32;
                    ldsm_x4(kf, a);
                    const int j0 = 2 * np;
                    mma_f16(S[j0],     qfh[kc], kf[0], kf[1]);
                    mma_f16(S[j0 + 1], qfh[kc], kf[2], kf[3]);
                    mma_f16(S[j0],     qfl[kc], kf[0], kf[1]);
                    mma_f16(S[j0 + 1], qfl[kc], kf[2], kf[3]);
                }
            }

            // ---- causal mask ----
            const int row0 = R + g, row1 = R + g + 8;
            const bool need_mask = (kv0 + 63 > R);
            if (need_mask) {
                #pragma unroll
                for (int j = 0; j < 8; j++) {
                    const int c0 = kv0 + 8 * j + 2 * t4;
                    if (c0     > row0) S[j][0] = -1e30f;
                    if (c0 + 1 > row0) S[j][1] = -1e30f;
                    if (c0     > row1) S[j][2] = -1e30f;
                    if (c0 + 1 > row1) S[j][3] = -1e30f;
                }
            }

            // ---- running max ----
            float mx0 = -1e30f, mx1 = -1e30f;
            #pragma unroll
            for (int j = 0; j < 8; j++) {
                mx0 = fmaxf(mx0, fmaxf(S[j][0], S[j][1]));
                mx1 = fmaxf(mx1, fmaxf(S[j][2], S[j][3]));
            }
            mx0 = fmaxf(mx0, __shfl_xor_sync(0xffffffffu, mx0, 1));
            mx0 = fmaxf(mx0, __shfl_xor_sync(0xffffffffu, mx0, 2));
            mx1 = fmaxf(mx1, __shfl_xor_sync(0xffffffffu, mx1, 1));
            mx1 = fmaxf(mx1, __shfl_xor_sync(0xffffffffu, mx1, 2));

            const float nm0 = fmaxf(m0, mx0);
            const float nm1 = fmaxf(m1, mx1);
            if (nm0 != m0 || nm1 != m1) {
                const float cr0 = fast_ex2(m0 - nm0);
                const float cr1 = fast_ex2(m1 - nm1);
                ps0 *= cr0;  ps1 *= cr1;
                #pragma unroll
                for (int j = 0; j < 8; j++) {
                    O[j][0] *= cr0;  O[j][1] *= cr0;
                    O[j][2] *= cr1;  O[j][3] *= cr1;
                }
                m0 = nm0;  m1 = nm1;
            }

            // ---- P = 2^(S - m), per-thread sum accumulation ----
            #pragma unroll
            for (int j = 0; j < 8; j++) {
                S[j][0] = fast_ex2(S[j][0] - m0);
                S[j][1] = fast_ex2(S[j][1] - m0);
                S[j][2] = fast_ex2(S[j][2] - m1);
                S[j][3] = fast_ex2(S[j][3] - m1);
                ps0 += S[j][0] + S[j][1];
                ps1 += S[j][2] + S[j][3];
            }

            // ---- O += P V (fp16 single x single) ----
            #pragma unroll
            for (int kc = 0; kc < 4; kc++) {
                uint32_t ph[4];
                ph[0] = pack_f16x2(S[2*kc][0],   S[2*kc][1]);
                ph[1] = pack_f16x2(S[2*kc][2],   S[2*kc][3]);
                ph[2] = pack_f16x2(S[2*kc+1][0], S[2*kc+1][1]);
                ph[3] = pack_f16x2(S[2*kc+1][2], S[2*kc+1][3]);
                #pragma unroll
                for (int np = 0; np < 4; np++) {
                    uint32_t vf[4];
                    const uint32_t a = st + AT_TILE + (kc * 16 + arow) * AT_STRIDE
                                     + np * 32 + achk * 16;
                    ldsm_x4t(vf, a);
                    const int j0 = 2 * np;
                    mma_f16(O[j0],     ph, vf[0], vf[1]);
                    mma_f16(O[j0 + 1], ph, vf[2], vf[3]);
                }
            }
        }
    }

    // ---- one-time row-sum reduction + epilogue ----
    ps0 += __shfl_xor_sync(0xffffffffu, ps0, 1);
    ps0 += __shfl_xor_sync(0xffffffffu, ps0, 2);
    ps1 += __shfl_xor_sync(0xffffffffu, ps1, 1);
    ps1 += __shfl_xor_sync(0xffffffffu, ps1, 2);
    const float inv0 = 1.0f / ps0;
    const float inv1 = 1.0f / ps1;

    const int row0 = q0 + warp * 16 + g;
    const int row1 = row0 + 8;
    #pragma unroll
    for (int j = 0; j < 8; j++) {
        const int col = h * HD_ + 8 * j + 2 * t4;
        const size_t o0 = (size_t)(b * T_ + row0) * E_ + col;
        const size_t o1 = (size_t)(b * T_ + row1) * E_ + col;
        uint32_t h2, l2;
        split2h(O[j][0] * inv0, O[j][1] * inv0, h2, l2);
        *(uint32_t*)&Yh[o0] = h2;
        *(uint32_t*)&Yl[o0] = l2;
        split2h(O[j][2] * inv1, O[j][3] * inv1, h2, l2);
        *(uint32_t*)&Yh[o1] = h2;
        *(uint32_t*)&Yl[o1] = l2;
    }
}

// ---------------------------------------------------------------------------
extern "C" void kernel_launch(void* const* d_in, const int* in_sizes, int n_in,
                              void* d_out, int out_size)
{
    const float* x  = (const float*)d_in[0];
    const float* Wq = (const float*)d_in[2];
    const float* bq = (const float*)d_in[3];
    const float* Wk = (const float*)d_in[4];
    const float* bk = (const float*)d_in[5];
    const float* Wv = (const float*)d_in[6];
    const float* bv = (const float*)d_in[7];
    const float* Wp = (const float*)d_in[8];
    const float* bp = (const float*)d_in[9];
    float* out = (float*)d_out;

    __half *xh, *xl, *yh, *yl, *qh, *ql, *kh, *vh;
    __half *wq, *wk, *wv, *wp;
    cudaGetSymbolAddress((void**)&xh, g_xh);  cudaGetSymbolAddress((void**)&xl, g_xl);
    cudaGetSymbolAddress((void**)&yh, g_yh);  cudaGetSymbolAddress((void**)&yl, g_yl);
    cudaGetSymbolAddress((void**)&qh, g_qh);  cudaGetSymbolAddress((void**)&ql, g_ql);
    cudaGetSymbolAddress((void**)&kh, g_kh);
    cudaGetSymbolAddress((void**)&vh, g_vh);
    cudaGetSymbolAddress((void**)&wq, g_wq);  cudaGetSymbolAddress((void**)&wk, g_wk);
    cudaGetSymbolAddress((void**)&wv, g_wv);  cudaGetSymbolAddress((void**)&wp, g_wp);

    cudaFuncSetAttribute(gemm_qkv,  cudaFuncAttributeMaxDynamicSharedMemorySize, GS_SMEM);
    cudaFuncSetAttribute(gemm_proj, cudaFuncAttributeMaxDynamicSharedMemorySize, GS_SMEM);
    cudaFuncSetAttribute(attn_tc,   cudaFuncAttributeMaxDynamicSharedMemorySize, AT_SMEM);

    // Prep: split x (fp16 hi/lo), transpose weights (single fp16)
    split_kernel<<<(M_*E_/4 + 255)/256, 256>>>(x, xh, xl, M_*E_/4);
    dim3 tgrid(E_/32, E_/32, 4), tblk(32, 8);
    tsplit4_kernel<<<tgrid, tblk>>>(Wq, Wk, Wv, Wp, wq, wk, wv, wp);

    // Fused QKV projections
    dim3 qkv_grid(E_ / 128, M_ / 128, 3);   // (8, 64, 3)
    gemm_qkv<<<qkv_grid, 256, GS_SMEM>>>(xh, xl, wq, wk, wv,
                                         bq, bk, bv,
                                         qh, ql, kh, vh);

    dim3 attn_grid(T_ / 128, H_, B_);       // (16, 16, 4)
    attn_tc<<<attn_grid, 256, AT_SMEM>>>(qh, ql, kh, vh, yh, yl);

    dim3 proj_grid(E_ / 128, M_ / 128);     // (8, 64)
    gemm_proj<<<proj_grid, 256, GS_SMEM>>>(yh, yl, wp, bp, out);
}